// round 7
// baseline (speedup 1.0000x reference)
#include <cuda_runtime.h>
#include <math.h>

// Problem constants
#define N_CLASS 32000
#define EMB     256
#define HID     512
#define BATCH   256
#define SEQ     64
#define G4      2048            // 4 gates * HID (gate-interleaved: n = u*4 + g)
#define MB_     (SEQ*BATCH)     // 16384
#define BH      (BATCH*HID)     // 131072

typedef unsigned long long u64;

// ---------------- static device scratch (allocation-free) ----------------
__device__ float g_emb  [MB_*EMB];        //  16 MB  gathered embeddings
__device__ float g_gin  [MB_*G4];         // 134 MB  input-gate terms (interleaved n)
__device__ float g_h0all[MB_*HID];        //  33 MB  layer-0 h for every step
__device__ float g_h    [2*BH];           //  h double buffer
__device__ float g_wicat[G4*EMB];         //  interleaved input weights  [n][e]
__device__ float g_whq  [G4*HID];         //  interleaved hidden weights [n][k]
__device__ float g_bcat [G4];             //  interleaved biases
__device__ float g_weff [G4*HID];         //  folded layer-1 input weights
__device__ float g_beff [G4];             //  folded layer-1 bias
__device__ unsigned          g_barcnt;    //  grid-barrier arrive counter
__device__ volatile unsigned g_bargen;    //  grid-barrier generation

// ---------------- f32x2 packed math helpers ----------------
__device__ __forceinline__ u64 pack2(float x, float y) {
    u64 r; asm("mov.b64 %0, {%1, %2};" : "=l"(r) : "f"(x), "f"(y)); return r;
}
__device__ __forceinline__ float2 unpack2(u64 v) {
    float2 r; asm("mov.b64 {%0, %1}, %2;" : "=f"(r.x), "=f"(r.y) : "l"(v)); return r;
}
__device__ __forceinline__ void fma2(u64& d, u64 a, u64 b) {
    asm("fma.rn.f32x2 %0, %1, %2, %0;" : "+l"(d) : "l"(a), "l"(b));
}
__device__ __forceinline__ float sigmoidf_(float x) { return 1.0f / (1.0f + expf(-x)); }

// ------------- build gate-interleaved weight/bias matrices -------------
// n = u*4 + g, gate order g: 0=i, 1=f, 2=g, 3=o
__global__ void __launch_bounds__(256) prep_concat_kernel(
    const float* __restrict__ Wii, const float* __restrict__ Whi, const float* __restrict__ bi,
    const float* __restrict__ Wif, const float* __restrict__ Whf, const float* __restrict__ bf,
    const float* __restrict__ Wig, const float* __restrict__ Whg, const float* __restrict__ bg,
    const float* __restrict__ Wio, const float* __restrict__ Who, const float* __restrict__ bo)
{
    int idx = blockIdx.x * 256 + threadIdx.x;
    if (idx >= G4 * HID) return;
    int n = idx / HID;
    int k = idx - n * HID;
    int u = n >> 2;
    int g = n & 3;
    const float* Wh = (g == 0) ? Whi : (g == 1) ? Whf : (g == 2) ? Whg : Who;
    g_whq[idx] = Wh[u * HID + k];
    if (k < EMB) {
        const float* Wi = (g == 0) ? Wii : (g == 1) ? Wif : (g == 2) ? Wig : Wio;
        g_wicat[n * EMB + k] = Wi[u * EMB + k];
    }
    if (k == 0) {
        const float* bv = (g == 0) ? bi : (g == 1) ? bf : (g == 2) ? bg : bo;
        g_bcat[n] = bv[u];
    }
}

// ------------- embedding gather -------------
__global__ void __launch_bounds__(EMB) embed_kernel(const int* __restrict__ X,
                                                    const float* __restrict__ C)
{
    int sb = blockIdx.x;          // s*BATCH + b
    int s  = sb >> 8;
    int b  = sb & 255;
    int row = X[b * SEQ + s];
    g_emb[(size_t)sb * EMB + threadIdx.x] = C[(size_t)row * EMB + threadIdx.x];
}

// ------------- 128x128x16 SGEMM: dup-B smem, m-pair A, reg-prefetch -------------
// Y[m][n] = (bias?bias[n]:0) + sum_k A[m][k] * B(n,k)
// B(n,k) = B[n*K+k] normally, B[k*N+n] if TRANSB.
// Requires M%128==0, N%128==0, K%16==0.
template <bool TRANSB>
__global__ void __launch_bounds__(256, 2) gemm128_kernel(
    const float* __restrict__ A, const float* __restrict__ B,
    const float* __restrict__ bias, float* __restrict__ Y,
    int M, int N, int K)
{
    const int BK = 16;
    __shared__ float As [BK][128];
    __shared__ float Bsd[BK][256];    // every B value duplicated: [k][2n],[k][2n+1]

    int bm = blockIdx.y * 128;
    int bn = blockIdx.x * 128;
    int tid = threadIdx.x;
    int tx = tid & 15;
    int ty = tid >> 4;
    int m0 = ty * 8;
    int n0 = tx * 8;

    u64 acc[4][8];
#pragma unroll
    for (int i = 0; i < 4; i++)
#pragma unroll
        for (int j = 0; j < 8; j++) acc[i][j] = 0ULL;

    // global-load lane mapping
    int ar = tid >> 2, ak = (tid & 3) * 4;          // A rows ar, ar+64
    const float* Ap0 = A + (size_t)(bm + ar) * K + ak;
    const float* Ap1 = Ap0 + (size_t)64 * K;
    const float* Bp0;
    const float* Bp1;
    int tk = 0, tn = 0;
    if (!TRANSB) {
        Bp0 = B + (size_t)(bn + ar) * K + ak;       // B rows ar, ar+64
        Bp1 = Bp0 + (size_t)64 * K;
    } else {
        tk = tid >> 5;          // k rows tk, tk+8
        tn = (tid & 31) * 4;
        Bp0 = B + (size_t)tk * N + bn + tn;
        Bp1 = Bp0 + (size_t)8 * N;
    }

    float4 aL0 = *(const float4*)Ap0;
    float4 aL1 = *(const float4*)Ap1;
    float4 bL0, bL1;
    if (!TRANSB) { bL0 = *(const float4*)Bp0; bL1 = *(const float4*)Bp1; }
    else         { bL0 = *(const float4*)Bp0; bL1 = *(const float4*)Bp1; }

    for (int k0 = 0; k0 < K; k0 += BK) {
        __syncthreads();
        // store A (transpose to As[k][m])
        As[ak + 0][ar] = aL0.x; As[ak + 1][ar] = aL0.y;
        As[ak + 2][ar] = aL0.z; As[ak + 3][ar] = aL0.w;
        As[ak + 0][ar + 64] = aL1.x; As[ak + 1][ar + 64] = aL1.y;
        As[ak + 2][ar + 64] = aL1.z; As[ak + 3][ar + 64] = aL1.w;
        // store B duplicated
        if (!TRANSB) {
            *(u64*)&Bsd[ak + 0][2 * ar] = pack2(bL0.x, bL0.x);
            *(u64*)&Bsd[ak + 1][2 * ar] = pack2(bL0.y, bL0.y);
            *(u64*)&Bsd[ak + 2][2 * ar] = pack2(bL0.z, bL0.z);
            *(u64*)&Bsd[ak + 3][2 * ar] = pack2(bL0.w, bL0.w);
            *(u64*)&Bsd[ak + 0][2 * (ar + 64)] = pack2(bL1.x, bL1.x);
            *(u64*)&Bsd[ak + 1][2 * (ar + 64)] = pack2(bL1.y, bL1.y);
            *(u64*)&Bsd[ak + 2][2 * (ar + 64)] = pack2(bL1.z, bL1.z);
            *(u64*)&Bsd[ak + 3][2 * (ar + 64)] = pack2(bL1.w, bL1.w);
        } else {
            *(u64*)&Bsd[tk][2 * tn + 0] = pack2(bL0.x, bL0.x);
            *(u64*)&Bsd[tk][2 * tn + 2] = pack2(bL0.y, bL0.y);
            *(u64*)&Bsd[tk][2 * tn + 4] = pack2(bL0.z, bL0.z);
            *(u64*)&Bsd[tk][2 * tn + 6] = pack2(bL0.w, bL0.w);
            *(u64*)&Bsd[tk + 8][2 * tn + 0] = pack2(bL1.x, bL1.x);
            *(u64*)&Bsd[tk + 8][2 * tn + 2] = pack2(bL1.y, bL1.y);
            *(u64*)&Bsd[tk + 8][2 * tn + 4] = pack2(bL1.z, bL1.z);
            *(u64*)&Bsd[tk + 8][2 * tn + 6] = pack2(bL1.w, bL1.w);
        }
        __syncthreads();

        // prefetch next tile into registers
        if (k0 + BK < K) {
            aL0 = *(const float4*)(Ap0 + k0 + BK);
            aL1 = *(const float4*)(Ap1 + k0 + BK);
            if (!TRANSB) {
                bL0 = *(const float4*)(Bp0 + k0 + BK);
                bL1 = *(const float4*)(Bp1 + k0 + BK);
            } else {
                bL0 = *(const float4*)(Bp0 + (size_t)(k0 + BK) * N);
                bL1 = *(const float4*)(Bp1 + (size_t)(k0 + BK) * N);
            }
        }

#pragma unroll
        for (int k = 0; k < BK; k++) {
            const u64* ap = (const u64*)&As[k][m0];     // 4 m-pairs
            const u64* bp = (const u64*)&Bsd[k][2 * n0]; // 8 dup'd n
            u64 a0 = ap[0], a1 = ap[1], a2 = ap[2], a3 = ap[3];
            u64 b[8];
#pragma unroll
            for (int j = 0; j < 8; j++) b[j] = bp[j];
#pragma unroll
            for (int j = 0; j < 8; j++) {
                fma2(acc[0][j], a0, b[j]);
                fma2(acc[1][j], a1, b[j]);
                fma2(acc[2][j], a2, b[j]);
                fma2(acc[3][j], a3, b[j]);
            }
        }
    }

    float bb[8] = {0, 0, 0, 0, 0, 0, 0, 0};
    if (bias) {
        float4 t0 = *(const float4*)&bias[bn + n0];
        float4 t1 = *(const float4*)&bias[bn + n0 + 4];
        bb[0] = t0.x; bb[1] = t0.y; bb[2] = t0.z; bb[3] = t0.w;
        bb[4] = t1.x; bb[5] = t1.y; bb[6] = t1.z; bb[7] = t1.w;
    }
#pragma unroll
    for (int mp = 0; mp < 4; mp++) {
        float2 p[8];
#pragma unroll
        for (int j = 0; j < 8; j++) p[j] = unpack2(acc[mp][j]);
        int r0 = bm + m0 + 2 * mp;
        float4 lo0 = make_float4(p[0].x + bb[0], p[1].x + bb[1], p[2].x + bb[2], p[3].x + bb[3]);
        float4 lo1 = make_float4(p[4].x + bb[4], p[5].x + bb[5], p[6].x + bb[6], p[7].x + bb[7]);
        float4 hi0 = make_float4(p[0].y + bb[0], p[1].y + bb[1], p[2].y + bb[2], p[3].y + bb[3]);
        float4 hi1 = make_float4(p[4].y + bb[4], p[5].y + bb[5], p[6].y + bb[6], p[7].y + bb[7]);
        *(float4*)&Y[(size_t)r0 * N + bn + n0]           = lo0;
        *(float4*)&Y[(size_t)r0 * N + bn + n0 + 4]       = lo1;
        *(float4*)&Y[(size_t)(r0 + 1) * N + bn + n0]     = hi0;
        *(float4*)&Y[(size_t)(r0 + 1) * N + bn + n0 + 4] = hi1;
    }
}

// ------------- software grid barrier (128 blocks, all co-resident) -------------
__device__ __forceinline__ void gridbar(unsigned target)
{
    __threadfence();
    __syncthreads();
    if (threadIdx.x == 0) {
        if (atomicAdd(&g_barcnt, 1u) == 127u) {
            g_barcnt = 0u;
            __threadfence();
            g_bargen = target;
        } else {
            while (g_bargen < target) { }
        }
    }
    __syncthreads();
}

// ------------- persistent LSTM layer: all 64 steps in one launch -------------
// grid (16 n-blocks, 8 m-blocks) = 128 blocks, 128 threads.
// Tile 32(batch) x 128(n = 32 units x 4 gates). c lives in registers.
__global__ void __launch_bounds__(128) lstm_layer_kernel(int store_all)
{
    const int BK = 16;
    __shared__ float As[BK][32];
    __shared__ float Bs[BK][128];

    int tid = threadIdx.x;
    int bn = blockIdx.x * 128;
    int bm = blockIdx.y * 32;
    int tx = tid & 15;
    int ty = tid >> 4;
    int m0 = ty * 4;
    int n0 = tx * 8;
    int U  = (bn + n0) >> 2;    // first of 2 hidden units this thread owns

    // global-load lane mapping
    int ar = tid >> 2, ak = (tid & 3) * 4;  // A: row ar (0..31), k cols ak..ak+3
    const float* Bq = g_whq + (size_t)(bn + ar) * HID + ak;  // rows ar+32i

    float cr[4][2];
#pragma unroll
    for (int i = 0; i < 4; i++) { cr[i][0] = 0.0f; cr[i][1] = 0.0f; }

    for (int s = 0; s < SEQ; s++) {
        const float* hp = &g_h[(s & 1) * BH];
        float*       hn = &g_h[((s + 1) & 1) * BH];

        u64 acc[4][4];
#pragma unroll
        for (int i = 0; i < 4; i++)
#pragma unroll
            for (int j = 0; j < 4; j++) acc[i][j] = 0ULL;

        const float* Ap = hp + (size_t)(bm + ar) * HID + ak;
        float4 aL = __ldcg((const float4*)Ap);
        float4 bL[4];
#pragma unroll
        for (int i = 0; i < 4; i++)
            bL[i] = *(const float4*)(Bq + (size_t)(32 * i) * HID);

        for (int k0 = 0; k0 < HID; k0 += BK) {
            __syncthreads();
            As[ak + 0][ar] = aL.x; As[ak + 1][ar] = aL.y;
            As[ak + 2][ar] = aL.z; As[ak + 3][ar] = aL.w;
#pragma unroll
            for (int i = 0; i < 4; i++) {
                int rb = ar + 32 * i;
                Bs[ak + 0][rb] = bL[i].x; Bs[ak + 1][rb] = bL[i].y;
                Bs[ak + 2][rb] = bL[i].z; Bs[ak + 3][rb] = bL[i].w;
            }
            __syncthreads();

            if (k0 + BK < HID) {
                aL = __ldcg((const float4*)(Ap + k0 + BK));
#pragma unroll
                for (int i = 0; i < 4; i++)
                    bL[i] = *(const float4*)(Bq + (size_t)(32 * i) * HID + k0 + BK);
            }

#pragma unroll
            for (int k = 0; k < BK; k++) {
                float4 av = *(const float4*)&As[k][m0];
                u64 a0 = pack2(av.x, av.x);
                u64 a1 = pack2(av.y, av.y);
                u64 a2 = pack2(av.z, av.z);
                u64 a3 = pack2(av.w, av.w);
                const u64* bp = (const u64*)&Bs[k][n0];   // 4 n-pairs
                u64 b0 = bp[0], b1 = bp[1], b2 = bp[2], b3 = bp[3];
                fma2(acc[0][0], a0, b0); fma2(acc[0][1], a0, b1);
                fma2(acc[0][2], a0, b2); fma2(acc[0][3], a0, b3);
                fma2(acc[1][0], a1, b0); fma2(acc[1][1], a1, b1);
                fma2(acc[1][2], a1, b2); fma2(acc[1][3], a1, b3);
                fma2(acc[2][0], a2, b0); fma2(acc[2][1], a2, b1);
                fma2(acc[2][2], a2, b2); fma2(acc[2][3], a2, b3);
                fma2(acc[3][0], a3, b0); fma2(acc[3][1], a3, b1);
                fma2(acc[3][2], a3, b2); fma2(acc[3][3], a3, b3);
            }
        }

        // epilogue: gates -> c (regs) -> h
#pragma unroll
        for (int i = 0; i < 4; i++) {
            int b = bm + m0 + i;
            const float* gp = &g_gin[((size_t)s * BATCH + b) * G4 + bn + n0];
            float4 gv0 = *(const float4*)&gp[0];
            float4 gv1 = *(const float4*)&gp[4];
            float2 p0 = unpack2(acc[i][0]), p1 = unpack2(acc[i][1]);
            float2 p2 = unpack2(acc[i][2]), p3 = unpack2(acc[i][3]);
            float f[8] = {p0.x + gv0.x, p0.y + gv0.y, p1.x + gv0.z, p1.y + gv0.w,
                          p2.x + gv1.x, p2.y + gv1.y, p3.x + gv1.z, p3.y + gv1.w};
#pragma unroll
            for (int ul = 0; ul < 2; ul++) {
                float ig = sigmoidf_(f[ul * 4 + 0]);
                float fg = sigmoidf_(f[ul * 4 + 1]);
                float gg = tanhf    (f[ul * 4 + 2]);
                float og = sigmoidf_(f[ul * 4 + 3]);
                float cn = fg * cr[i][ul] + ig * gg;
                float hv = og * tanhf(cn);
                cr[i][ul] = cn;
                size_t idx = (size_t)b * HID + U + ul;
                __stcg(&hn[idx], hv);
                if (store_all) g_h0all[(size_t)s * BH + idx] = hv;
            }
        }

        if (s != SEQ - 1) gridbar((unsigned)(s + 1));
    }
}

// ------------- beff[n] = bcat[n] + sum_e Wicat[n][e] * b_proj[e] -------------
__global__ void __launch_bounds__(256) beff_kernel(const float* __restrict__ bproj)
{
    int n = blockIdx.x * 256 + threadIdx.x;
    if (n >= G4) return;
    float s = g_bcat[n];
    const float* w = &g_wicat[n * EMB];
    for (int e = 0; e < EMB; e++) s += w[e] * bproj[e];
    g_beff[n] = s;
}

// ------------- zero h buffer 0 + reset grid barrier -------------
__global__ void __launch_bounds__(256) zero_hc_kernel()
{
    int i = blockIdx.x * 256 + threadIdx.x;
    if (i < BH) g_h[i] = 0.0f;
    if (i == 0) { g_barcnt = 0u; g_bargen = 0u; }
}

// =============================== launch ===============================
extern "C" void kernel_launch(void* const* d_in, const int* in_sizes, int n_in,
                              void* d_out, int out_size)
{
    const int*   X    = (const int*)  d_in[0];
    const float* C    = (const float*)d_in[1];
    const float* Wii  = (const float*)d_in[2];
    const float* Whi  = (const float*)d_in[3];
    const float* bi   = (const float*)d_in[4];
    const float* Wif  = (const float*)d_in[5];
    const float* Whf  = (const float*)d_in[6];
    const float* bf   = (const float*)d_in[7];
    const float* Wig  = (const float*)d_in[8];
    const float* Whg  = (const float*)d_in[9];
    const float* bg   = (const float*)d_in[10];
    const float* Wio  = (const float*)d_in[11];
    const float* Who  = (const float*)d_in[12];
    const float* bo   = (const float*)d_in[13];
    const float* Wp   = (const float*)d_in[14];   // [EMB, HID]
    const float* bp   = (const float*)d_in[15];   // [EMB]
    const float* Wfin = (const float*)d_in[16];   // [N_CLASS, HID]
    const float* bfin = (const float*)d_in[17];   // [N_CLASS]
    float* out = (float*)d_out;

    float *p_emb, *p_gin, *p_h0all, *p_h, *p_wicat, *p_bcat, *p_weff, *p_beff;
    cudaGetSymbolAddress((void**)&p_emb,   g_emb);
    cudaGetSymbolAddress((void**)&p_gin,   g_gin);
    cudaGetSymbolAddress((void**)&p_h0all, g_h0all);
    cudaGetSymbolAddress((void**)&p_h,     g_h);
    cudaGetSymbolAddress((void**)&p_wicat, g_wicat);
    cudaGetSymbolAddress((void**)&p_bcat,  g_bcat);
    cudaGetSymbolAddress((void**)&p_weff,  g_weff);
    cudaGetSymbolAddress((void**)&p_beff,  g_beff);

    // 1) gate-interleaved weight concat
    prep_concat_kernel<<<(G4 * HID) / 256, 256>>>(Wii, Whi, bi, Wif, Whf, bf,
                                                  Wig, Whg, bg, Wio, Who, bo);
    // 2) embedding gather
    embed_kernel<<<MB_, EMB>>>(X, C);

    // 3) Gin0 = Emb @ Wicat^T + bcat        [16384 x 2048], K=256
    gemm128_kernel<false><<<dim3(G4 / 128, MB_ / 128), 256>>>(
        p_emb, p_wicat, p_bcat, p_gin, MB_, G4, EMB);

    // 4) fold projection: Weff[n][k] = sum_e Wicat[n][e] * Wp[e][k]
    gemm128_kernel<true><<<dim3(HID / 128, G4 / 128), 256>>>(
        p_wicat, Wp, nullptr, p_weff, G4, HID, EMB);
    beff_kernel<<<G4 / 256, 256>>>(bp);

    // 5) layer-0 recurrence: one persistent launch, 64 steps
    zero_hc_kernel<<<BH / 256, 256>>>();
    lstm_layer_kernel<<<dim3(16, 8), 128>>>(1);

    // 6) Gin1 = H0all @ Weff^T + beff       [16384 x 2048], K=512
    gemm128_kernel<false><<<dim3(G4 / 128, MB_ / 128), 256>>>(
        p_h0all, p_weff, p_beff, p_gin, MB_, G4, HID);

    // 7) layer-1 recurrence
    zero_hc_kernel<<<BH / 256, 256>>>();
    lstm_layer_kernel<<<dim3(16, 8), 128>>>(0);

    // 8) logits = h_last @ Wfin^T + bfin    [256 x 32000], K=512
    //    (SEQ even -> final h in buffer 0)
    gemm128_kernel<false><<<dim3(N_CLASS / 128, BATCH / 128), 256>>>(
        p_h, Wfin, bfin, out, BATCH, N_CLASS, HID);
}

// round 9
// speedup vs baseline: 1.5674x; 1.5674x over previous
#include <cuda_runtime.h>
#include <cuda_bf16.h>
#include <math.h>
#include <stdint.h>

// Problem constants
#define N_CLASS 32000
#define EMB     256
#define HID     512
#define BATCH   256
#define SEQ     64
#define G4      2048            // 4 gates * HID (gate-interleaved: n = u*4 + g)
#define MB_     (SEQ*BATCH)     // 16384
#define BH      (BATCH*HID)     // 131072

typedef unsigned long long u64;
typedef unsigned short u16;

// ---------------- static device scratch (allocation-free) ----------------
__device__ __align__(16) float g_emb  [MB_*EMB];
__device__ __align__(16) float g_gin  [MB_*G4];
__device__ __align__(16) float g_h0all[MB_*HID];
__device__ __align__(16) float g_h    [2*BH];
__device__ __align__(16) float g_wicat[G4*EMB];
__device__ __align__(16) float g_whq  [G4*HID];
__device__ __align__(16) float g_bcat [G4];
__device__ __align__(16) float g_weff [G4*HID];
__device__ __align__(16) float g_beff [G4];
__device__ unsigned          g_barcnt;
__device__ volatile unsigned g_bargen;
// split-bf16 operand buffers (raw u16 bits)
__device__ __align__(16) u16 g_ahi[MB_*HID];
__device__ __align__(16) u16 g_alo[MB_*HID];
__device__ __align__(16) u16 g_bhi[N_CLASS*HID];
__device__ __align__(16) u16 g_blo[N_CLASS*HID];

// ---------------- f32x2 packed math helpers ----------------
__device__ __forceinline__ u64 pack2(float x, float y) {
    u64 r; asm("mov.b64 %0, {%1, %2};" : "=l"(r) : "f"(x), "f"(y)); return r;
}
__device__ __forceinline__ float2 unpack2(u64 v) {
    float2 r; asm("mov.b64 {%0, %1}, %2;" : "=f"(r.x), "=f"(r.y) : "l"(v)); return r;
}
__device__ __forceinline__ void fma2(u64& d, u64 a, u64 b) {
    asm("fma.rn.f32x2 %0, %1, %2, %0;" : "+l"(d) : "l"(a), "l"(b));
}
__device__ __forceinline__ float sigmoidf_(float x) { return 1.0f / (1.0f + expf(-x)); }

__device__ __forceinline__ uint32_t smem_u32(const void* p) {
    uint32_t a;
    asm("{ .reg .u64 t; cvta.to.shared.u64 t, %1; cvt.u32.u64 %0, t; }"
        : "=r"(a) : "l"(p));
    return a;
}

// ---------------- mma.sync helpers (legacy tensor path, valid on sm_103) -----
__device__ __forceinline__ void ldm_x4(uint32_t* r, uint32_t addr) {
    asm volatile("ldmatrix.sync.aligned.m8n8.x4.shared.b16 {%0,%1,%2,%3}, [%4];"
                 : "=r"(r[0]), "=r"(r[1]), "=r"(r[2]), "=r"(r[3]) : "r"(addr));
}
__device__ __forceinline__ void mma16816(float* c, const uint32_t* a,
                                         uint32_t b0, uint32_t b1) {
    asm volatile(
        "mma.sync.aligned.m16n8k16.row.col.f32.bf16.bf16.f32 "
        "{%0,%1,%2,%3}, {%4,%5,%6,%7}, {%8,%9}, {%0,%1,%2,%3};"
        : "+f"(c[0]), "+f"(c[1]), "+f"(c[2]), "+f"(c[3])
        : "r"(a[0]), "r"(a[1]), "r"(a[2]), "r"(a[3]), "r"(b0), "r"(b1));
}

// ------------- build gate-interleaved weight/bias matrices -------------
__global__ void __launch_bounds__(256) prep_concat_kernel(
    const float* __restrict__ Wii, const float* __restrict__ Whi, const float* __restrict__ bi,
    const float* __restrict__ Wif, const float* __restrict__ Whf, const float* __restrict__ bf,
    const float* __restrict__ Wig, const float* __restrict__ Whg, const float* __restrict__ bg,
    const float* __restrict__ Wio, const float* __restrict__ Who, const float* __restrict__ bo)
{
    int idx = blockIdx.x * 256 + threadIdx.x;
    if (idx >= G4 * HID) return;
    int n = idx / HID;
    int k = idx - n * HID;
    int u = n >> 2;
    int g = n & 3;
    const float* Wh = (g == 0) ? Whi : (g == 1) ? Whf : (g == 2) ? Whg : Who;
    g_whq[idx] = Wh[u * HID + k];
    if (k < EMB) {
        const float* Wi = (g == 0) ? Wii : (g == 1) ? Wif : (g == 2) ? Wig : Wio;
        g_wicat[n * EMB + k] = Wi[u * EMB + k];
    }
    if (k == 0) {
        const float* bv = (g == 0) ? bi : (g == 1) ? bf : (g == 2) ? bg : bo;
        g_bcat[n] = bv[u];
    }
}

// ------------- embedding gather -------------
__global__ void __launch_bounds__(EMB) embed_kernel(const int* __restrict__ X,
                                                    const float* __restrict__ C)
{
    int sb = blockIdx.x;
    int s  = sb >> 8;
    int b  = sb & 255;
    int row = X[b * SEQ + s];
    g_emb[(size_t)sb * EMB + threadIdx.x] = C[(size_t)row * EMB + threadIdx.x];
}

// ------------- fp32 -> split bf16 (hi + lo) -------------
__global__ void __launch_bounds__(256) cvt_split_kernel(
    const float* __restrict__ src, u16* __restrict__ hi,
    u16* __restrict__ lo, int n)
{
    int i = blockIdx.x * 256 + threadIdx.x;
    if (i >= n) return;
    float x = src[i];
    __nv_bfloat16 h = __float2bfloat16(x);
    float r = x - __bfloat162float(h);
    hi[i] = __bfloat16_as_ushort(h);
    lo[i] = __bfloat16_as_ushort(__float2bfloat16(r));
}

// ------------- split-bf16 tensor-core GEMM via mma.sync -------------
// Y[m][n] = bias[n] + sum_k A[m][k]*B[n][k]   (3-term compensated bf16)
// CTA tile 128x128, 8 warps (warp w: m-block (w&3)*32, n-block (w>>2)*64),
// BK=32, double-buffered smem. Rows padded to 80B (conflict-free ldmatrix).
// Requires M%128==0, N%128==0, K%32==0.
#define MG_ROWU  40                       // padded row stride (ushorts) = 80 B
#define MG_TILEU (128*MG_ROWU)            // 5120 ushorts = 10240 B per tile
#define MG_STGU  (4*MG_TILEU)             // stage stride (Ahi,Alo,Bhi,Blo)
#define MG_SMEM  (2*MG_STGU*2)            // bytes = 81920

__device__ __forceinline__ void mg_load_stage(
    u16* s, const u16* __restrict__ Ahi, const u16* __restrict__ Alo,
    const u16* __restrict__ Bhi, const u16* __restrict__ Blo,
    int bm, int bn, int K, int k0, int tid)
{
#pragma unroll
    for (int t = 0; t < 2; t++) {
        int idx = tid + 256 * t;
        int row = idx >> 2, seg = (idx & 3) * 8;
        size_t ga = (size_t)(bm + row) * K + k0 + seg;
        size_t gb = (size_t)(bn + row) * K + k0 + seg;
        u16* d = s + row * MG_ROWU + seg;
        *(uint4*)(d + 0 * MG_TILEU) = *(const uint4*)(Ahi + ga);
        *(uint4*)(d + 1 * MG_TILEU) = *(const uint4*)(Alo + ga);
        *(uint4*)(d + 2 * MG_TILEU) = *(const uint4*)(Bhi + gb);
        *(uint4*)(d + 3 * MG_TILEU) = *(const uint4*)(Blo + gb);
    }
}

__global__ void __launch_bounds__(256) mma_gemm_kernel(
    const u16* __restrict__ Ahi, const u16* __restrict__ Alo,
    const u16* __restrict__ Bhi, const u16* __restrict__ Blo,
    const float* __restrict__ bias, float* __restrict__ Y, int N, int K)
{
    extern __shared__ u16 smu[];
    uint32_t smb = smem_u32(smu);
    int tid  = threadIdx.x;
    int w    = tid >> 5;
    int lane = tid & 31;
    int bm = blockIdx.y * 128;
    int bn = blockIdx.x * 128;
    int wm = (w & 3) * 32;
    int wn = (w >> 2) * 64;
    int nch = K >> 5;

    // ldmatrix per-thread addressing
    int mat = lane >> 3, mi = lane & 7;
    // A: matrix j -> row offset (j&1)*8, col offset (j>>1)*8 (bf16)
    uint32_t aoff = (uint32_t)((wm + (mat & 1) * 8 + mi) * 80 + (mat >> 1) * 16);
    // B: matrix j -> n offset (j>>1)*8, k offset (j&1)*8
    uint32_t boff = (uint32_t)((wn + (mat >> 1) * 8 + mi) * 80 + (mat & 1) * 16);

    float acc[2][8][4];
#pragma unroll
    for (int i = 0; i < 2; i++)
#pragma unroll
        for (int j = 0; j < 8; j++)
#pragma unroll
            for (int q = 0; q < 4; q++) acc[i][j][q] = 0.0f;

    mg_load_stage(smu, Ahi, Alo, Bhi, Blo, bm, bn, K, 0, tid);
    __syncthreads();

    for (int c = 0; c < nch; c++) {
        if (c + 1 < nch)
            mg_load_stage(smu + ((c + 1) & 1) * MG_STGU, Ahi, Alo, Bhi, Blo,
                          bm, bn, K, (c + 1) * 32, tid);

        uint32_t sb = smb + (uint32_t)((c & 1) * MG_STGU * 2);   // byte offset
#pragma unroll
        for (int k16 = 0; k16 < 2; k16++) {
            uint32_t kb = (uint32_t)(k16 * 32);
            uint32_t ah[2][4], al[2][4];
            ldm_x4(ah[0], sb + 0 * 10240 + aoff + kb);
            ldm_x4(ah[1], sb + 0 * 10240 + aoff + kb + 16 * 80);
            ldm_x4(al[0], sb + 1 * 10240 + aoff + kb);
            ldm_x4(al[1], sb + 1 * 10240 + aoff + kb + 16 * 80);
#pragma unroll
            for (int nb = 0; nb < 4; nb++) {
                uint32_t bh[4], bl[4];
                uint32_t bo = boff + kb + (uint32_t)(nb * 16 * 80);
                ldm_x4(bh, sb + 2 * 10240 + bo);
                ldm_x4(bl, sb + 3 * 10240 + bo);
#pragma unroll
                for (int mb = 0; mb < 2; mb++) {
#pragma unroll
                    for (int h = 0; h < 2; h++) {
                        float* cc = acc[mb][nb * 2 + h];
                        mma16816(cc, ah[mb], bh[2 * h], bh[2 * h + 1]);
                        mma16816(cc, ah[mb], bl[2 * h], bl[2 * h + 1]);
                        mma16816(cc, al[mb], bh[2 * h], bh[2 * h + 1]);
                    }
                }
            }
        }
        __syncthreads();
    }

    // epilogue: thread (grp = lane>>2, t2 = lane&3)
    int grp = lane >> 2, t2 = lane & 3;
#pragma unroll
    for (int mb = 0; mb < 2; mb++) {
#pragma unroll
        for (int nj = 0; nj < 8; nj++) {
            int n = bn + wn + nj * 8 + t2 * 2;
            float2 bv = *(const float2*)&bias[n];
            int mlo = bm + wm + mb * 16 + grp;
            const float* cc = acc[mb][nj];
            float2 v0 = make_float2(cc[0] + bv.x, cc[1] + bv.y);
            float2 v1 = make_float2(cc[2] + bv.x, cc[3] + bv.y);
            *(float2*)&Y[(size_t)mlo * N + n]       = v0;
            *(float2*)&Y[(size_t)(mlo + 8) * N + n] = v1;
        }
    }
}

// ------------- fp32 fold GEMM (round-6 known-good) -------------
template <bool TRANSB>
__global__ void __launch_bounds__(256) gemm128_kernel(
    const float* __restrict__ A, const float* __restrict__ B,
    const float* __restrict__ bias, float* __restrict__ Y,
    int M, int N, int K)
{
    const int BK = 16;
    __shared__ float As[BK][128];
    __shared__ float Bs[BK][128];

    int bm = blockIdx.y * 128;
    int bn = blockIdx.x * 128;
    int tid = threadIdx.x;
    int tx = tid & 15;
    int ty = tid >> 4;
    int m0 = ty * 8;
    int n0 = tx * 8;

    u64 acc[8][4];
#pragma unroll
    for (int i = 0; i < 8; i++)
#pragma unroll
        for (int j = 0; j < 4; j++) acc[i][j] = 0ULL;

    for (int k0 = 0; k0 < K; k0 += BK) {
#pragma unroll
        for (int l = tid; l < 512; l += 256) {
            int r = l >> 2, kq = l & 3;
            float4 v = *(const float4*)&A[(size_t)(bm + r) * K + k0 + kq * 4];
            As[kq * 4 + 0][r] = v.x; As[kq * 4 + 1][r] = v.y;
            As[kq * 4 + 2][r] = v.z; As[kq * 4 + 3][r] = v.w;
        }
        if (!TRANSB) {
#pragma unroll
            for (int l = tid; l < 512; l += 256) {
                int r = l >> 2, kq = l & 3;
                float4 v = *(const float4*)&B[(size_t)(bn + r) * K + k0 + kq * 4];
                Bs[kq * 4 + 0][r] = v.x; Bs[kq * 4 + 1][r] = v.y;
                Bs[kq * 4 + 2][r] = v.z; Bs[kq * 4 + 3][r] = v.w;
            }
        } else {
#pragma unroll
            for (int l = tid; l < 512; l += 256) {
                int k = l >> 5, nq = l & 31;
                *(float4*)&Bs[k][nq * 4] =
                    *(const float4*)&B[(size_t)(k0 + k) * N + bn + nq * 4];
            }
        }
        __syncthreads();

#pragma unroll
        for (int k = 0; k < BK; k++) {
            float4 av0 = *(const float4*)&As[k][m0];
            float4 av1 = *(const float4*)&As[k][m0 + 4];
            u64 bp[4];
            bp[0] = *(const u64*)&Bs[k][n0];
            bp[1] = *(const u64*)&Bs[k][n0 + 2];
            bp[2] = *(const u64*)&Bs[k][n0 + 4];
            bp[3] = *(const u64*)&Bs[k][n0 + 6];
            float am[8] = {av0.x, av0.y, av0.z, av0.w, av1.x, av1.y, av1.z, av1.w};
#pragma unroll
            for (int i = 0; i < 8; i++) {
                u64 ad = pack2(am[i], am[i]);
#pragma unroll
                for (int j = 0; j < 4; j++) fma2(acc[i][j], ad, bp[j]);
            }
        }
        __syncthreads();
    }

#pragma unroll
    for (int i = 0; i < 8; i++) {
        int m = bm + m0 + i;
        float2 p0 = unpack2(acc[i][0]), p1 = unpack2(acc[i][1]);
        float2 p2 = unpack2(acc[i][2]), p3 = unpack2(acc[i][3]);
        float4 v0 = make_float4(p0.x, p0.y, p1.x, p1.y);
        float4 v1 = make_float4(p2.x, p2.y, p3.x, p3.y);
        *(float4*)&Y[(size_t)m * N + bn + n0]     = v0;
        *(float4*)&Y[(size_t)m * N + bn + n0 + 4] = v1;
    }
}

// ------------- software grid barrier (128 blocks, all co-resident) -------------
__device__ __forceinline__ void gridbar(unsigned target)
{
    __threadfence();
    __syncthreads();
    if (threadIdx.x == 0) {
        if (atomicAdd(&g_barcnt, 1u) == 127u) {
            g_barcnt = 0u;
            __threadfence();
            g_bargen = target;
        } else {
            while (g_bargen < target) { }
        }
    }
    __syncthreads();
}

// ------------- persistent LSTM layer: all 64 steps in one launch -------------
__global__ void __launch_bounds__(128) lstm_layer_kernel(int store_all)
{
    const int BK = 16;
    __shared__ float As[BK][32];
    __shared__ float Bs[BK][128];

    int tid = threadIdx.x;
    int bn = blockIdx.x * 128;
    int bm = blockIdx.y * 32;
    int tx = tid & 15;
    int ty = tid >> 4;
    int m0 = ty * 4;
    int n0 = tx * 8;
    int U  = (bn + n0) >> 2;

    int ar = tid >> 2, ak = (tid & 3) * 4;
    const float* Bq = g_whq + (size_t)(bn + ar) * HID + ak;

    float cr[4][2];
#pragma unroll
    for (int i = 0; i < 4; i++) { cr[i][0] = 0.0f; cr[i][1] = 0.0f; }

    for (int s = 0; s < SEQ; s++) {
        const float* hp = &g_h[(s & 1) * BH];
        float*       hn = &g_h[((s + 1) & 1) * BH];

        u64 acc[4][4];
#pragma unroll
        for (int i = 0; i < 4; i++)
#pragma unroll
            for (int j = 0; j < 4; j++) acc[i][j] = 0ULL;

        const float* Ap = hp + (size_t)(bm + ar) * HID + ak;
        float4 aL = __ldcg((const float4*)Ap);
        float4 bL[4];
#pragma unroll
        for (int i = 0; i < 4; i++)
            bL[i] = *(const float4*)(Bq + (size_t)(32 * i) * HID);

        for (int k0 = 0; k0 < HID; k0 += BK) {
            __syncthreads();
            As[ak + 0][ar] = aL.x; As[ak + 1][ar] = aL.y;
            As[ak + 2][ar] = aL.z; As[ak + 3][ar] = aL.w;
#pragma unroll
            for (int i = 0; i < 4; i++) {
                int rb = ar + 32 * i;
                Bs[ak + 0][rb] = bL[i].x; Bs[ak + 1][rb] = bL[i].y;
                Bs[ak + 2][rb] = bL[i].z; Bs[ak + 3][rb] = bL[i].w;
            }
            __syncthreads();

            if (k0 + BK < HID) {
                aL = __ldcg((const float4*)(Ap + k0 + BK));
#pragma unroll
                for (int i = 0; i < 4; i++)
                    bL[i] = *(const float4*)(Bq + (size_t)(32 * i) * HID + k0 + BK);
            }

#pragma unroll
            for (int k = 0; k < BK; k++) {
                float4 av = *(const float4*)&As[k][m0];
                u64 a0 = pack2(av.x, av.x);
                u64 a1 = pack2(av.y, av.y);
                u64 a2 = pack2(av.z, av.z);
                u64 a3 = pack2(av.w, av.w);
                const u64* bp = (const u64*)&Bs[k][n0];
                u64 b0 = bp[0], b1 = bp[1], b2 = bp[2], b3 = bp[3];
                fma2(acc[0][0], a0, b0); fma2(acc[0][1], a0, b1);
                fma2(acc[0][2], a0, b2); fma2(acc[0][3], a0, b3);
                fma2(acc[1][0], a1, b0); fma2(acc[1][1], a1, b1);
                fma2(acc[1][2], a1, b2); fma2(acc[1][3], a1, b3);
                fma2(acc[2][0], a2, b0); fma2(acc[2][1], a2, b1);
                fma2(acc[2][2], a2, b2); fma2(acc[2][3], a2, b3);
                fma2(acc[3][0], a3, b0); fma2(acc[3][1], a3, b1);
                fma2(acc[3][2], a3, b2); fma2(acc[3][3], a3, b3);
            }
        }

#pragma unroll
        for (int i = 0; i < 4; i++) {
            int b = bm + m0 + i;
            const float* gp = &g_gin[((size_t)s * BATCH + b) * G4 + bn + n0];
            float4 gv0 = *(const float4*)&gp[0];
            float4 gv1 = *(const float4*)&gp[4];
            float2 p0 = unpack2(acc[i][0]), p1 = unpack2(acc[i][1]);
            float2 p2 = unpack2(acc[i][2]), p3 = unpack2(acc[i][3]);
            float f[8] = {p0.x + gv0.x, p0.y + gv0.y, p1.x + gv0.z, p1.y + gv0.w,
                          p2.x + gv1.x, p2.y + gv1.y, p3.x + gv1.z, p3.y + gv1.w};
#pragma unroll
            for (int ul = 0; ul < 2; ul++) {
                float ig = sigmoidf_(f[ul * 4 + 0]);
                float fg = sigmoidf_(f[ul * 4 + 1]);
                float gg = tanhf    (f[ul * 4 + 2]);
                float og = sigmoidf_(f[ul * 4 + 3]);
                float cn = fg * cr[i][ul] + ig * gg;
                float hv = og * tanhf(cn);
                cr[i][ul] = cn;
                size_t idx = (size_t)b * HID + U + ul;
                __stcg(&hn[idx], hv);
                if (store_all) g_h0all[(size_t)s * BH + idx] = hv;
            }
        }

        if (s != SEQ - 1) gridbar((unsigned)(s + 1));
    }
}

// ------------- beff[n] = bcat[n] + sum_e Wicat[n][e] * b_proj[e] -------------
__global__ void __launch_bounds__(256) beff_kernel(const float* __restrict__ bproj)
{
    int n = blockIdx.x * 256 + threadIdx.x;
    if (n >= G4) return;
    float s = g_bcat[n];
    const float* w = &g_wicat[n * EMB];
    for (int e = 0; e < EMB; e++) s += w[e] * bproj[e];
    g_beff[n] = s;
}

// ------------- zero h buffer 0 + reset grid barrier -------------
__global__ void __launch_bounds__(256) zero_hc_kernel()
{
    int i = blockIdx.x * 256 + threadIdx.x;
    if (i < BH) g_h[i] = 0.0f;
    if (i == 0) { g_barcnt = 0u; g_bargen = 0u; }
}

// =============================== launch ===============================
extern "C" void kernel_launch(void* const* d_in, const int* in_sizes, int n_in,
                              void* d_out, int out_size)
{
    const int*   X    = (const int*)  d_in[0];
    const float* C    = (const float*)d_in[1];
    const float* Wii  = (const float*)d_in[2];
    const float* Whi  = (const float*)d_in[3];
    const float* bi   = (const float*)d_in[4];
    const float* Wif  = (const float*)d_in[5];
    const float* Whf  = (const float*)d_in[6];
    const float* bf   = (const float*)d_in[7];
    const float* Wig  = (const float*)d_in[8];
    const float* Whg  = (const float*)d_in[9];
    const float* bg   = (const float*)d_in[10];
    const float* Wio  = (const float*)d_in[11];
    const float* Who  = (const float*)d_in[12];
    const float* bo   = (const float*)d_in[13];
    const float* Wp   = (const float*)d_in[14];   // [EMB, HID]
    const float* bp   = (const float*)d_in[15];   // [EMB]
    const float* Wfin = (const float*)d_in[16];   // [N_CLASS, HID]
    const float* bfin = (const float*)d_in[17];   // [N_CLASS]
    float* out = (float*)d_out;

    float *p_emb, *p_gin, *p_h0all, *p_h, *p_wicat, *p_bcat, *p_weff, *p_beff;
    u16 *p_ahi, *p_alo, *p_bhi, *p_blo;
    cudaGetSymbolAddress((void**)&p_emb,   g_emb);
    cudaGetSymbolAddress((void**)&p_gin,   g_gin);
    cudaGetSymbolAddress((void**)&p_h0all, g_h0all);
    cudaGetSymbolAddress((void**)&p_h,     g_h);
    cudaGetSymbolAddress((void**)&p_wicat, g_wicat);
    cudaGetSymbolAddress((void**)&p_bcat,  g_bcat);
    cudaGetSymbolAddress((void**)&p_weff,  g_weff);
    cudaGetSymbolAddress((void**)&p_beff,  g_beff);
    cudaGetSymbolAddress((void**)&p_ahi,   g_ahi);
    cudaGetSymbolAddress((void**)&p_alo,   g_alo);
    cudaGetSymbolAddress((void**)&p_bhi,   g_bhi);
    cudaGetSymbolAddress((void**)&p_blo,   g_blo);

    cudaFuncSetAttribute(mma_gemm_kernel,
                         cudaFuncAttributeMaxDynamicSharedMemorySize, MG_SMEM);

    // 1) gate-interleaved weight concat
    prep_concat_kernel<<<(G4 * HID) / 256, 256>>>(Wii, Whi, bi, Wif, Whf, bf,
                                                  Wig, Whg, bg, Wio, Who, bo);
    // 2) embedding gather
    embed_kernel<<<MB_, EMB>>>(X, C);

    // 3) Gin0 = Emb @ Wicat^T + bcat   [16384 x 2048], K=256  (tensor, split-bf16)
    cvt_split_kernel<<<(MB_ * EMB) / 256, 256>>>(p_emb, p_ahi, p_alo, MB_ * EMB);
    cvt_split_kernel<<<(G4 * EMB) / 256, 256>>>(p_wicat, p_bhi, p_blo, G4 * EMB);
    mma_gemm_kernel<<<dim3(G4 / 128, MB_ / 128), 256, MG_SMEM>>>(
        p_ahi, p_alo, p_bhi, p_blo, p_bcat, p_gin, G4, EMB);

    // 4) fold projection: Weff[n][k] = sum_e Wicat[n][e] * Wp[e][k]  (fp32)
    gemm128_kernel<true><<<dim3(HID / 128, G4 / 128), 256>>>(
        p_wicat, Wp, nullptr, p_weff, G4, HID, EMB);
    beff_kernel<<<G4 / 256, 256>>>(bp);

    // 5) layer-0 recurrence: one persistent launch, 64 steps
    zero_hc_kernel<<<BH / 256, 256>>>();
    lstm_layer_kernel<<<dim3(16, 8), 128>>>(1);

    // 6) Gin1 = H0all @ Weff^T + beff  [16384 x 2048], K=512  (tensor)
    cvt_split_kernel<<<(MB_ * HID) / 256, 256>>>(p_h0all, p_ahi, p_alo, MB_ * HID);
    cvt_split_kernel<<<(G4 * HID) / 256, 256>>>(p_weff, p_bhi, p_blo, G4 * HID);
    mma_gemm_kernel<<<dim3(G4 / 128, MB_ / 128), 256, MG_SMEM>>>(
        p_ahi, p_alo, p_bhi, p_blo, p_beff, p_gin, G4, HID);

    // 7) layer-1 recurrence
    zero_hc_kernel<<<BH / 256, 256>>>();
    lstm_layer_kernel<<<dim3(16, 8), 128>>>(0);

    // 8) logits = h_last @ Wfin^T + bfin  [256 x 32000], K=512  (tensor)
    //    (SEQ even -> final h in buffer 0)
    cvt_split_kernel<<<BH / 256, 256>>>(p_h, p_ahi, p_alo, BH);
    cvt_split_kernel<<<(N_CLASS * HID) / 256, 256>>>(Wfin, p_bhi, p_blo, N_CLASS * HID);
    mma_gemm_kernel<<<dim3(N_CLASS / 128, BATCH / 128), 256, MG_SMEM>>>(
        p_ahi, p_alo, p_bhi, p_blo, bfin, out, N_CLASS, HID);
}

// round 10
// speedup vs baseline: 2.6953x; 1.7196x over previous
#include <cuda_runtime.h>
#include <cuda_bf16.h>
#include <math.h>
#include <stdint.h>

// Problem constants
#define N_CLASS 32000
#define EMB     256
#define HID     512
#define BATCH   256
#define SEQ     64
#define G4      2048            // 4 gates * HID (gate-interleaved: n = u*4 + g)
#define MB_     (SEQ*BATCH)     // 16384
#define BH      (BATCH*HID)     // 131072

typedef unsigned long long u64;
typedef unsigned short u16;

// ---------------- static device scratch (allocation-free) ----------------
__device__ __align__(16) float g_gin  [MB_*G4];         // 134 MB gate inputs
__device__ __align__(16) float g_wicat[G4*EMB];         // fp32 (fold + cvt source)
__device__ __align__(16) float g_bcat [G4];
__device__ __align__(16) float g_weff [G4*HID];
__device__ __align__(16) float g_beff [G4];
__device__ __align__(16) u16   g_whqhi[G4*HID];         // hidden weights split bf16
__device__ __align__(16) u16   g_whqlo[G4*HID];
__device__ __align__(16) u16   g_hhi  [2*BH];           // h double buffer (split bf16)
__device__ __align__(16) u16   g_hlo  [2*BH];
__device__ unsigned          g_barcnt;
__device__ volatile unsigned g_bargen;
// split-bf16 A/B operand buffers for the big GEMMs
__device__ __align__(16) u16 g_ahi[MB_*HID];            // emb, then h0all
__device__ __align__(16) u16 g_alo[MB_*HID];
__device__ __align__(16) u16 g_bhi[N_CLASS*HID];
__device__ __align__(16) u16 g_blo[N_CLASS*HID];

// ---------------- small helpers ----------------
__device__ __forceinline__ u64 pack2(float x, float y) {
    u64 r; asm("mov.b64 %0, {%1, %2};" : "=l"(r) : "f"(x), "f"(y)); return r;
}
__device__ __forceinline__ float2 unpack2(u64 v) {
    float2 r; asm("mov.b64 {%0, %1}, %2;" : "=f"(r.x), "=f"(r.y) : "l"(v)); return r;
}
__device__ __forceinline__ void fma2(u64& d, u64 a, u64 b) {
    asm("fma.rn.f32x2 %0, %1, %2, %0;" : "+l"(d) : "l"(a), "l"(b));
}
__device__ __forceinline__ float sigmoidf_(float x) { return 1.0f / (1.0f + expf(-x)); }
__device__ __forceinline__ uint32_t smem_u32(const void* p) {
    uint32_t a;
    asm("{ .reg .u64 t; cvta.to.shared.u64 t, %1; cvt.u32.u64 %0, t; }"
        : "=r"(a) : "l"(p));
    return a;
}
__device__ __forceinline__ void split_bf16(float x, u16& hi, u16& lo) {
    __nv_bfloat16 h = __float2bfloat16(x);
    hi = __bfloat16_as_ushort(h);
    lo = __bfloat16_as_ushort(__float2bfloat16(x - __bfloat162float(h)));
}
__device__ __forceinline__ void st_cg_u16(u16* p, u16 v) {
    asm volatile("st.global.cg.u16 [%0], %1;" :: "l"(p), "h"(v));
}

// ---------------- mma.sync helpers (legacy tensor path, valid on sm_103) -----
__device__ __forceinline__ void ldm_x4(uint32_t* r, uint32_t addr) {
    asm volatile("ldmatrix.sync.aligned.m8n8.x4.shared.b16 {%0,%1,%2,%3}, [%4];"
                 : "=r"(r[0]), "=r"(r[1]), "=r"(r[2]), "=r"(r[3]) : "r"(addr));
}
__device__ __forceinline__ void mma16816(float* c, const uint32_t* a,
                                         uint32_t b0, uint32_t b1) {
    asm volatile(
        "mma.sync.aligned.m16n8k16.row.col.f32.bf16.bf16.f32 "
        "{%0,%1,%2,%3}, {%4,%5,%6,%7}, {%8,%9}, {%0,%1,%2,%3};"
        : "+f"(c[0]), "+f"(c[1]), "+f"(c[2]), "+f"(c[3])
        : "r"(a[0]), "r"(a[1]), "r"(a[2]), "r"(a[3]), "r"(b0), "r"(b1));
}

// ------------- build gate-interleaved weights (whq -> split bf16) -------------
__global__ void __launch_bounds__(256) prep_concat_kernel(
    const float* __restrict__ Wii, const float* __restrict__ Whi, const float* __restrict__ bi,
    const float* __restrict__ Wif, const float* __restrict__ Whf, const float* __restrict__ bf,
    const float* __restrict__ Wig, const float* __restrict__ Whg, const float* __restrict__ bg,
    const float* __restrict__ Wio, const float* __restrict__ Who, const float* __restrict__ bo)
{
    int idx = blockIdx.x * 256 + threadIdx.x;
    if (idx >= G4 * HID) return;
    int n = idx / HID;
    int k = idx - n * HID;
    int u = n >> 2;
    int g = n & 3;
    const float* Wh = (g == 0) ? Whi : (g == 1) ? Whf : (g == 2) ? Whg : Who;
    u16 hi, lo;
    split_bf16(Wh[u * HID + k], hi, lo);
    g_whqhi[idx] = hi;
    g_whqlo[idx] = lo;
    if (k < EMB) {
        const float* Wi = (g == 0) ? Wii : (g == 1) ? Wif : (g == 2) ? Wig : Wio;
        g_wicat[n * EMB + k] = Wi[u * EMB + k];
    }
    if (k == 0) {
        const float* bv = (g == 0) ? bi : (g == 1) ? bf : (g == 2) ? bg : bo;
        g_bcat[n] = bv[u];
    }
}

// ------------- embedding gather -> split bf16 directly -------------
__global__ void __launch_bounds__(EMB) embed_kernel(const int* __restrict__ X,
                                                    const float* __restrict__ C)
{
    int sb = blockIdx.x;
    int s  = sb >> 8;
    int b  = sb & 255;
    int row = X[b * SEQ + s];
    float v = C[(size_t)row * EMB + threadIdx.x];
    u16 hi, lo;
    split_bf16(v, hi, lo);
    g_ahi[(size_t)sb * EMB + threadIdx.x] = hi;
    g_alo[(size_t)sb * EMB + threadIdx.x] = lo;
}

// ------------- fp32 -> split bf16 (hi + lo) -------------
__global__ void __launch_bounds__(256) cvt_split_kernel(
    const float* __restrict__ src, u16* __restrict__ hi,
    u16* __restrict__ lo, int n)
{
    int i = blockIdx.x * 256 + threadIdx.x;
    if (i >= n) return;
    u16 h, l;
    split_bf16(src[i], h, l);
    hi[i] = h;
    lo[i] = l;
}

// ------------- split-bf16 tensor-core GEMM via mma.sync (R9 known-good) -------
#define MG_ROWU  40
#define MG_TILEU (128*MG_ROWU)
#define MG_STGU  (4*MG_TILEU)
#define MG_SMEM  (2*MG_STGU*2)

__device__ __forceinline__ void mg_load_stage(
    u16* s, const u16* __restrict__ Ahi, const u16* __restrict__ Alo,
    const u16* __restrict__ Bhi, const u16* __restrict__ Blo,
    int bm, int bn, int K, int k0, int tid)
{
#pragma unroll
    for (int t = 0; t < 2; t++) {
        int idx = tid + 256 * t;
        int row = idx >> 2, seg = (idx & 3) * 8;
        size_t ga = (size_t)(bm + row) * K + k0 + seg;
        size_t gb = (size_t)(bn + row) * K + k0 + seg;
        u16* d = s + row * MG_ROWU + seg;
        *(uint4*)(d + 0 * MG_TILEU) = *(const uint4*)(Ahi + ga);
        *(uint4*)(d + 1 * MG_TILEU) = *(const uint4*)(Alo + ga);
        *(uint4*)(d + 2 * MG_TILEU) = *(const uint4*)(Bhi + gb);
        *(uint4*)(d + 3 * MG_TILEU) = *(const uint4*)(Blo + gb);
    }
}

__global__ void __launch_bounds__(256) mma_gemm_kernel(
    const u16* __restrict__ Ahi, const u16* __restrict__ Alo,
    const u16* __restrict__ Bhi, const u16* __restrict__ Blo,
    const float* __restrict__ bias, float* __restrict__ Y, int N, int K)
{
    extern __shared__ u16 smu[];
    uint32_t smb = smem_u32(smu);
    int tid  = threadIdx.x;
    int w    = tid >> 5;
    int lane = tid & 31;
    int bm = blockIdx.y * 128;
    int bn = blockIdx.x * 128;
    int wm = (w & 3) * 32;
    int wn = (w >> 2) * 64;
    int nch = K >> 5;

    int mat = lane >> 3, mi = lane & 7;
    uint32_t aoff = (uint32_t)((wm + (mat & 1) * 8 + mi) * 80 + (mat >> 1) * 16);
    uint32_t boff = (uint32_t)((wn + (mat >> 1) * 8 + mi) * 80 + (mat & 1) * 16);

    float acc[2][8][4];
#pragma unroll
    for (int i = 0; i < 2; i++)
#pragma unroll
        for (int j = 0; j < 8; j++)
#pragma unroll
            for (int q = 0; q < 4; q++) acc[i][j][q] = 0.0f;

    mg_load_stage(smu, Ahi, Alo, Bhi, Blo, bm, bn, K, 0, tid);
    __syncthreads();

    for (int c = 0; c < nch; c++) {
        if (c + 1 < nch)
            mg_load_stage(smu + ((c + 1) & 1) * MG_STGU, Ahi, Alo, Bhi, Blo,
                          bm, bn, K, (c + 1) * 32, tid);

        uint32_t sb = smb + (uint32_t)((c & 1) * MG_STGU * 2);
#pragma unroll
        for (int k16 = 0; k16 < 2; k16++) {
            uint32_t kb = (uint32_t)(k16 * 32);
            uint32_t ah[2][4], al[2][4];
            ldm_x4(ah[0], sb + 0 * 10240 + aoff + kb);
            ldm_x4(ah[1], sb + 0 * 10240 + aoff + kb + 16 * 80);
            ldm_x4(al[0], sb + 1 * 10240 + aoff + kb);
            ldm_x4(al[1], sb + 1 * 10240 + aoff + kb + 16 * 80);
#pragma unroll
            for (int nb = 0; nb < 4; nb++) {
                uint32_t bh[4], bl[4];
                uint32_t bo = boff + kb + (uint32_t)(nb * 16 * 80);
                ldm_x4(bh, sb + 2 * 10240 + bo);
                ldm_x4(bl, sb + 3 * 10240 + bo);
#pragma unroll
                for (int mb = 0; mb < 2; mb++) {
#pragma unroll
                    for (int h = 0; h < 2; h++) {
                        float* cc = acc[mb][nb * 2 + h];
                        mma16816(cc, ah[mb], bh[2 * h], bh[2 * h + 1]);
                        mma16816(cc, ah[mb], bl[2 * h], bl[2 * h + 1]);
                        mma16816(cc, al[mb], bh[2 * h], bh[2 * h + 1]);
                    }
                }
            }
        }
        __syncthreads();
    }

    int grp = lane >> 2, t2 = lane & 3;
#pragma unroll
    for (int mb = 0; mb < 2; mb++) {
#pragma unroll
        for (int nj = 0; nj < 8; nj++) {
            int n = bn + wn + nj * 8 + t2 * 2;
            float2 bv = *(const float2*)&bias[n];
            int mlo = bm + wm + mb * 16 + grp;
            const float* cc = acc[mb][nj];
            float2 v0 = make_float2(cc[0] + bv.x, cc[1] + bv.y);
            float2 v1 = make_float2(cc[2] + bv.x, cc[3] + bv.y);
            *(float2*)&Y[(size_t)mlo * N + n]       = v0;
            *(float2*)&Y[(size_t)(mlo + 8) * N + n] = v1;
        }
    }
}

// ------------- fp32 fold GEMM (known-good), TRANSB -------------
template <bool TRANSB>
__global__ void __launch_bounds__(256) gemm128_kernel(
    const float* __restrict__ A, const float* __restrict__ B,
    const float* __restrict__ bias, float* __restrict__ Y,
    int M, int N, int K)
{
    const int BK = 16;
    __shared__ float As[BK][128];
    __shared__ float Bs[BK][128];

    int bm = blockIdx.y * 128;
    int bn = blockIdx.x * 128;
    int tid = threadIdx.x;
    int tx = tid & 15;
    int ty = tid >> 4;
    int m0 = ty * 8;
    int n0 = tx * 8;

    u64 acc[8][4];
#pragma unroll
    for (int i = 0; i < 8; i++)
#pragma unroll
        for (int j = 0; j < 4; j++) acc[i][j] = 0ULL;

    for (int k0 = 0; k0 < K; k0 += BK) {
#pragma unroll
        for (int l = tid; l < 512; l += 256) {
            int r = l >> 2, kq = l & 3;
            float4 v = *(const float4*)&A[(size_t)(bm + r) * K + k0 + kq * 4];
            As[kq * 4 + 0][r] = v.x; As[kq * 4 + 1][r] = v.y;
            As[kq * 4 + 2][r] = v.z; As[kq * 4 + 3][r] = v.w;
        }
        if (!TRANSB) {
#pragma unroll
            for (int l = tid; l < 512; l += 256) {
                int r = l >> 2, kq = l & 3;
                float4 v = *(const float4*)&B[(size_t)(bn + r) * K + k0 + kq * 4];
                Bs[kq * 4 + 0][r] = v.x; Bs[kq * 4 + 1][r] = v.y;
                Bs[kq * 4 + 2][r] = v.z; Bs[kq * 4 + 3][r] = v.w;
            }
        } else {
#pragma unroll
            for (int l = tid; l < 512; l += 256) {
                int k = l >> 5, nq = l & 31;
                *(float4*)&Bs[k][nq * 4] =
                    *(const float4*)&B[(size_t)(k0 + k) * N + bn + nq * 4];
            }
        }
        __syncthreads();

#pragma unroll
        for (int k = 0; k < BK; k++) {
            float4 av0 = *(const float4*)&As[k][m0];
            float4 av1 = *(const float4*)&As[k][m0 + 4];
            u64 bp[4];
            bp[0] = *(const u64*)&Bs[k][n0];
            bp[1] = *(const u64*)&Bs[k][n0 + 2];
            bp[2] = *(const u64*)&Bs[k][n0 + 4];
            bp[3] = *(const u64*)&Bs[k][n0 + 6];
            float am[8] = {av0.x, av0.y, av0.z, av0.w, av1.x, av1.y, av1.z, av1.w};
#pragma unroll
            for (int i = 0; i < 8; i++) {
                u64 ad = pack2(am[i], am[i]);
#pragma unroll
                for (int j = 0; j < 4; j++) fma2(acc[i][j], ad, bp[j]);
            }
        }
        __syncthreads();
    }

#pragma unroll
    for (int i = 0; i < 8; i++) {
        int m = bm + m0 + i;
        float2 p0 = unpack2(acc[i][0]), p1 = unpack2(acc[i][1]);
        float2 p2 = unpack2(acc[i][2]), p3 = unpack2(acc[i][3]);
        float4 v0 = make_float4(p0.x, p0.y, p1.x, p1.y);
        float4 v1 = make_float4(p2.x, p2.y, p3.x, p3.y);
        *(float4*)&Y[(size_t)m * N + bn + n0]     = v0;
        *(float4*)&Y[(size_t)m * N + bn + n0 + 4] = v1;
    }
}

// ------------- software grid barrier (128 blocks co-resident) -------------
__device__ __forceinline__ void gridbar(unsigned target)
{
    __threadfence();
    __syncthreads();
    if (threadIdx.x == 0) {
        if (atomicAdd(&g_barcnt, 1u) == 127u) {
            g_barcnt = 0u;
            __threadfence();
            g_bargen = target;
        } else {
            while (g_bargen < target) { }
        }
    }
    __syncthreads();
}

// ------------- persistent LSTM layer, tensor-core step GEMM -------------
// grid (16,8) = 128 blocks, 256 threads (8 warps: 2m x 4n).
// Block tile: 32 batch x 128 gates x K512, split-bf16 3-term mma.
#define LS_A_LO   16640
#define LS_B_BASE 33280
#define LS_SMEMU  (33280 + 4*5120)          // 53760 u16
#define LS_SMEM   (LS_SMEMU*2)              // 107520 bytes

__global__ void __launch_bounds__(256) lstm_layer_mma_kernel(int store_all)
{
    extern __shared__ u16 smu[];
    uint32_t smb = smem_u32(smu);
    int tid  = threadIdx.x;
    int w    = tid >> 5;
    int lane = tid & 31;
    int bn = blockIdx.x * 128;
    int bm = blockIdx.y * 32;
    int wm = (w & 1) * 16;
    int wn = (w >> 1) * 32;

    int mat = lane >> 3, mi = lane & 7;
    // A tile rows padded to 520 u16 (1040 B) -> conflict-free ldmatrix
    uint32_t aoff = (uint32_t)((wm + (mat & 1) * 8 + mi) * 1040 + (mat >> 1) * 16);
    // B tile rows padded to 40 u16 (80 B)
    uint32_t boff = (uint32_t)((wn + (mat >> 1) * 8 + mi) * 80 + (mat & 1) * 16);

    int grp = lane >> 2, t2 = lane & 3;
    int m0r = bm + wm + grp;
    bool owner = (t2 & 1) == 0;

    float cst[4][2];
#pragma unroll
    for (int j = 0; j < 4; j++) { cst[j][0] = 0.0f; cst[j][1] = 0.0f; }

    for (int s = 0; s < SEQ; s++) {
        const u16* hp_hi = g_hhi + (s & 1) * BH;
        const u16* hp_lo = g_hlo + (s & 1) * BH;
        u16* hn_hi = g_hhi + ((s + 1) & 1) * BH;
        u16* hn_lo = g_hlo + ((s + 1) & 1) * BH;

        // ---- load A (h prev, 32 rows x 512 u16, hi+lo) ----
#pragma unroll
        for (int t = 0; t < 8; t++) {
            int i = tid + t * 256;          // 0..2047
            int r = i >> 6, c = i & 63;
            size_t gsrc = (size_t)(bm + r) * HID + c * 8;
            *(uint4*)&smu[r * 520 + c * 8] =
                __ldcg((const uint4*)&hp_hi[gsrc]);
            *(uint4*)&smu[LS_A_LO + r * 520 + c * 8] =
                __ldcg((const uint4*)&hp_lo[gsrc]);
        }
        // ---- load B chunk 0 into buf 0 ----
#pragma unroll
        for (int t = 0; t < 2; t++) {
            int idx = tid + t * 256;
            int r = idx >> 2, c4 = idx & 3;
            size_t gsrc = (size_t)(bn + r) * HID + c4 * 8;
            *(uint4*)&smu[LS_B_BASE + r * 40 + c4 * 8] =
                *(const uint4*)&g_whqhi[gsrc];
            *(uint4*)&smu[LS_B_BASE + 5120 + r * 40 + c4 * 8] =
                *(const uint4*)&g_whqlo[gsrc];
        }
        __syncthreads();

        float acc[4][4];
#pragma unroll
        for (int j = 0; j < 4; j++)
#pragma unroll
            for (int q = 0; q < 4; q++) acc[j][q] = 0.0f;

        for (int ch = 0; ch < 16; ch++) {
            if (ch + 1 < 16) {
                int nb = (ch + 1) & 1;
#pragma unroll
                for (int t = 0; t < 2; t++) {
                    int idx = tid + t * 256;
                    int r = idx >> 2, c4 = idx & 3;
                    size_t gsrc = (size_t)(bn + r) * HID + (ch + 1) * 32 + c4 * 8;
                    *(uint4*)&smu[LS_B_BASE + nb * 10240 + r * 40 + c4 * 8] =
                        *(const uint4*)&g_whqhi[gsrc];
                    *(uint4*)&smu[LS_B_BASE + nb * 10240 + 5120 + r * 40 + c4 * 8] =
                        *(const uint4*)&g_whqlo[gsrc];
                }
            }

            uint32_t bbase = smb + (uint32_t)((LS_B_BASE + (ch & 1) * 10240) * 2) + boff;
#pragma unroll
            for (int k16 = 0; k16 < 2; k16++) {
                uint32_t ka = (uint32_t)(ch * 64 + k16 * 32);
                uint32_t kb = (uint32_t)(k16 * 32);
                uint32_t ah[4], al[4], bh0[4], bh1[4], bl0[4], bl1[4];
                ldm_x4(ah, smb + aoff + ka);
                ldm_x4(al, smb + (uint32_t)(LS_A_LO * 2) + aoff + ka);
                ldm_x4(bh0, bbase + kb);
                ldm_x4(bh1, bbase + kb + 16 * 80);
                ldm_x4(bl0, bbase + (uint32_t)(5120 * 2) + kb);
                ldm_x4(bl1, bbase + (uint32_t)(5120 * 2) + kb + 16 * 80);

                mma16816(acc[0], ah, bh0[0], bh0[1]);
                mma16816(acc[0], ah, bl0[0], bl0[1]);
                mma16816(acc[0], al, bh0[0], bh0[1]);
                mma16816(acc[1], ah, bh0[2], bh0[3]);
                mma16816(acc[1], ah, bl0[2], bl0[3]);
                mma16816(acc[1], al, bh0[2], bh0[3]);
                mma16816(acc[2], ah, bh1[0], bh1[1]);
                mma16816(acc[2], ah, bl1[0], bl1[1]);
                mma16816(acc[2], al, bh1[0], bh1[1]);
                mma16816(acc[3], ah, bh1[2], bh1[3]);
                mma16816(acc[3], ah, bl1[2], bl1[3]);
                mma16816(acc[3], al, bh1[2], bh1[3]);
            }
            __syncthreads();
        }

        // ---- epilogue: gin add, gate pair-exchange, LSTM cell, h store ----
#pragma unroll
        for (int nj = 0; nj < 4; nj++) {
            int ncol = bn + wn + nj * 8 + t2 * 2;
            const float* gp = &g_gin[((size_t)(s * BATCH + m0r)) * G4 + ncol];
            float2 gv0 = *(const float2*)gp;
            float2 gv1 = *(const float2*)(gp + 8 * G4);
            float fa = acc[nj][0] + gv0.x;
            float fb = acc[nj][1] + gv0.y;
            float fc = acc[nj][2] + gv1.x;
            float fd = acc[nj][3] + gv1.y;
            float pa = __shfl_xor_sync(0xffffffffu, fa, 1);
            float pb = __shfl_xor_sync(0xffffffffu, fb, 1);
            float pc = __shfl_xor_sync(0xffffffffu, fc, 1);
            float pd = __shfl_xor_sync(0xffffffffu, fd, 1);
            if (owner) {
                int u = ncol >> 2;
                {
                    float ig = sigmoidf_(fa), fg = sigmoidf_(fb);
                    float gg = tanhf(pa),     og = sigmoidf_(pb);
                    float cn = fg * cst[nj][0] + ig * gg;
                    cst[nj][0] = cn;
                    float hv = og * tanhf(cn);
                    u16 hi, lo; split_bf16(hv, hi, lo);
                    size_t idx = (size_t)m0r * HID + u;
                    st_cg_u16(&hn_hi[idx], hi);
                    st_cg_u16(&hn_lo[idx], lo);
                    if (store_all) {
                        size_t oidx = ((size_t)(s * BATCH + m0r)) * HID + u;
                        g_ahi[oidx] = hi; g_alo[oidx] = lo;
                    }
                }
                {
                    float ig = sigmoidf_(fc), fg = sigmoidf_(fd);
                    float gg = tanhf(pc),     og = sigmoidf_(pd);
                    float cn = fg * cst[nj][1] + ig * gg;
                    cst[nj][1] = cn;
                    float hv = og * tanhf(cn);
                    u16 hi, lo; split_bf16(hv, hi, lo);
                    size_t idx = (size_t)(m0r + 8) * HID + u;
                    st_cg_u16(&hn_hi[idx], hi);
                    st_cg_u16(&hn_lo[idx], lo);
                    if (store_all) {
                        size_t oidx = ((size_t)(s * BATCH + m0r + 8)) * HID + u;
                        g_ahi[oidx] = hi; g_alo[oidx] = lo;
                    }
                }
            }
        }

        if (s != SEQ - 1) gridbar((unsigned)(s + 1));
    }
}

// ------------- beff[n] = bcat[n] + sum_e Wicat[n][e] * b_proj[e] -------------
__global__ void __launch_bounds__(256) beff_kernel(const float* __restrict__ bproj)
{
    int n = blockIdx.x * 256 + threadIdx.x;
    if (n >= G4) return;
    float s = g_bcat[n];
    const float* w = &g_wicat[n * EMB];
    for (int e = 0; e < EMB; e++) s += w[e] * bproj[e];
    g_beff[n] = s;
}

// ------------- zero h buffer 0 + reset grid barrier -------------
__global__ void __launch_bounds__(256) zero_h_kernel()
{
    int i = blockIdx.x * 256 + threadIdx.x;
    if (i < BH) { g_hhi[i] = 0; g_hlo[i] = 0; }
    if (i == 0) { g_barcnt = 0u; g_bargen = 0u; }
}

// =============================== launch ===============================
extern "C" void kernel_launch(void* const* d_in, const int* in_sizes, int n_in,
                              void* d_out, int out_size)
{
    const int*   X    = (const int*)  d_in[0];
    const float* C    = (const float*)d_in[1];
    const float* Wii  = (const float*)d_in[2];
    const float* Whi  = (const float*)d_in[3];
    const float* bi   = (const float*)d_in[4];
    const float* Wif  = (const float*)d_in[5];
    const float* Whf  = (const float*)d_in[6];
    const float* bf   = (const float*)d_in[7];
    const float* Wig  = (const float*)d_in[8];
    const float* Whg  = (const float*)d_in[9];
    const float* bg   = (const float*)d_in[10];
    const float* Wio  = (const float*)d_in[11];
    const float* Who  = (const float*)d_in[12];
    const float* bo   = (const float*)d_in[13];
    const float* Wp   = (const float*)d_in[14];   // [EMB, HID]
    const float* bp   = (const float*)d_in[15];   // [EMB]
    const float* Wfin = (const float*)d_in[16];   // [N_CLASS, HID]
    const float* bfin = (const float*)d_in[17];   // [N_CLASS]
    float* out = (float*)d_out;

    float *p_gin, *p_wicat, *p_bcat, *p_weff, *p_beff;
    u16 *p_ahi, *p_alo, *p_bhi, *p_blo, *p_hhi, *p_hlo;
    cudaGetSymbolAddress((void**)&p_gin,   g_gin);
    cudaGetSymbolAddress((void**)&p_wicat, g_wicat);
    cudaGetSymbolAddress((void**)&p_bcat,  g_bcat);
    cudaGetSymbolAddress((void**)&p_weff,  g_weff);
    cudaGetSymbolAddress((void**)&p_beff,  g_beff);
    cudaGetSymbolAddress((void**)&p_ahi,   g_ahi);
    cudaGetSymbolAddress((void**)&p_alo,   g_alo);
    cudaGetSymbolAddress((void**)&p_bhi,   g_bhi);
    cudaGetSymbolAddress((void**)&p_blo,   g_blo);
    cudaGetSymbolAddress((void**)&p_hhi,   g_hhi);
    cudaGetSymbolAddress((void**)&p_hlo,   g_hlo);

    cudaFuncSetAttribute(mma_gemm_kernel,
                         cudaFuncAttributeMaxDynamicSharedMemorySize, MG_SMEM);
    cudaFuncSetAttribute(lstm_layer_mma_kernel,
                         cudaFuncAttributeMaxDynamicSharedMemorySize, LS_SMEM);

    // 1) weight prep
    prep_concat_kernel<<<(G4 * HID) / 256, 256>>>(Wii, Whi, bi, Wif, Whf, bf,
                                                  Wig, Whg, bg, Wio, Who, bo);
    // 2) embedding gather -> split bf16 A
    embed_kernel<<<MB_, EMB>>>(X, C);

    // 3) Gin0 = Emb @ Wicat^T + bcat   [16384 x 2048], K=256
    cvt_split_kernel<<<(G4 * EMB) / 256, 256>>>(p_wicat, p_bhi, p_blo, G4 * EMB);
    mma_gemm_kernel<<<dim3(G4 / 128, MB_ / 128), 256, MG_SMEM>>>(
        p_ahi, p_alo, p_bhi, p_blo, p_bcat, p_gin, G4, EMB);

    // 4) fold projection: Weff = Wicat @ Wp  (fp32), beff; cvt to bf16 B
    gemm128_kernel<true><<<dim3(HID / 128, G4 / 128), 256>>>(
        p_wicat, Wp, nullptr, p_weff, G4, HID, EMB);
    beff_kernel<<<G4 / 256, 256>>>(bp);
    cvt_split_kernel<<<(G4 * HID) / 256, 256>>>(p_weff, p_bhi, p_blo, G4 * HID);

    // 5) layer-0 recurrence (persistent, tensor-core; h0all -> g_ahi/g_alo)
    zero_h_kernel<<<BH / 256, 256>>>();
    lstm_layer_mma_kernel<<<dim3(16, 8), 256, LS_SMEM>>>(1);

    // 6) Gin1 = H0all @ Weff^T + beff  [16384 x 2048], K=512
    mma_gemm_kernel<<<dim3(G4 / 128, MB_ / 128), 256, MG_SMEM>>>(
        p_ahi, p_alo, p_bhi, p_blo, p_beff, p_gin, G4, HID);

    // 7) layer-1 recurrence
    zero_h_kernel<<<BH / 256, 256>>>();
    lstm_layer_mma_kernel<<<dim3(16, 8), 256, LS_SMEM>>>(0);

    // 8) logits = h_last @ Wfin^T + bfin  [256 x 32000], K=512
    //    (SEQ even -> final h in buffer 0 of g_hhi/g_hlo)
    cvt_split_kernel<<<(N_CLASS * HID) / 256, 256>>>(Wfin, p_bhi, p_blo, N_CLASS * HID);
    mma_gemm_kernel<<<dim3(N_CLASS / 128, BATCH / 128), 256, MG_SMEM>>>(
        p_hhi, p_hlo, p_bhi, p_blo, bfin, out, N_CLASS, HID);
}

// round 11
// speedup vs baseline: 3.4352x; 1.2745x over previous
#include <cuda_runtime.h>
#include <cuda_bf16.h>
#include <math.h>
#include <stdint.h>

// Problem constants
#define N_CLASS 32000
#define EMB     256
#define HID     512
#define BATCH   256
#define SEQ     64
#define G4      2048            // 4 gates * HID (gate-interleaved: n = u*4 + g)
#define MB_     (SEQ*BATCH)     // 16384
#define BH      (BATCH*HID)     // 131072

typedef unsigned long long u64;
typedef unsigned short u16;

// ---------------- static device scratch (allocation-free) ----------------
__device__ __align__(16) float g_gin  [MB_*G4];         // 134 MB gate inputs
__device__ __align__(16) float g_wicat[G4*EMB];         // fp32 (fold + cvt source)
__device__ __align__(16) float g_bcat [G4];
__device__ __align__(16) float g_weff [G4*HID];
__device__ __align__(16) float g_beff [G4];
__device__ __align__(16) u16   g_whqhi[G4*HID];         // hidden weights split bf16
__device__ __align__(16) u16   g_whqlo[G4*HID];
__device__ __align__(16) u16   g_hhi  [2*BH];           // h double buffer (split bf16)
__device__ __align__(16) u16   g_hlo  [2*BH];
__device__ unsigned          g_barcnt;
__device__ volatile unsigned g_bargen;
// split-bf16 A/B operand buffers for the big GEMMs
__device__ __align__(16) u16 g_ahi[MB_*HID];            // emb, then h0all
__device__ __align__(16) u16 g_alo[MB_*HID];
__device__ __align__(16) u16 g_bhi[N_CLASS*HID];
__device__ __align__(16) u16 g_blo[N_CLASS*HID];

// ---------------- small helpers ----------------
__device__ __forceinline__ u64 pack2(float x, float y) {
    u64 r; asm("mov.b64 %0, {%1, %2};" : "=l"(r) : "f"(x), "f"(y)); return r;
}
__device__ __forceinline__ float2 unpack2(u64 v) {
    float2 r; asm("mov.b64 {%0, %1}, %2;" : "=f"(r.x), "=f"(r.y) : "l"(v)); return r;
}
__device__ __forceinline__ void fma2(u64& d, u64 a, u64 b) {
    asm("fma.rn.f32x2 %0, %1, %2, %0;" : "+l"(d) : "l"(a), "l"(b));
}
__device__ __forceinline__ float sigmoidf_(float x) { return 1.0f / (1.0f + expf(-x)); }
__device__ __forceinline__ uint32_t smem_u32(const void* p) {
    uint32_t a;
    asm("{ .reg .u64 t; cvta.to.shared.u64 t, %1; cvt.u32.u64 %0, t; }"
        : "=r"(a) : "l"(p));
    return a;
}
__device__ __forceinline__ void split_bf16(float x, u16& hi, u16& lo) {
    __nv_bfloat16 h = __float2bfloat16(x);
    hi = __bfloat16_as_ushort(h);
    lo = __bfloat16_as_ushort(__float2bfloat16(x - __bfloat162float(h)));
}
__device__ __forceinline__ void st_cg_u16(u16* p, u16 v) {
    asm volatile("st.global.cg.u16 [%0], %1;" :: "l"(p), "h"(v));
}

// ---------------- cp.async helpers ----------------
__device__ __forceinline__ void cp16(uint32_t saddr, const void* g) {
    asm volatile("cp.async.cg.shared.global [%0], [%1], 16;"
                 :: "r"(saddr), "l"(g) : "memory");
}
#define CP_COMMIT() asm volatile("cp.async.commit_group;" ::: "memory")
#define CP_WAIT2()  asm volatile("cp.async.wait_group 2;" ::: "memory")

// ---------------- mma.sync helpers (legacy tensor path, valid on sm_103) -----
__device__ __forceinline__ void ldm_x4(uint32_t* r, uint32_t addr) {
    asm volatile("ldmatrix.sync.aligned.m8n8.x4.shared.b16 {%0,%1,%2,%3}, [%4];"
                 : "=r"(r[0]), "=r"(r[1]), "=r"(r[2]), "=r"(r[3]) : "r"(addr));
}
__device__ __forceinline__ void mma16816(float* c, const uint32_t* a,
                                         uint32_t b0, uint32_t b1) {
    asm volatile(
        "mma.sync.aligned.m16n8k16.row.col.f32.bf16.bf16.f32 "
        "{%0,%1,%2,%3}, {%4,%5,%6,%7}, {%8,%9}, {%0,%1,%2,%3};"
        : "+f"(c[0]), "+f"(c[1]), "+f"(c[2]), "+f"(c[3])
        : "r"(a[0]), "r"(a[1]), "r"(a[2]), "r"(a[3]), "r"(b0), "r"(b1));
}

// ------------- build gate-interleaved weights (whq -> split bf16) -------------
__global__ void __launch_bounds__(256) prep_concat_kernel(
    const float* __restrict__ Wii, const float* __restrict__ Whi, const float* __restrict__ bi,
    const float* __restrict__ Wif, const float* __restrict__ Whf, const float* __restrict__ bf,
    const float* __restrict__ Wig, const float* __restrict__ Whg, const float* __restrict__ bg,
    const float* __restrict__ Wio, const float* __restrict__ Who, const float* __restrict__ bo)
{
    int idx = blockIdx.x * 256 + threadIdx.x;
    if (idx >= G4 * HID) return;
    int n = idx / HID;
    int k = idx - n * HID;
    int u = n >> 2;
    int g = n & 3;
    const float* Wh = (g == 0) ? Whi : (g == 1) ? Whf : (g == 2) ? Whg : Who;
    u16 hi, lo;
    split_bf16(Wh[u * HID + k], hi, lo);
    g_whqhi[idx] = hi;
    g_whqlo[idx] = lo;
    if (k < EMB) {
        const float* Wi = (g == 0) ? Wii : (g == 1) ? Wif : (g == 2) ? Wig : Wio;
        g_wicat[n * EMB + k] = Wi[u * EMB + k];
    }
    if (k == 0) {
        const float* bv = (g == 0) ? bi : (g == 1) ? bf : (g == 2) ? bg : bo;
        g_bcat[n] = bv[u];
    }
}

// ------------- embedding gather -> split bf16 directly -------------
__global__ void __launch_bounds__(EMB) embed_kernel(const int* __restrict__ X,
                                                    const float* __restrict__ C)
{
    int sb = blockIdx.x;
    int s  = sb >> 8;
    int b  = sb & 255;
    int row = X[b * SEQ + s];
    float v = C[(size_t)row * EMB + threadIdx.x];
    u16 hi, lo;
    split_bf16(v, hi, lo);
    g_ahi[(size_t)sb * EMB + threadIdx.x] = hi;
    g_alo[(size_t)sb * EMB + threadIdx.x] = lo;
}

// ------------- fp32 -> split bf16 (hi + lo) -------------
__global__ void __launch_bounds__(256) cvt_split_kernel(
    const float* __restrict__ src, u16* __restrict__ hi,
    u16* __restrict__ lo, int n)
{
    int i = blockIdx.x * 256 + threadIdx.x;
    if (i >= n) return;
    u16 h, l;
    split_bf16(src[i], h, l);
    hi[i] = h;
    lo[i] = l;
}

// ------------- split-bf16 tensor-core GEMM, 4-stage cp.async pipeline ---------
// Y[m][n] = bias[n] + sum_k A[m][k]*B[n][k]   (3-term compensated bf16)
// CTA tile 128x128, 8 warps (warp w: m-block (w&3)*32, n-block (w>>2)*64).
// Stage = 32 k. Arrays per stage: Ahi, Alo, Bhi, Blo; rows padded to 80 B.
#define MG_ROWU  40
#define MG_ARRU  (128*MG_ROWU)            // 5120 u16 per array per stage
#define MG_STGU  (4*MG_ARRU)              // 20480 u16 per stage
#define MG_SMEM  (4*MG_STGU*2)            // 163840 bytes

__device__ __forceinline__ void mg_issue_stage(
    uint32_t sbase, const u16* __restrict__ Ahi, const u16* __restrict__ Alo,
    const u16* __restrict__ Bhi, const u16* __restrict__ Blo,
    int bm, int bn, int K, int k0, int tid)
{
#pragma unroll
    for (int t = 0; t < 2; t++) {
        int idx = tid + 256 * t;            // 0..511
        int row = idx >> 2, seg = (idx & 3) * 8;
        size_t ga = (size_t)(bm + row) * K + k0 + seg;
        size_t gb = (size_t)(bn + row) * K + k0 + seg;
        uint32_t d = sbase + (uint32_t)((row * MG_ROWU + seg) * 2);
        cp16(d + 0u * (MG_ARRU * 2), Ahi + ga);
        cp16(d + 1u * (MG_ARRU * 2), Alo + ga);
        cp16(d + 2u * (MG_ARRU * 2), Bhi + gb);
        cp16(d + 3u * (MG_ARRU * 2), Blo + gb);
    }
}

__global__ void __launch_bounds__(256) mma_gemm_kernel(
    const u16* __restrict__ Ahi, const u16* __restrict__ Alo,
    const u16* __restrict__ Bhi, const u16* __restrict__ Blo,
    const float* __restrict__ bias, float* __restrict__ Y, int N, int K)
{
    extern __shared__ u16 smu[];
    uint32_t smb = smem_u32(smu);
    int tid  = threadIdx.x;
    int w    = tid >> 5;
    int lane = tid & 31;
    int bm = blockIdx.y * 128;
    int bn = blockIdx.x * 128;
    int wm = (w & 3) * 32;
    int wn = (w >> 2) * 64;
    int nch = K >> 5;

    int mat = lane >> 3, mi = lane & 7;
    uint32_t aoff = (uint32_t)((wm + (mat & 1) * 8 + mi) * 80 + (mat >> 1) * 16);
    uint32_t boff = (uint32_t)((wn + (mat >> 1) * 8 + mi) * 80 + (mat & 1) * 16);

    float acc[2][8][4];
#pragma unroll
    for (int i = 0; i < 2; i++)
#pragma unroll
        for (int j = 0; j < 8; j++)
#pragma unroll
            for (int q = 0; q < 4; q++) acc[i][j][q] = 0.0f;

    // prologue: stages 0..2
#pragma unroll
    for (int p = 0; p < 3; p++) {
        if (p < nch)
            mg_issue_stage(smb + (uint32_t)(p * MG_STGU * 2),
                           Ahi, Alo, Bhi, Blo, bm, bn, K, p * 32, tid);
        CP_COMMIT();
    }

    for (int c = 0; c < nch; c++) {
        CP_WAIT2();
        __syncthreads();
        if (c + 3 < nch)
            mg_issue_stage(smb + (uint32_t)(((c + 3) & 3) * MG_STGU * 2),
                           Ahi, Alo, Bhi, Blo, bm, bn, K, (c + 3) * 32, tid);
        CP_COMMIT();

        uint32_t sb = smb + (uint32_t)((c & 3) * MG_STGU * 2);
#pragma unroll
        for (int k16 = 0; k16 < 2; k16++) {
            uint32_t kb = (uint32_t)(k16 * 32);
            uint32_t ah[2][4], al[2][4];
            ldm_x4(ah[0], sb + 0 * 10240 + aoff + kb);
            ldm_x4(ah[1], sb + 0 * 10240 + aoff + kb + 16 * 80);
            ldm_x4(al[0], sb + 1 * 10240 + aoff + kb);
            ldm_x4(al[1], sb + 1 * 10240 + aoff + kb + 16 * 80);
#pragma unroll
            for (int nb = 0; nb < 4; nb++) {
                uint32_t bh[4], bl[4];
                uint32_t bo = boff + kb + (uint32_t)(nb * 16 * 80);
                ldm_x4(bh, sb + 2 * 10240 + bo);
                ldm_x4(bl, sb + 3 * 10240 + bo);
#pragma unroll
                for (int mb = 0; mb < 2; mb++) {
#pragma unroll
                    for (int h = 0; h < 2; h++) {
                        float* cc = acc[mb][nb * 2 + h];
                        mma16816(cc, ah[mb], bh[2 * h], bh[2 * h + 1]);
                        mma16816(cc, ah[mb], bl[2 * h], bl[2 * h + 1]);
                        mma16816(cc, al[mb], bh[2 * h], bh[2 * h + 1]);
                    }
                }
            }
        }
    }

    int grp = lane >> 2, t2 = lane & 3;
#pragma unroll
    for (int mb = 0; mb < 2; mb++) {
#pragma unroll
        for (int nj = 0; nj < 8; nj++) {
            int n = bn + wn + nj * 8 + t2 * 2;
            float2 bv = *(const float2*)&bias[n];
            int mlo = bm + wm + mb * 16 + grp;
            const float* cc = acc[mb][nj];
            float2 v0 = make_float2(cc[0] + bv.x, cc[1] + bv.y);
            float2 v1 = make_float2(cc[2] + bv.x, cc[3] + bv.y);
            *(float2*)&Y[(size_t)mlo * N + n]       = v0;
            *(float2*)&Y[(size_t)(mlo + 8) * N + n] = v1;
        }
    }
}

// ------------- fp32 fold GEMM (known-good), TRANSB -------------
template <bool TRANSB>
__global__ void __launch_bounds__(256) gemm128_kernel(
    const float* __restrict__ A, const float* __restrict__ B,
    const float* __restrict__ bias, float* __restrict__ Y,
    int M, int N, int K)
{
    const int BK = 16;
    __shared__ float As[BK][128];
    __shared__ float Bs[BK][128];

    int bm = blockIdx.y * 128;
    int bn = blockIdx.x * 128;
    int tid = threadIdx.x;
    int tx = tid & 15;
    int ty = tid >> 4;
    int m0 = ty * 8;
    int n0 = tx * 8;

    u64 acc[8][4];
#pragma unroll
    for (int i = 0; i < 8; i++)
#pragma unroll
        for (int j = 0; j < 4; j++) acc[i][j] = 0ULL;

    for (int k0 = 0; k0 < K; k0 += BK) {
#pragma unroll
        for (int l = tid; l < 512; l += 256) {
            int r = l >> 2, kq = l & 3;
            float4 v = *(const float4*)&A[(size_t)(bm + r) * K + k0 + kq * 4];
            As[kq * 4 + 0][r] = v.x; As[kq * 4 + 1][r] = v.y;
            As[kq * 4 + 2][r] = v.z; As[kq * 4 + 3][r] = v.w;
        }
        if (!TRANSB) {
#pragma unroll
            for (int l = tid; l < 512; l += 256) {
                int r = l >> 2, kq = l & 3;
                float4 v = *(const float4*)&B[(size_t)(bn + r) * K + k0 + kq * 4];
                Bs[kq * 4 + 0][r] = v.x; Bs[kq * 4 + 1][r] = v.y;
                Bs[kq * 4 + 2][r] = v.z; Bs[kq * 4 + 3][r] = v.w;
            }
        } else {
#pragma unroll
            for (int l = tid; l < 512; l += 256) {
                int k = l >> 5, nq = l & 31;
                *(float4*)&Bs[k][nq * 4] =
                    *(const float4*)&B[(size_t)(k0 + k) * N + bn + nq * 4];
            }
        }
        __syncthreads();

#pragma unroll
        for (int k = 0; k < BK; k++) {
            float4 av0 = *(const float4*)&As[k][m0];
            float4 av1 = *(const float4*)&As[k][m0 + 4];
            u64 bp[4];
            bp[0] = *(const u64*)&Bs[k][n0];
            bp[1] = *(const u64*)&Bs[k][n0 + 2];
            bp[2] = *(const u64*)&Bs[k][n0 + 4];
            bp[3] = *(const u64*)&Bs[k][n0 + 6];
            float am[8] = {av0.x, av0.y, av0.z, av0.w, av1.x, av1.y, av1.z, av1.w};
#pragma unroll
            for (int i = 0; i < 8; i++) {
                u64 ad = pack2(am[i], am[i]);
#pragma unroll
                for (int j = 0; j < 4; j++) fma2(acc[i][j], ad, bp[j]);
            }
        }
        __syncthreads();
    }

#pragma unroll
    for (int i = 0; i < 8; i++) {
        int m = bm + m0 + i;
        float2 p0 = unpack2(acc[i][0]), p1 = unpack2(acc[i][1]);
        float2 p2 = unpack2(acc[i][2]), p3 = unpack2(acc[i][3]);
        float4 v0 = make_float4(p0.x, p0.y, p1.x, p1.y);
        float4 v1 = make_float4(p2.x, p2.y, p3.x, p3.y);
        *(float4*)&Y[(size_t)m * N + bn + n0]     = v0;
        *(float4*)&Y[(size_t)m * N + bn + n0 + 4] = v1;
    }
}

// ------------- software grid barrier (128 blocks co-resident) -------------
__device__ __forceinline__ void gridbar(unsigned target)
{
    __threadfence();
    __syncthreads();
    if (threadIdx.x == 0) {
        if (atomicAdd(&g_barcnt, 1u) == 127u) {
            g_barcnt = 0u;
            __threadfence();
            g_bargen = target;
        } else {
            while (g_bargen < target) { }
        }
    }
    __syncthreads();
}

// ------------- persistent LSTM layer, tensor-core step GEMM, cp.async --------
// grid (16,8) = 128 blocks, 256 threads (8 warps: 2m x 4n).
// Block tile: 32 batch x 128 gates x K512, split-bf16 3-term mma.
// smem (u16): Ahi[32x520], Alo[32x520], B ring: 4 stages x (hi 5120 + lo 5120)
#define LS_A_LO   16640
#define LS_B_BASE 33280
#define LS_SMEMU  (33280 + 4*10240)          // 74240 u16
#define LS_SMEM   (LS_SMEMU*2)               // 148480 bytes

__device__ __forceinline__ void ls_issue_b(uint32_t smb, int st, int bn,
                                           int k0, int tid)
{
#pragma unroll
    for (int t = 0; t < 2; t++) {
        int idx = tid + t * 256;
        int r = idx >> 2, seg = (idx & 3) * 8;
        size_t g = (size_t)(bn + r) * HID + k0 + seg;
        uint32_t d = smb + (uint32_t)(((LS_B_BASE + st * 10240) + r * 40 + seg) * 2);
        cp16(d, g_whqhi + g);
        cp16(d + 5120 * 2, g_whqlo + g);
    }
}

__global__ void __launch_bounds__(256) lstm_layer_mma_kernel(int store_all)
{
    extern __shared__ u16 smu[];
    uint32_t smb = smem_u32(smu);
    int tid  = threadIdx.x;
    int w    = tid >> 5;
    int lane = tid & 31;
    int bn = blockIdx.x * 128;
    int bm = blockIdx.y * 32;
    int wm = (w & 1) * 16;
    int wn = (w >> 1) * 32;

    int mat = lane >> 3, mi = lane & 7;
    uint32_t aoff = (uint32_t)((wm + (mat & 1) * 8 + mi) * 1040 + (mat >> 1) * 16);
    uint32_t boff = (uint32_t)((wn + (mat >> 1) * 8 + mi) * 80 + (mat & 1) * 16);

    int grp = lane >> 2, t2 = lane & 3;
    int m0r = bm + wm + grp;
    bool owner = (t2 & 1) == 0;

    float cst[4][2];
#pragma unroll
    for (int j = 0; j < 4; j++) { cst[j][0] = 0.0f; cst[j][1] = 0.0f; }

    for (int s = 0; s < SEQ; s++) {
        const u16* hp_hi = g_hhi + (s & 1) * BH;
        const u16* hp_lo = g_hlo + (s & 1) * BH;
        u16* hn_hi = g_hhi + ((s + 1) & 1) * BH;
        u16* hn_lo = g_hlo + ((s + 1) & 1) * BH;

        // ---- group 0: A (h prev, hi+lo) + B stage 0 ----
#pragma unroll
        for (int t = 0; t < 8; t++) {
            int i = tid + t * 256;          // 0..2047
            int r = i >> 6, cseg = (i & 63) * 8;
            size_t g = (size_t)(bm + r) * HID + cseg;
            cp16(smb + (uint32_t)((r * 520 + cseg) * 2), hp_hi + g);
            cp16(smb + (uint32_t)((LS_A_LO + r * 520 + cseg) * 2), hp_lo + g);
        }
        ls_issue_b(smb, 0, bn, 0, tid);
        CP_COMMIT();
        ls_issue_b(smb, 1, bn, 32, tid);
        CP_COMMIT();
        ls_issue_b(smb, 2, bn, 64, tid);
        CP_COMMIT();

        float acc[4][4];
#pragma unroll
        for (int j = 0; j < 4; j++)
#pragma unroll
            for (int q = 0; q < 4; q++) acc[j][q] = 0.0f;

        for (int ch = 0; ch < 16; ch++) {
            CP_WAIT2();
            __syncthreads();
            if (ch + 3 < 16)
                ls_issue_b(smb, (ch + 3) & 3, bn, (ch + 3) * 32, tid);
            CP_COMMIT();

            uint32_t bbase = smb + (uint32_t)((LS_B_BASE + (ch & 3) * 10240) * 2) + boff;
#pragma unroll
            for (int k16 = 0; k16 < 2; k16++) {
                uint32_t ka = (uint32_t)(ch * 64 + k16 * 32);
                uint32_t kb = (uint32_t)(k16 * 32);
                uint32_t ah[4], al[4], bh0[4], bh1[4], bl0[4], bl1[4];
                ldm_x4(ah, smb + aoff + ka);
                ldm_x4(al, smb + (uint32_t)(LS_A_LO * 2) + aoff + ka);
                ldm_x4(bh0, bbase + kb);
                ldm_x4(bh1, bbase + kb + 16 * 80);
                ldm_x4(bl0, bbase + (uint32_t)(5120 * 2) + kb);
                ldm_x4(bl1, bbase + (uint32_t)(5120 * 2) + kb + 16 * 80);

                mma16816(acc[0], ah, bh0[0], bh0[1]);
                mma16816(acc[0], ah, bl0[0], bl0[1]);
                mma16816(acc[0], al, bh0[0], bh0[1]);
                mma16816(acc[1], ah, bh0[2], bh0[3]);
                mma16816(acc[1], ah, bl0[2], bl0[3]);
                mma16816(acc[1], al, bh0[2], bh0[3]);
                mma16816(acc[2], ah, bh1[0], bh1[1]);
                mma16816(acc[2], ah, bl1[0], bl1[1]);
                mma16816(acc[2], al, bh1[0], bh1[1]);
                mma16816(acc[3], ah, bh1[2], bh1[3]);
                mma16816(acc[3], ah, bl1[2], bl1[3]);
                mma16816(acc[3], al, bh1[2], bh1[3]);
            }
        }

        // ---- epilogue: gin add, gate pair-exchange, LSTM cell, h store ----
#pragma unroll
        for (int nj = 0; nj < 4; nj++) {
            int ncol = bn + wn + nj * 8 + t2 * 2;
            const float* gp = &g_gin[((size_t)(s * BATCH + m0r)) * G4 + ncol];
            float2 gv0 = *(const float2*)gp;
            float2 gv1 = *(const float2*)(gp + 8 * G4);
            float fa = acc[nj][0] + gv0.x;
            float fb = acc[nj][1] + gv0.y;
            float fc = acc[nj][2] + gv1.x;
            float fd = acc[nj][3] + gv1.y;
            float pa = __shfl_xor_sync(0xffffffffu, fa, 1);
            float pb = __shfl_xor_sync(0xffffffffu, fb, 1);
            float pc = __shfl_xor_sync(0xffffffffu, fc, 1);
            float pd = __shfl_xor_sync(0xffffffffu, fd, 1);
            if (owner) {
                int u = ncol >> 2;
                {
                    float ig = sigmoidf_(fa), fg = sigmoidf_(fb);
                    float gg = tanhf(pa),     og = sigmoidf_(pb);
                    float cn = fg * cst[nj][0] + ig * gg;
                    cst[nj][0] = cn;
                    float hv = og * tanhf(cn);
                    u16 hi, lo; split_bf16(hv, hi, lo);
                    size_t idx = (size_t)m0r * HID + u;
                    st_cg_u16(&hn_hi[idx], hi);
                    st_cg_u16(&hn_lo[idx], lo);
                    if (store_all) {
                        size_t oidx = ((size_t)(s * BATCH + m0r)) * HID + u;
                        g_ahi[oidx] = hi; g_alo[oidx] = lo;
                    }
                }
                {
                    float ig = sigmoidf_(fc), fg = sigmoidf_(fd);
                    float gg = tanhf(pc),     og = sigmoidf_(pd);
                    float cn = fg * cst[nj][1] + ig * gg;
                    cst[nj][1] = cn;
                    float hv = og * tanhf(cn);
                    u16 hi, lo; split_bf16(hv, hi, lo);
                    size_t idx = (size_t)(m0r + 8) * HID + u;
                    st_cg_u16(&hn_hi[idx], hi);
                    st_cg_u16(&hn_lo[idx], lo);
                    if (store_all) {
                        size_t oidx = ((size_t)(s * BATCH + m0r + 8)) * HID + u;
                        g_ahi[oidx] = hi; g_alo[oidx] = lo;
                    }
                }
            }
        }

        if (s != SEQ - 1) gridbar((unsigned)(s + 1));
    }
}

// ------------- beff[n] = bcat[n] + sum_e Wicat[n][e] * b_proj[e] -------------
__global__ void __launch_bounds__(256) beff_kernel(const float* __restrict__ bproj)
{
    int n = blockIdx.x * 256 + threadIdx.x;
    if (n >= G4) return;
    float s = g_bcat[n];
    const float* w = &g_wicat[n * EMB];
    for (int e = 0; e < EMB; e++) s += w[e] * bproj[e];
    g_beff[n] = s;
}

// ------------- zero h buffer 0 + reset grid barrier -------------
__global__ void __launch_bounds__(256) zero_h_kernel()
{
    int i = blockIdx.x * 256 + threadIdx.x;
    if (i < BH) { g_hhi[i] = 0; g_hlo[i] = 0; }
    if (i == 0) { g_barcnt = 0u; g_bargen = 0u; }
}

// =============================== launch ===============================
extern "C" void kernel_launch(void* const* d_in, const int* in_sizes, int n_in,
                              void* d_out, int out_size)
{
    const int*   X    = (const int*)  d_in[0];
    const float* C    = (const float*)d_in[1];
    const float* Wii  = (const float*)d_in[2];
    const float* Whi  = (const float*)d_in[3];
    const float* bi   = (const float*)d_in[4];
    const float* Wif  = (const float*)d_in[5];
    const float* Whf  = (const float*)d_in[6];
    const float* bf   = (const float*)d_in[7];
    const float* Wig  = (const float*)d_in[8];
    const float* Whg  = (const float*)d_in[9];
    const float* bg   = (const float*)d_in[10];
    const float* Wio  = (const float*)d_in[11];
    const float* Who  = (const float*)d_in[12];
    const float* bo   = (const float*)d_in[13];
    const float* Wp   = (const float*)d_in[14];   // [EMB, HID]
    const float* bp   = (const float*)d_in[15];   // [EMB]
    const float* Wfin = (const float*)d_in[16];   // [N_CLASS, HID]
    const float* bfin = (const float*)d_in[17];   // [N_CLASS]
    float* out = (float*)d_out;

    float *p_gin, *p_wicat, *p_bcat, *p_weff, *p_beff;
    u16 *p_ahi, *p_alo, *p_bhi, *p_blo, *p_hhi, *p_hlo;
    cudaGetSymbolAddress((void**)&p_gin,   g_gin);
    cudaGetSymbolAddress((void**)&p_wicat, g_wicat);
    cudaGetSymbolAddress((void**)&p_bcat,  g_bcat);
    cudaGetSymbolAddress((void**)&p_weff,  g_weff);
    cudaGetSymbolAddress((void**)&p_beff,  g_beff);
    cudaGetSymbolAddress((void**)&p_ahi,   g_ahi);
    cudaGetSymbolAddress((void**)&p_alo,   g_alo);
    cudaGetSymbolAddress((void**)&p_bhi,   g_bhi);
    cudaGetSymbolAddress((void**)&p_blo,   g_blo);
    cudaGetSymbolAddress((void**)&p_hhi,   g_hhi);
    cudaGetSymbolAddress((void**)&p_hlo,   g_hlo);

    cudaFuncSetAttribute(mma_gemm_kernel,
                         cudaFuncAttributeMaxDynamicSharedMemorySize, MG_SMEM);
    cudaFuncSetAttribute(lstm_layer_mma_kernel,
                         cudaFuncAttributeMaxDynamicSharedMemorySize, LS_SMEM);

    // 1) weight prep
    prep_concat_kernel<<<(G4 * HID) / 256, 256>>>(Wii, Whi, bi, Wif, Whf, bf,
                                                  Wig, Whg, bg, Wio, Who, bo);
    // 2) embedding gather -> split bf16 A
    embed_kernel<<<MB_, EMB>>>(X, C);

    // 3) Gin0 = Emb @ Wicat^T + bcat   [16384 x 2048], K=256
    cvt_split_kernel<<<(G4 * EMB) / 256, 256>>>(p_wicat, p_bhi, p_blo, G4 * EMB);
    mma_gemm_kernel<<<dim3(G4 / 128, MB_ / 128), 256, MG_SMEM>>>(
        p_ahi, p_alo, p_bhi, p_blo, p_bcat, p_gin, G4, EMB);

    // 4) fold projection: Weff = Wicat @ Wp  (fp32), beff; cvt to bf16 B
    gemm128_kernel<true><<<dim3(HID / 128, G4 / 128), 256>>>(
        p_wicat, Wp, nullptr, p_weff, G4, HID, EMB);
    beff_kernel<<<G4 / 256, 256>>>(bp);
    cvt_split_kernel<<<(G4 * HID) / 256, 256>>>(p_weff, p_bhi, p_blo, G4 * HID);

    // 5) layer-0 recurrence (persistent, tensor-core; h0all -> g_ahi/g_alo)
    zero_h_kernel<<<BH / 256, 256>>>();
    lstm_layer_mma_kernel<<<dim3(16, 8), 256, LS_SMEM>>>(1);

    // 6) Gin1 = H0all @ Weff^T + beff  [16384 x 2048], K=512
    mma_gemm_kernel<<<dim3(G4 / 128, MB_ / 128), 256, MG_SMEM>>>(
        p_ahi, p_alo, p_bhi, p_blo, p_beff, p_gin, G4, HID);

    // 7) layer-1 recurrence
    zero_h_kernel<<<BH / 256, 256>>>();
    lstm_layer_mma_kernel<<<dim3(16, 8), 256, LS_SMEM>>>(0);

    // 8) logits = h_last @ Wfin^T + bfin  [256 x 32000], K=512
    //    (SEQ even -> final h in buffer 0 of g_hhi/g_hlo)
    cvt_split_kernel<<<(N_CLASS * HID) / 256, 256>>>(Wfin, p_bhi, p_blo, N_CLASS * HID);
    mma_gemm_kernel<<<dim3(N_CLASS / 128, BATCH / 128), 256, MG_SMEM>>>(
        p_hhi, p_hlo, p_bhi, p_blo, bfin, out, N_CLASS, HID);
}

// round 12
// speedup vs baseline: 3.7349x; 1.0872x over previous
#include <cuda_runtime.h>
#include <cuda_bf16.h>
#include <math.h>
#include <stdint.h>

// Problem constants
#define N_CLASS 32000
#define EMB     256
#define HID     512
#define BATCH   256
#define SEQ     64
#define G4      2048            // 4 gates * HID (gate-interleaved: n = u*4 + g)
#define MB_     (SEQ*BATCH)     // 16384
#define BH      (BATCH*HID)     // 131072

typedef unsigned long long u64;
typedef unsigned short u16;

// ---------------- static device scratch (allocation-free) ----------------
__device__ __align__(16) float g_gin  [MB_*G4];         // 134 MB gate inputs
__device__ __align__(16) float g_wicat[G4*EMB];         // fp32 (fold + cvt source)
__device__ __align__(16) float g_bcat [G4];
__device__ __align__(16) float g_weff [G4*HID];
__device__ __align__(16) float g_beff [G4];
__device__ __align__(16) u16   g_whqhi[G4*HID];         // hidden weights split bf16
__device__ __align__(16) u16   g_whqlo[G4*HID];
__device__ __align__(16) u16   g_hhi  [2*BH];           // h double buffer (split bf16)
__device__ __align__(16) u16   g_hlo  [2*BH];
__device__ unsigned          g_bcnt8[8];                // per-bm-group barrier counters
__device__ volatile unsigned g_bgen8[8];                // per-bm-group barrier generations
// split-bf16 A/B operand buffers for the big GEMMs
__device__ __align__(16) u16 g_ahi[MB_*HID];            // emb, then h0all
__device__ __align__(16) u16 g_alo[MB_*HID];
__device__ __align__(16) u16 g_bhi[N_CLASS*HID];
__device__ __align__(16) u16 g_blo[N_CLASS*HID];

// ---------------- small helpers ----------------
__device__ __forceinline__ u64 pack2(float x, float y) {
    u64 r; asm("mov.b64 %0, {%1, %2};" : "=l"(r) : "f"(x), "f"(y)); return r;
}
__device__ __forceinline__ float2 unpack2(u64 v) {
    float2 r; asm("mov.b64 {%0, %1}, %2;" : "=f"(r.x), "=f"(r.y) : "l"(v)); return r;
}
__device__ __forceinline__ void fma2(u64& d, u64 a, u64 b) {
    asm("fma.rn.f32x2 %0, %1, %2, %0;" : "+l"(d) : "l"(a), "l"(b));
}
__device__ __forceinline__ float sigmoidf_(float x) { return 1.0f / (1.0f + expf(-x)); }
__device__ __forceinline__ uint32_t smem_u32(const void* p) {
    uint32_t a;
    asm("{ .reg .u64 t; cvta.to.shared.u64 t, %1; cvt.u32.u64 %0, t; }"
        : "=r"(a) : "l"(p));
    return a;
}
__device__ __forceinline__ void split_bf16(float x, u16& hi, u16& lo) {
    __nv_bfloat16 h = __float2bfloat16(x);
    hi = __bfloat16_as_ushort(h);
    lo = __bfloat16_as_ushort(__float2bfloat16(x - __bfloat162float(h)));
}
__device__ __forceinline__ void st_cg_u16(u16* p, u16 v) {
    asm volatile("st.global.cg.u16 [%0], %1;" :: "l"(p), "h"(v));
}

// ---------------- cp.async helpers ----------------
__device__ __forceinline__ void cp16(uint32_t saddr, const void* g) {
    asm volatile("cp.async.cg.shared.global [%0], [%1], 16;"
                 :: "r"(saddr), "l"(g) : "memory");
}
#define CP_COMMIT() asm volatile("cp.async.commit_group;" ::: "memory")
#define CP_WAIT2()  asm volatile("cp.async.wait_group 2;" ::: "memory")
#define CP_WAIT0()  asm volatile("cp.async.wait_group 0;" ::: "memory")

// ---------------- mma.sync helpers (legacy tensor path, valid on sm_103) -----
__device__ __forceinline__ void ldm_x4(uint32_t* r, uint32_t addr) {
    asm volatile("ldmatrix.sync.aligned.m8n8.x4.shared.b16 {%0,%1,%2,%3}, [%4];"
                 : "=r"(r[0]), "=r"(r[1]), "=r"(r[2]), "=r"(r[3]) : "r"(addr));
}
__device__ __forceinline__ void mma16816(float* c, const uint32_t* a,
                                         uint32_t b0, uint32_t b1) {
    asm volatile(
        "mma.sync.aligned.m16n8k16.row.col.f32.bf16.bf16.f32 "
        "{%0,%1,%2,%3}, {%4,%5,%6,%7}, {%8,%9}, {%0,%1,%2,%3};"
        : "+f"(c[0]), "+f"(c[1]), "+f"(c[2]), "+f"(c[3])
        : "r"(a[0]), "r"(a[1]), "r"(a[2]), "r"(a[3]), "r"(b0), "r"(b1));
}

// ------------- build gate-interleaved weights (whq -> split bf16) -------------
__global__ void __launch_bounds__(256) prep_concat_kernel(
    const float* __restrict__ Wii, const float* __restrict__ Whi, const float* __restrict__ bi,
    const float* __restrict__ Wif, const float* __restrict__ Whf, const float* __restrict__ bf,
    const float* __restrict__ Wig, const float* __restrict__ Whg, const float* __restrict__ bg,
    const float* __restrict__ Wio, const float* __restrict__ Who, const float* __restrict__ bo)
{
    int idx = blockIdx.x * 256 + threadIdx.x;
    if (idx >= G4 * HID) return;
    int n = idx / HID;
    int k = idx - n * HID;
    int u = n >> 2;
    int g = n & 3;
    const float* Wh = (g == 0) ? Whi : (g == 1) ? Whf : (g == 2) ? Whg : Who;
    u16 hi, lo;
    split_bf16(Wh[u * HID + k], hi, lo);
    g_whqhi[idx] = hi;
    g_whqlo[idx] = lo;
    if (k < EMB) {
        const float* Wi = (g == 0) ? Wii : (g == 1) ? Wif : (g == 2) ? Wig : Wio;
        g_wicat[n * EMB + k] = Wi[u * EMB + k];
    }
    if (k == 0) {
        const float* bv = (g == 0) ? bi : (g == 1) ? bf : (g == 2) ? bg : bo;
        g_bcat[n] = bv[u];
    }
}

// ------------- embedding gather -> split bf16 directly -------------
__global__ void __launch_bounds__(EMB) embed_kernel(const int* __restrict__ X,
                                                    const float* __restrict__ C)
{
    int sb = blockIdx.x;
    int s  = sb >> 8;
    int b  = sb & 255;
    int row = X[b * SEQ + s];
    float v = C[(size_t)row * EMB + threadIdx.x];
    u16 hi, lo;
    split_bf16(v, hi, lo);
    g_ahi[(size_t)sb * EMB + threadIdx.x] = hi;
    g_alo[(size_t)sb * EMB + threadIdx.x] = lo;
}

// ------------- fp32 -> split bf16 (hi + lo) -------------
__global__ void __launch_bounds__(256) cvt_split_kernel(
    const float* __restrict__ src, u16* __restrict__ hi,
    u16* __restrict__ lo, int n)
{
    int i = blockIdx.x * 256 + threadIdx.x;
    if (i >= n) return;
    u16 h, l;
    split_bf16(src[i], h, l);
    hi[i] = h;
    lo[i] = l;
}

// ------------- split-bf16 tensor-core GEMM, 2-stage cp.async, 2 CTA/SM --------
// Y[m][n] = bias[n] + sum_k A[m][k]*B[n][k]   (3-term compensated bf16)
// CTA tile 128x128, 8 warps (warp w: m-block (w&3)*32, n-block (w>>2)*64).
// Stage = 32 k. Arrays per stage: Ahi, Alo, Bhi, Blo; rows padded to 80 B.
#define MG_ROWU  40
#define MG_ARRU  (128*MG_ROWU)            // 5120 u16 per array per stage
#define MG_STGU  (4*MG_ARRU)              // 20480 u16 per stage
#define MG_SMEM  (2*MG_STGU*2)            // 81920 bytes -> 2 CTAs/SM

__device__ __forceinline__ void mg_issue_stage(
    uint32_t sbase, const u16* __restrict__ Ahi, const u16* __restrict__ Alo,
    const u16* __restrict__ Bhi, const u16* __restrict__ Blo,
    int bm, int bn, int K, int k0, int tid)
{
#pragma unroll
    for (int t = 0; t < 2; t++) {
        int idx = tid + 256 * t;            // 0..511
        int row = idx >> 2, seg = (idx & 3) * 8;
        size_t ga = (size_t)(bm + row) * K + k0 + seg;
        size_t gb = (size_t)(bn + row) * K + k0 + seg;
        uint32_t d = sbase + (uint32_t)((row * MG_ROWU + seg) * 2);
        cp16(d + 0u * (MG_ARRU * 2), Ahi + ga);
        cp16(d + 1u * (MG_ARRU * 2), Alo + ga);
        cp16(d + 2u * (MG_ARRU * 2), Bhi + gb);
        cp16(d + 3u * (MG_ARRU * 2), Blo + gb);
    }
}

__global__ void __launch_bounds__(256, 2) mma_gemm_kernel(
    const u16* __restrict__ Ahi, const u16* __restrict__ Alo,
    const u16* __restrict__ Bhi, const u16* __restrict__ Blo,
    const float* __restrict__ bias, float* __restrict__ Y, int N, int K)
{
    extern __shared__ u16 smu[];
    uint32_t smb = smem_u32(smu);
    int tid  = threadIdx.x;
    int w    = tid >> 5;
    int lane = tid & 31;
    int bm = blockIdx.y * 128;
    int bn = blockIdx.x * 128;
    int wm = (w & 3) * 32;
    int wn = (w >> 2) * 64;
    int nch = K >> 5;

    int mat = lane >> 3, mi = lane & 7;
    uint32_t aoff = (uint32_t)((wm + (mat & 1) * 8 + mi) * 80 + (mat >> 1) * 16);
    uint32_t boff = (uint32_t)((wn + (mat >> 1) * 8 + mi) * 80 + (mat & 1) * 16);

    float acc[2][8][4];
#pragma unroll
    for (int i = 0; i < 2; i++)
#pragma unroll
        for (int j = 0; j < 8; j++)
#pragma unroll
            for (int q = 0; q < 4; q++) acc[i][j][q] = 0.0f;

    // prologue: stage 0
    mg_issue_stage(smb, Ahi, Alo, Bhi, Blo, bm, bn, K, 0, tid);
    CP_COMMIT();

    for (int c = 0; c < nch; c++) {
        CP_WAIT0();
        __syncthreads();
        if (c + 1 < nch)
            mg_issue_stage(smb + (uint32_t)(((c + 1) & 1) * MG_STGU * 2),
                           Ahi, Alo, Bhi, Blo, bm, bn, K, (c + 1) * 32, tid);
        CP_COMMIT();

        uint32_t sb = smb + (uint32_t)((c & 1) * MG_STGU * 2);
#pragma unroll
        for (int k16 = 0; k16 < 2; k16++) {
            uint32_t kb = (uint32_t)(k16 * 32);
            uint32_t ah[2][4], al[2][4];
            ldm_x4(ah[0], sb + 0 * 10240 + aoff + kb);
            ldm_x4(ah[1], sb + 0 * 10240 + aoff + kb + 16 * 80);
            ldm_x4(al[0], sb + 1 * 10240 + aoff + kb);
            ldm_x4(al[1], sb + 1 * 10240 + aoff + kb + 16 * 80);
#pragma unroll
            for (int nb = 0; nb < 4; nb++) {
                uint32_t bh[4], bl[4];
                uint32_t bo = boff + kb + (uint32_t)(nb * 16 * 80);
                ldm_x4(bh, sb + 2 * 10240 + bo);
                ldm_x4(bl, sb + 3 * 10240 + bo);
#pragma unroll
                for (int mb = 0; mb < 2; mb++) {
#pragma unroll
                    for (int h = 0; h < 2; h++) {
                        float* cc = acc[mb][nb * 2 + h];
                        mma16816(cc, ah[mb], bh[2 * h], bh[2 * h + 1]);
                        mma16816(cc, ah[mb], bl[2 * h], bl[2 * h + 1]);
                        mma16816(cc, al[mb], bh[2 * h], bh[2 * h + 1]);
                    }
                }
            }
        }
    }

    int grp = lane >> 2, t2 = lane & 3;
#pragma unroll
    for (int mb = 0; mb < 2; mb++) {
#pragma unroll
        for (int nj = 0; nj < 8; nj++) {
            int n = bn + wn + nj * 8 + t2 * 2;
            float2 bv = *(const float2*)&bias[n];
            int mlo = bm + wm + mb * 16 + grp;
            const float* cc = acc[mb][nj];
            float2 v0 = make_float2(cc[0] + bv.x, cc[1] + bv.y);
            float2 v1 = make_float2(cc[2] + bv.x, cc[3] + bv.y);
            *(float2*)&Y[(size_t)mlo * N + n]       = v0;
            *(float2*)&Y[(size_t)(mlo + 8) * N + n] = v1;
        }
    }
}

// ------------- fp32 fold GEMM (known-good), TRANSB -------------
template <bool TRANSB>
__global__ void __launch_bounds__(256) gemm128_kernel(
    const float* __restrict__ A, const float* __restrict__ B,
    const float* __restrict__ bias, float* __restrict__ Y,
    int M, int N, int K)
{
    const int BK = 16;
    __shared__ float As[BK][128];
    __shared__ float Bs[BK][128];

    int bm = blockIdx.y * 128;
    int bn = blockIdx.x * 128;
    int tid = threadIdx.x;
    int tx = tid & 15;
    int ty = tid >> 4;
    int m0 = ty * 8;
    int n0 = tx * 8;

    u64 acc[8][4];
#pragma unroll
    for (int i = 0; i < 8; i++)
#pragma unroll
        for (int j = 0; j < 4; j++) acc[i][j] = 0ULL;

    for (int k0 = 0; k0 < K; k0 += BK) {
#pragma unroll
        for (int l = tid; l < 512; l += 256) {
            int r = l >> 2, kq = l & 3;
            float4 v = *(const float4*)&A[(size_t)(bm + r) * K + k0 + kq * 4];
            As[kq * 4 + 0][r] = v.x; As[kq * 4 + 1][r] = v.y;
            As[kq * 4 + 2][r] = v.z; As[kq * 4 + 3][r] = v.w;
        }
        if (!TRANSB) {
#pragma unroll
            for (int l = tid; l < 512; l += 256) {
                int r = l >> 2, kq = l & 3;
                float4 v = *(const float4*)&B[(size_t)(bn + r) * K + k0 + kq * 4];
                Bs[kq * 4 + 0][r] = v.x; Bs[kq * 4 + 1][r] = v.y;
                Bs[kq * 4 + 2][r] = v.z; Bs[kq * 4 + 3][r] = v.w;
            }
        } else {
#pragma unroll
            for (int l = tid; l < 512; l += 256) {
                int k = l >> 5, nq = l & 31;
                *(float4*)&Bs[k][nq * 4] =
                    *(const float4*)&B[(size_t)(k0 + k) * N + bn + nq * 4];
            }
        }
        __syncthreads();

#pragma unroll
        for (int k = 0; k < BK; k++) {
            float4 av0 = *(const float4*)&As[k][m0];
            float4 av1 = *(const float4*)&As[k][m0 + 4];
            u64 bp[4];
            bp[0] = *(const u64*)&Bs[k][n0];
            bp[1] = *(const u64*)&Bs[k][n0 + 2];
            bp[2] = *(const u64*)&Bs[k][n0 + 4];
            bp[3] = *(const u64*)&Bs[k][n0 + 6];
            float am[8] = {av0.x, av0.y, av0.z, av0.w, av1.x, av1.y, av1.z, av1.w};
#pragma unroll
            for (int i = 0; i < 8; i++) {
                u64 ad = pack2(am[i], am[i]);
#pragma unroll
                for (int j = 0; j < 4; j++) fma2(acc[i][j], ad, bp[j]);
            }
        }
        __syncthreads();
    }

#pragma unroll
    for (int i = 0; i < 8; i++) {
        int m = bm + m0 + i;
        float2 p0 = unpack2(acc[i][0]), p1 = unpack2(acc[i][1]);
        float2 p2 = unpack2(acc[i][2]), p3 = unpack2(acc[i][3]);
        float4 v0 = make_float4(p0.x, p0.y, p1.x, p1.y);
        float4 v1 = make_float4(p2.x, p2.y, p3.x, p3.y);
        *(float4*)&Y[(size_t)m * N + bn + n0]     = v0;
        *(float4*)&Y[(size_t)m * N + bn + n0 + 4] = v1;
    }
}

// ------------- per-bm-group barrier (16 blocks each, all co-resident) ---------
__device__ __forceinline__ void groupbar(int gid, unsigned target)
{
    __threadfence();
    __syncthreads();
    if (threadIdx.x == 0) {
        if (atomicAdd(&g_bcnt8[gid], 1u) == 15u) {
            g_bcnt8[gid] = 0u;
            __threadfence();
            g_bgen8[gid] = target;
        } else {
            while (g_bgen8[gid] < target) { }
        }
    }
    __syncthreads();
}

// ------------- persistent LSTM layer, tensor-core step GEMM, cp.async --------
// grid (16,8) = 128 blocks, 256 threads (8 warps: 2m x 4n).
// Block tile: 32 batch x 128 gates x K512, split-bf16 3-term mma.
// smem (u16): Ahi[32x520], Alo[32x520], B ring: 4 stages x (hi 5120 + lo 5120)
#define LS_A_LO   16640
#define LS_B_BASE 33280
#define LS_SMEMU  (33280 + 4*10240)          // 74240 u16
#define LS_SMEM   (LS_SMEMU*2)               // 148480 bytes

__device__ __forceinline__ void ls_issue_b(uint32_t smb, int st, int bn,
                                           int k0, int tid)
{
#pragma unroll
    for (int t = 0; t < 2; t++) {
        int idx = tid + t * 256;
        int r = idx >> 2, seg = (idx & 3) * 8;
        size_t g = (size_t)(bn + r) * HID + k0 + seg;
        uint32_t d = smb + (uint32_t)(((LS_B_BASE + st * 10240) + r * 40 + seg) * 2);
        cp16(d, g_whqhi + g);
        cp16(d + 5120 * 2, g_whqlo + g);
    }
}

__global__ void __launch_bounds__(256) lstm_layer_mma_kernel(int store_all)
{
    extern __shared__ u16 smu[];
    uint32_t smb = smem_u32(smu);
    int tid  = threadIdx.x;
    int w    = tid >> 5;
    int lane = tid & 31;
    int bn = blockIdx.x * 128;
    int bm = blockIdx.y * 32;
    int gid = blockIdx.y;               // barrier group = bm row-group
    int wm = (w & 1) * 16;
    int wn = (w >> 1) * 32;

    int mat = lane >> 3, mi = lane & 7;
    uint32_t aoff = (uint32_t)((wm + (mat & 1) * 8 + mi) * 1040 + (mat >> 1) * 16);
    uint32_t boff = (uint32_t)((wn + (mat >> 1) * 8 + mi) * 80 + (mat & 1) * 16);

    int grp = lane >> 2, t2 = lane & 3;
    int m0r = bm + wm + grp;
    bool owner = (t2 & 1) == 0;

    float cst[4][2];
#pragma unroll
    for (int j = 0; j < 4; j++) { cst[j][0] = 0.0f; cst[j][1] = 0.0f; }

    for (int s = 0; s < SEQ; s++) {
        const u16* hp_hi = g_hhi + (s & 1) * BH;
        const u16* hp_lo = g_hlo + (s & 1) * BH;
        u16* hn_hi = g_hhi + ((s + 1) & 1) * BH;
        u16* hn_lo = g_hlo + ((s + 1) & 1) * BH;

        // ---- prefetch this step's gin into registers (independent of h) ----
        float2 pg0[4], pg1[4];
#pragma unroll
        for (int nj = 0; nj < 4; nj++) {
            int ncol = bn + wn + nj * 8 + t2 * 2;
            const float* gp = &g_gin[((size_t)(s * BATCH + m0r)) * G4 + ncol];
            pg0[nj] = *(const float2*)gp;
            pg1[nj] = *(const float2*)(gp + 8 * G4);
        }

        // ---- group 0: A (h prev, hi+lo) + B stage 0 ----
#pragma unroll
        for (int t = 0; t < 8; t++) {
            int i = tid + t * 256;          // 0..2047
            int r = i >> 6, cseg = (i & 63) * 8;
            size_t g = (size_t)(bm + r) * HID + cseg;
            cp16(smb + (uint32_t)((r * 520 + cseg) * 2), hp_hi + g);
            cp16(smb + (uint32_t)((LS_A_LO + r * 520 + cseg) * 2), hp_lo + g);
        }
        ls_issue_b(smb, 0, bn, 0, tid);
        CP_COMMIT();
        ls_issue_b(smb, 1, bn, 32, tid);
        CP_COMMIT();
        ls_issue_b(smb, 2, bn, 64, tid);
        CP_COMMIT();

        float acc[4][4];
#pragma unroll
        for (int j = 0; j < 4; j++)
#pragma unroll
            for (int q = 0; q < 4; q++) acc[j][q] = 0.0f;

        for (int ch = 0; ch < 16; ch++) {
            CP_WAIT2();
            __syncthreads();
            if (ch + 3 < 16)
                ls_issue_b(smb, (ch + 3) & 3, bn, (ch + 3) * 32, tid);
            CP_COMMIT();

            uint32_t bbase = smb + (uint32_t)((LS_B_BASE + (ch & 3) * 10240) * 2) + boff;
#pragma unroll
            for (int k16 = 0; k16 < 2; k16++) {
                uint32_t ka = (uint32_t)(ch * 64 + k16 * 32);
                uint32_t kb = (uint32_t)(k16 * 32);
                uint32_t ah[4], al[4], bh0[4], bh1[4], bl0[4], bl1[4];
                ldm_x4(ah, smb + aoff + ka);
                ldm_x4(al, smb + (uint32_t)(LS_A_LO * 2) + aoff + ka);
                ldm_x4(bh0, bbase + kb);
                ldm_x4(bh1, bbase + kb + 16 * 80);
                ldm_x4(bl0, bbase + (uint32_t)(5120 * 2) + kb);
                ldm_x4(bl1, bbase + (uint32_t)(5120 * 2) + kb + 16 * 80);

                mma16816(acc[0], ah, bh0[0], bh0[1]);
                mma16816(acc[0], ah, bl0[0], bl0[1]);
                mma16816(acc[0], al, bh0[0], bh0[1]);
                mma16816(acc[1], ah, bh0[2], bh0[3]);
                mma16816(acc[1], ah, bl0[2], bl0[3]);
                mma16816(acc[1], al, bh0[2], bh0[3]);
                mma16816(acc[2], ah, bh1[0], bh1[1]);
                mma16816(acc[2], ah, bl1[0], bl1[1]);
                mma16816(acc[2], al, bh1[0], bh1[1]);
                mma16816(acc[3], ah, bh1[2], bh1[3]);
                mma16816(acc[3], ah, bl1[2], bl1[3]);
                mma16816(acc[3], al, bh1[2], bh1[3]);
            }
        }

        // ---- epilogue: prefetched gin, gate pair-exchange, LSTM cell, h store --
#pragma unroll
        for (int nj = 0; nj < 4; nj++) {
            int ncol = bn + wn + nj * 8 + t2 * 2;
            float fa = acc[nj][0] + pg0[nj].x;
            float fb = acc[nj][1] + pg0[nj].y;
            float fc = acc[nj][2] + pg1[nj].x;
            float fd = acc[nj][3] + pg1[nj].y;
            float pa = __shfl_xor_sync(0xffffffffu, fa, 1);
            float pb = __shfl_xor_sync(0xffffffffu, fb, 1);
            float pc = __shfl_xor_sync(0xffffffffu, fc, 1);
            float pd = __shfl_xor_sync(0xffffffffu, fd, 1);
            if (owner) {
                int u = ncol >> 2;
                {
                    float ig = sigmoidf_(fa), fg = sigmoidf_(fb);
                    float gg = tanhf(pa),     og = sigmoidf_(pb);
                    float cn = fg * cst[nj][0] + ig * gg;
                    cst[nj][0] = cn;
                    float hv = og * tanhf(cn);
                    u16 hi, lo; split_bf16(hv, hi, lo);
                    size_t idx = (size_t)m0r * HID + u;
                    st_cg_u16(&hn_hi[idx], hi);
                    st_cg_u16(&hn_lo[idx], lo);
                    if (store_all) {
                        size_t oidx = ((size_t)(s * BATCH + m0r)) * HID + u;
                        g_ahi[oidx] = hi; g_alo[oidx] = lo;
                    }
                }
                {
                    float ig = sigmoidf_(fc), fg = sigmoidf_(fd);
                    float gg = tanhf(pc),     og = sigmoidf_(pd);
                    float cn = fg * cst[nj][1] + ig * gg;
                    cst[nj][1] = cn;
                    float hv = og * tanhf(cn);
                    u16 hi, lo; split_bf16(hv, hi, lo);
                    size_t idx = (size_t)(m0r + 8) * HID + u;
                    st_cg_u16(&hn_hi[idx], hi);
                    st_cg_u16(&hn_lo[idx], lo);
                    if (store_all) {
                        size_t oidx = ((size_t)(s * BATCH + m0r + 8)) * HID + u;
                        g_ahi[oidx] = hi; g_alo[oidx] = lo;
                    }
                }
            }
        }

        if (s != SEQ - 1) groupbar(gid, (unsigned)(s + 1));
    }
}

// ------------- beff[n] = bcat[n] + sum_e Wicat[n][e] * b_proj[e] -------------
__global__ void __launch_bounds__(256) beff_kernel(const float* __restrict__ bproj)
{
    int n = blockIdx.x * 256 + threadIdx.x;
    if (n >= G4) return;
    float s = g_bcat[n];
    const float* w = &g_wicat[n * EMB];
    for (int e = 0; e < EMB; e++) s += w[e] * bproj[e];
    g_beff[n] = s;
}

// ------------- zero h buffer 0 + reset group barriers -------------
__global__ void __launch_bounds__(256) zero_h_kernel()
{
    int i = blockIdx.x * 256 + threadIdx.x;
    if (i < BH) { g_hhi[i] = 0; g_hlo[i] = 0; }
    if (i < 8) { g_bcnt8[i] = 0u; g_bgen8[i] = 0u; }
}

// =============================== launch ===============================
extern "C" void kernel_launch(void* const* d_in, const int* in_sizes, int n_in,
                              void* d_out, int out_size)
{
    const int*   X    = (const int*)  d_in[0];
    const float* C    = (const float*)d_in[1];
    const float* Wii  = (const float*)d_in[2];
    const float* Whi  = (const float*)d_in[3];
    const float* bi   = (const float*)d_in[4];
    const float* Wif  = (const float*)d_in[5];
    const float* Whf  = (const float*)d_in[6];
    const float* bf   = (const float*)d_in[7];
    const float* Wig  = (const float*)d_in[8];
    const float* Whg  = (const float*)d_in[9];
    const float* bg   = (const float*)d_in[10];
    const float* Wio  = (const float*)d_in[11];
    const float* Who  = (const float*)d_in[12];
    const float* bo   = (const float*)d_in[13];
    const float* Wp   = (const float*)d_in[14];   // [EMB, HID]
    const float* bp   = (const float*)d_in[15];   // [EMB]
    const float* Wfin = (const float*)d_in[16];   // [N_CLASS, HID]
    const float* bfin = (const float*)d_in[17];   // [N_CLASS]
    float* out = (float*)d_out;

    float *p_gin, *p_wicat, *p_bcat, *p_weff, *p_beff;
    u16 *p_ahi, *p_alo, *p_bhi, *p_blo, *p_hhi, *p_hlo;
    cudaGetSymbolAddress((void**)&p_gin,   g_gin);
    cudaGetSymbolAddress((void**)&p_wicat, g_wicat);
    cudaGetSymbolAddress((void**)&p_bcat,  g_bcat);
    cudaGetSymbolAddress((void**)&p_weff,  g_weff);
    cudaGetSymbolAddress((void**)&p_beff,  g_beff);
    cudaGetSymbolAddress((void**)&p_ahi,   g_ahi);
    cudaGetSymbolAddress((void**)&p_alo,   g_alo);
    cudaGetSymbolAddress((void**)&p_bhi,   g_bhi);
    cudaGetSymbolAddress((void**)&p_blo,   g_blo);
    cudaGetSymbolAddress((void**)&p_hhi,   g_hhi);
    cudaGetSymbolAddress((void**)&p_hlo,   g_hlo);

    cudaFuncSetAttribute(mma_gemm_kernel,
                         cudaFuncAttributeMaxDynamicSharedMemorySize, MG_SMEM);
    cudaFuncSetAttribute(lstm_layer_mma_kernel,
                         cudaFuncAttributeMaxDynamicSharedMemorySize, LS_SMEM);

    // 1) weight prep
    prep_concat_kernel<<<(G4 * HID) / 256, 256>>>(Wii, Whi, bi, Wif, Whf, bf,
                                                  Wig, Whg, bg, Wio, Who, bo);
    // 2) embedding gather -> split bf16 A
    embed_kernel<<<MB_, EMB>>>(X, C);

    // 3) Gin0 = Emb @ Wicat^T + bcat   [16384 x 2048], K=256
    cvt_split_kernel<<<(G4 * EMB) / 256, 256>>>(p_wicat, p_bhi, p_blo, G4 * EMB);
    mma_gemm_kernel<<<dim3(G4 / 128, MB_ / 128), 256, MG_SMEM>>>(
        p_ahi, p_alo, p_bhi, p_blo, p_bcat, p_gin, G4, EMB);

    // 4) fold projection: Weff = Wicat @ Wp  (fp32), beff; cvt to bf16 B
    gemm128_kernel<true><<<dim3(HID / 128, G4 / 128), 256>>>(
        p_wicat, Wp, nullptr, p_weff, G4, HID, EMB);
    beff_kernel<<<G4 / 256, 256>>>(bp);
    cvt_split_kernel<<<(G4 * HID) / 256, 256>>>(p_weff, p_bhi, p_blo, G4 * HID);

    // 5) layer-0 recurrence (persistent, tensor-core; h0all -> g_ahi/g_alo)
    zero_h_kernel<<<BH / 256, 256>>>();
    lstm_layer_mma_kernel<<<dim3(16, 8), 256, LS_SMEM>>>(1);

    // 6) Gin1 = H0all @ Weff^T + beff  [16384 x 2048], K=512
    mma_gemm_kernel<<<dim3(G4 / 128, MB_ / 128), 256, MG_SMEM>>>(
        p_ahi, p_alo, p_bhi, p_blo, p_beff, p_gin, G4, HID);

    // 7) layer-1 recurrence
    zero_h_kernel<<<BH / 256, 256>>>();
    lstm_layer_mma_kernel<<<dim3(16, 8), 256, LS_SMEM>>>(0);

    // 8) logits = h_last @ Wfin^T + bfin  [256 x 32000], K=512
    //    (SEQ even -> final h in buffer 0 of g_hhi/g_hlo)
    cvt_split_kernel<<<(N_CLASS * HID) / 256, 256>>>(Wfin, p_bhi, p_blo, N_CLASS * HID);
    mma_gemm_kernel<<<dim3(N_CLASS / 128, BATCH / 128), 256, MG_SMEM>>>(
        p_hhi, p_hlo, p_bhi, p_blo, bfin, out, N_CLASS, HID);
}

// round 13
// speedup vs baseline: 3.7659x; 1.0083x over previous
#include <cuda_runtime.h>
#include <cuda_bf16.h>
#include <math.h>
#include <stdint.h>

// Problem constants
#define N_CLASS 32000
#define EMB     256
#define HID     512
#define BATCH   256
#define SEQ     64
#define G4      2048            // 4 gates * HID (gate-interleaved: n = u*4 + g)
#define MB_     (SEQ*BATCH)     // 16384
#define BH      (BATCH*HID)     // 131072

typedef unsigned long long u64;
typedef unsigned short u16;

// ---------------- static device scratch (allocation-free) ----------------
__device__ __align__(16) float g_gin  [MB_*G4];         // 134 MB gate inputs
__device__ __align__(16) float g_wicat[G4*EMB];         // fp32 (fold + cvt source)
__device__ __align__(16) float g_bcat [G4];
__device__ __align__(16) float g_weff [G4*HID];
__device__ __align__(16) float g_beff [G4];
__device__ __align__(16) u16   g_whqhi[G4*HID];         // hidden weights split bf16
__device__ __align__(16) u16   g_whqlo[G4*HID];
__device__ __align__(16) u16   g_hhi  [2*BH];           // h double buffer (split bf16)
__device__ __align__(16) u16   g_hlo  [2*BH];
__device__ unsigned          g_bcnt8[8];                // per-bm-group barrier counters
__device__ volatile unsigned g_bgen8[8];                // per-bm-group barrier generations
// split-bf16 A/B operand buffers for the big GEMMs
__device__ __align__(16) u16 g_ahi[MB_*HID];            // emb, then h0all
__device__ __align__(16) u16 g_alo[MB_*HID];
__device__ __align__(16) u16 g_bhi[N_CLASS*HID];
__device__ __align__(16) u16 g_blo[N_CLASS*HID];

// ---------------- small helpers ----------------
__device__ __forceinline__ u64 pack2(float x, float y) {
    u64 r; asm("mov.b64 %0, {%1, %2};" : "=l"(r) : "f"(x), "f"(y)); return r;
}
__device__ __forceinline__ float2 unpack2(u64 v) {
    float2 r; asm("mov.b64 {%0, %1}, %2;" : "=f"(r.x), "=f"(r.y) : "l"(v)); return r;
}
__device__ __forceinline__ void fma2(u64& d, u64 a, u64 b) {
    asm("fma.rn.f32x2 %0, %1, %2, %0;" : "+l"(d) : "l"(a), "l"(b));
}
__device__ __forceinline__ float sigmoidf_(float x) { return 1.0f / (1.0f + expf(-x)); }
__device__ __forceinline__ uint32_t smem_u32(const void* p) {
    uint32_t a;
    asm("{ .reg .u64 t; cvta.to.shared.u64 t, %1; cvt.u32.u64 %0, t; }"
        : "=r"(a) : "l"(p));
    return a;
}
__device__ __forceinline__ void split_bf16(float x, u16& hi, u16& lo) {
    __nv_bfloat16 h = __float2bfloat16(x);
    hi = __bfloat16_as_ushort(h);
    lo = __bfloat16_as_ushort(__float2bfloat16(x - __bfloat162float(h)));
}
__device__ __forceinline__ void st_cg_u16(u16* p, u16 v) {
    asm volatile("st.global.cg.u16 [%0], %1;" :: "l"(p), "h"(v));
}

// ---------------- cp.async helpers ----------------
__device__ __forceinline__ void cp16(uint32_t saddr, const void* g) {
    asm volatile("cp.async.cg.shared.global [%0], [%1], 16;"
                 :: "r"(saddr), "l"(g) : "memory");
}
#define CP_COMMIT() asm volatile("cp.async.commit_group;" ::: "memory")
#define CP_WAIT1()  asm volatile("cp.async.wait_group 1;" ::: "memory")
#define CP_WAIT0()  asm volatile("cp.async.wait_group 0;" ::: "memory")

// ---------------- mma.sync helpers (legacy tensor path, valid on sm_103) -----
__device__ __forceinline__ void ldm_x4(uint32_t* r, uint32_t addr) {
    asm volatile("ldmatrix.sync.aligned.m8n8.x4.shared.b16 {%0,%1,%2,%3}, [%4];"
                 : "=r"(r[0]), "=r"(r[1]), "=r"(r[2]), "=r"(r[3]) : "r"(addr));
}
__device__ __forceinline__ void mma16816(float* c, const uint32_t* a,
                                         uint32_t b0, uint32_t b1) {
    asm volatile(
        "mma.sync.aligned.m16n8k16.row.col.f32.bf16.bf16.f32 "
        "{%0,%1,%2,%3}, {%4,%5,%6,%7}, {%8,%9}, {%0,%1,%2,%3};"
        : "+f"(c[0]), "+f"(c[1]), "+f"(c[2]), "+f"(c[3])
        : "r"(a[0]), "r"(a[1]), "r"(a[2]), "r"(a[3]), "r"(b0), "r"(b1));
}

// ------------- build gate-interleaved weights (whq -> split bf16) -------------
__global__ void __launch_bounds__(256) prep_concat_kernel(
    const float* __restrict__ Wii, const float* __restrict__ Whi, const float* __restrict__ bi,
    const float* __restrict__ Wif, const float* __restrict__ Whf, const float* __restrict__ bf,
    const float* __restrict__ Wig, const float* __restrict__ Whg, const float* __restrict__ bg,
    const float* __restrict__ Wio, const float* __restrict__ Who, const float* __restrict__ bo)
{
    int idx = blockIdx.x * 256 + threadIdx.x;
    if (idx >= G4 * HID) return;
    int n = idx / HID;
    int k = idx - n * HID;
    int u = n >> 2;
    int g = n & 3;
    const float* Wh = (g == 0) ? Whi : (g == 1) ? Whf : (g == 2) ? Whg : Who;
    u16 hi, lo;
    split_bf16(Wh[u * HID + k], hi, lo);
    g_whqhi[idx] = hi;
    g_whqlo[idx] = lo;
    if (k < EMB) {
        const float* Wi = (g == 0) ? Wii : (g == 1) ? Wif : (g == 2) ? Wig : Wio;
        g_wicat[n * EMB + k] = Wi[u * EMB + k];
    }
    if (k == 0) {
        const float* bv = (g == 0) ? bi : (g == 1) ? bf : (g == 2) ? bg : bo;
        g_bcat[n] = bv[u];
    }
}

// ------------- embedding gather -> split bf16 directly -------------
__global__ void __launch_bounds__(EMB) embed_kernel(const int* __restrict__ X,
                                                    const float* __restrict__ C)
{
    int sb = blockIdx.x;
    int s  = sb >> 8;
    int b  = sb & 255;
    int row = X[b * SEQ + s];
    float v = C[(size_t)row * EMB + threadIdx.x];
    u16 hi, lo;
    split_bf16(v, hi, lo);
    g_ahi[(size_t)sb * EMB + threadIdx.x] = hi;
    g_alo[(size_t)sb * EMB + threadIdx.x] = lo;
}

// ------------- fp32 -> split bf16 (hi + lo) -------------
__global__ void __launch_bounds__(256) cvt_split_kernel(
    const float* __restrict__ src, u16* __restrict__ hi,
    u16* __restrict__ lo, int n)
{
    int i = blockIdx.x * 256 + threadIdx.x;
    if (i >= n) return;
    u16 h, l;
    split_bf16(src[i], h, l);
    hi[i] = h;
    lo[i] = l;
}

// ------------- split-bf16 tensor-core GEMM, 2-stage cp.async, 2 CTA/SM --------
// (R12 known-good, unchanged)
#define MG_ROWU  40
#define MG_ARRU  (128*MG_ROWU)            // 5120 u16 per array per stage
#define MG_STGU  (4*MG_ARRU)              // 20480 u16 per stage
#define MG_SMEM  (2*MG_STGU*2)            // 81920 bytes -> 2 CTAs/SM

__device__ __forceinline__ void mg_issue_stage(
    uint32_t sbase, const u16* __restrict__ Ahi, const u16* __restrict__ Alo,
    const u16* __restrict__ Bhi, const u16* __restrict__ Blo,
    int bm, int bn, int K, int k0, int tid)
{
#pragma unroll
    for (int t = 0; t < 2; t++) {
        int idx = tid + 256 * t;            // 0..511
        int row = idx >> 2, seg = (idx & 3) * 8;
        size_t ga = (size_t)(bm + row) * K + k0 + seg;
        size_t gb = (size_t)(bn + row) * K + k0 + seg;
        uint32_t d = sbase + (uint32_t)((row * MG_ROWU + seg) * 2);
        cp16(d + 0u * (MG_ARRU * 2), Ahi + ga);
        cp16(d + 1u * (MG_ARRU * 2), Alo + ga);
        cp16(d + 2u * (MG_ARRU * 2), Bhi + gb);
        cp16(d + 3u * (MG_ARRU * 2), Blo + gb);
    }
}

__global__ void __launch_bounds__(256, 2) mma_gemm_kernel(
    const u16* __restrict__ Ahi, const u16* __restrict__ Alo,
    const u16* __restrict__ Bhi, const u16* __restrict__ Blo,
    const float* __restrict__ bias, float* __restrict__ Y, int N, int K)
{
    extern __shared__ u16 smu[];
    uint32_t smb = smem_u32(smu);
    int tid  = threadIdx.x;
    int w    = tid >> 5;
    int lane = tid & 31;
    int bm = blockIdx.y * 128;
    int bn = blockIdx.x * 128;
    int wm = (w & 3) * 32;
    int wn = (w >> 2) * 64;
    int nch = K >> 5;

    int mat = lane >> 3, mi = lane & 7;
    uint32_t aoff = (uint32_t)((wm + (mat & 1) * 8 + mi) * 80 + (mat >> 1) * 16);
    uint32_t boff = (uint32_t)((wn + (mat >> 1) * 8 + mi) * 80 + (mat & 1) * 16);

    float acc[2][8][4];
#pragma unroll
    for (int i = 0; i < 2; i++)
#pragma unroll
        for (int j = 0; j < 8; j++)
#pragma unroll
            for (int q = 0; q < 4; q++) acc[i][j][q] = 0.0f;

    mg_issue_stage(smb, Ahi, Alo, Bhi, Blo, bm, bn, K, 0, tid);
    CP_COMMIT();

    for (int c = 0; c < nch; c++) {
        CP_WAIT0();
        __syncthreads();
        if (c + 1 < nch)
            mg_issue_stage(smb + (uint32_t)(((c + 1) & 1) * MG_STGU * 2),
                           Ahi, Alo, Bhi, Blo, bm, bn, K, (c + 1) * 32, tid);
        CP_COMMIT();

        uint32_t sb = smb + (uint32_t)((c & 1) * MG_STGU * 2);
#pragma unroll
        for (int k16 = 0; k16 < 2; k16++) {
            uint32_t kb = (uint32_t)(k16 * 32);
            uint32_t ah[2][4], al[2][4];
            ldm_x4(ah[0], sb + 0 * 10240 + aoff + kb);
            ldm_x4(ah[1], sb + 0 * 10240 + aoff + kb + 16 * 80);
            ldm_x4(al[0], sb + 1 * 10240 + aoff + kb);
            ldm_x4(al[1], sb + 1 * 10240 + aoff + kb + 16 * 80);
#pragma unroll
            for (int nb = 0; nb < 4; nb++) {
                uint32_t bh[4], bl[4];
                uint32_t bo = boff + kb + (uint32_t)(nb * 16 * 80);
                ldm_x4(bh, sb + 2 * 10240 + bo);
                ldm_x4(bl, sb + 3 * 10240 + bo);
#pragma unroll
                for (int mb = 0; mb < 2; mb++) {
#pragma unroll
                    for (int h = 0; h < 2; h++) {
                        float* cc = acc[mb][nb * 2 + h];
                        mma16816(cc, ah[mb], bh[2 * h], bh[2 * h + 1]);
                        mma16816(cc, ah[mb], bl[2 * h], bl[2 * h + 1]);
                        mma16816(cc, al[mb], bh[2 * h], bh[2 * h + 1]);
                    }
                }
            }
        }
    }

    int grp = lane >> 2, t2 = lane & 3;
#pragma unroll
    for (int mb = 0; mb < 2; mb++) {
#pragma unroll
        for (int nj = 0; nj < 8; nj++) {
            int n = bn + wn + nj * 8 + t2 * 2;
            float2 bv = *(const float2*)&bias[n];
            int mlo = bm + wm + mb * 16 + grp;
            const float* cc = acc[mb][nj];
            float2 v0 = make_float2(cc[0] + bv.x, cc[1] + bv.y);
            float2 v1 = make_float2(cc[2] + bv.x, cc[3] + bv.y);
            *(float2*)&Y[(size_t)mlo * N + n]       = v0;
            *(float2*)&Y[(size_t)(mlo + 8) * N + n] = v1;
        }
    }
}

// ------------- fp32 fold GEMM (known-good), TRANSB -------------
template <bool TRANSB>
__global__ void __launch_bounds__(256) gemm128_kernel(
    const float* __restrict__ A, const float* __restrict__ B,
    const float* __restrict__ bias, float* __restrict__ Y,
    int M, int N, int K)
{
    const int BK = 16;
    __shared__ float As[BK][128];
    __shared__ float Bs[BK][128];

    int bm = blockIdx.y * 128;
    int bn = blockIdx.x * 128;
    int tid = threadIdx.x;
    int tx = tid & 15;
    int ty = tid >> 4;
    int m0 = ty * 8;
    int n0 = tx * 8;

    u64 acc[8][4];
#pragma unroll
    for (int i = 0; i < 8; i++)
#pragma unroll
        for (int j = 0; j < 4; j++) acc[i][j] = 0ULL;

    for (int k0 = 0; k0 < K; k0 += BK) {
#pragma unroll
        for (int l = tid; l < 512; l += 256) {
            int r = l >> 2, kq = l & 3;
            float4 v = *(const float4*)&A[(size_t)(bm + r) * K + k0 + kq * 4];
            As[kq * 4 + 0][r] = v.x; As[kq * 4 + 1][r] = v.y;
            As[kq * 4 + 2][r] = v.z; As[kq * 4 + 3][r] = v.w;
        }
        if (!TRANSB) {
#pragma unroll
            for (int l = tid; l < 512; l += 256) {
                int r = l >> 2, kq = l & 3;
                float4 v = *(const float4*)&B[(size_t)(bn + r) * K + k0 + kq * 4];
                Bs[kq * 4 + 0][r] = v.x; Bs[kq * 4 + 1][r] = v.y;
                Bs[kq * 4 + 2][r] = v.z; Bs[kq * 4 + 3][r] = v.w;
            }
        } else {
#pragma unroll
            for (int l = tid; l < 512; l += 256) {
                int k = l >> 5, nq = l & 31;
                *(float4*)&Bs[k][nq * 4] =
                    *(const float4*)&B[(size_t)(k0 + k) * N + bn + nq * 4];
            }
        }
        __syncthreads();

#pragma unroll
        for (int k = 0; k < BK; k++) {
            float4 av0 = *(const float4*)&As[k][m0];
            float4 av1 = *(const float4*)&As[k][m0 + 4];
            u64 bp[4];
            bp[0] = *(const u64*)&Bs[k][n0];
            bp[1] = *(const u64*)&Bs[k][n0 + 2];
            bp[2] = *(const u64*)&Bs[k][n0 + 4];
            bp[3] = *(const u64*)&Bs[k][n0 + 6];
            float am[8] = {av0.x, av0.y, av0.z, av0.w, av1.x, av1.y, av1.z, av1.w};
#pragma unroll
            for (int i = 0; i < 8; i++) {
                u64 ad = pack2(am[i], am[i]);
#pragma unroll
                for (int j = 0; j < 4; j++) fma2(acc[i][j], ad, bp[j]);
            }
        }
        __syncthreads();
    }

#pragma unroll
    for (int i = 0; i < 8; i++) {
        int m = bm + m0 + i;
        float2 p0 = unpack2(acc[i][0]), p1 = unpack2(acc[i][1]);
        float2 p2 = unpack2(acc[i][2]), p3 = unpack2(acc[i][3]);
        float4 v0 = make_float4(p0.x, p0.y, p1.x, p1.y);
        float4 v1 = make_float4(p2.x, p2.y, p3.x, p3.y);
        *(float4*)&Y[(size_t)m * N + bn + n0]     = v0;
        *(float4*)&Y[(size_t)m * N + bn + n0 + 4] = v1;
    }
}

// ------------- per-bm-group barrier (16 blocks each, all co-resident) ---------
__device__ __forceinline__ void groupbar(int gid, unsigned target)
{
    __threadfence();
    __syncthreads();
    if (threadIdx.x == 0) {
        if (atomicAdd(&g_bcnt8[gid], 1u) == 15u) {
            g_bcnt8[gid] = 0u;
            __threadfence();
            g_bgen8[gid] = target;
        } else {
            while (g_bgen8[gid] < target) { }
        }
    }
    __syncthreads();
}

// ------------- persistent LSTM layer: resident-B + 3-slot ring ---------------
// grid (16,8) = 128 blocks, 256 threads (8 warps: 2m x 4n).
// Block tile: 32 batch x 128 gates x K512, split-bf16 3-term mma.
// smem (u16): Ahi[32x520]=16640, Alo=16640,
//   resident B chunks 0..4 (5 x 10240), ring B chunks 5..15 (3 slots x 10240)
#define LSR_A_LO  16640
#define LSR_RES   33280
#define LSR_RING  (33280 + 5*10240)          // 84480
#define LSR_SMEMU (84480 + 3*10240)          // 115200 u16
#define LSR_SMEM  (LSR_SMEMU*2)              // 230400 bytes

// load B chunk (128 gates x 32 k, hi+lo) into smem offset (u16 units)
__device__ __forceinline__ void lsr_issue_chunk(uint32_t smb, uint32_t off_u16,
                                                int bn, int k0, int tid)
{
#pragma unroll
    for (int t = 0; t < 2; t++) {
        int idx = tid + t * 256;
        int r = idx >> 2, seg = (idx & 3) * 8;
        size_t g = (size_t)(bn + r) * HID + k0 + seg;
        uint32_t d = smb + (off_u16 + (uint32_t)(r * 40 + seg)) * 2;
        cp16(d, g_whqhi + g);
        cp16(d + 5120 * 2, g_whqlo + g);
    }
}

__global__ void __launch_bounds__(256) lstm_layer_mma_kernel(int store_all)
{
    extern __shared__ u16 smu[];
    uint32_t smb = smem_u32(smu);
    int tid  = threadIdx.x;
    int w    = tid >> 5;
    int lane = tid & 31;
    int bn = blockIdx.x * 128;
    int bm = blockIdx.y * 32;
    int gid = blockIdx.y;
    int wm = (w & 1) * 16;
    int wn = (w >> 1) * 32;

    int mat = lane >> 3, mi = lane & 7;
    uint32_t aoff = (uint32_t)((wm + (mat & 1) * 8 + mi) * 1040 + (mat >> 1) * 16);
    uint32_t boff = (uint32_t)((wn + (mat >> 1) * 8 + mi) * 80 + (mat & 1) * 16);

    int grp = lane >> 2, t2 = lane & 3;
    int m0r = bm + wm + grp;
    bool owner = (t2 & 1) == 0;

    float cst[4][2];
#pragma unroll
    for (int j = 0; j < 4; j++) { cst[j][0] = 0.0f; cst[j][1] = 0.0f; }

    // s=0 prologue: resident chunks 0..4 (one group), then ring chunks 5,6
    for (int c = 0; c < 5; c++)
        lsr_issue_chunk(smb, (uint32_t)(LSR_RES + c * 10240), bn, c * 32, tid);
    CP_COMMIT();
    lsr_issue_chunk(smb, (uint32_t)(LSR_RING + 0 * 10240), bn, 5 * 32, tid);
    CP_COMMIT();
    lsr_issue_chunk(smb, (uint32_t)(LSR_RING + 1 * 10240), bn, 6 * 32, tid);
    CP_COMMIT();

    for (int s = 0; s < SEQ; s++) {
        const u16* hp_hi = g_hhi + (s & 1) * BH;
        const u16* hp_lo = g_hlo + (s & 1) * BH;
        u16* hn_hi = g_hhi + ((s + 1) & 1) * BH;
        u16* hn_lo = g_hlo + ((s + 1) & 1) * BH;

        // prefetch this step's gin into registers (no h dependency)
        float2 pg0[4], pg1[4];
#pragma unroll
        for (int nj = 0; nj < 4; nj++) {
            int ncol = bn + wn + nj * 8 + t2 * 2;
            const float* gp = &g_gin[((size_t)(s * BATCH + m0r)) * G4 + ncol];
            pg0[nj] = *(const float2*)gp;
            pg1[nj] = *(const float2*)(gp + 8 * G4);
        }

        // group barrier: previous step's h stores must be visible
        if (s > 0) groupbar(gid, (unsigned)s);

        // A load (h prev, 32 rows x 512 u16, hi+lo)
#pragma unroll
        for (int t = 0; t < 8; t++) {
            int i = tid + t * 256;          // 0..2047
            int r = i >> 6, cseg = (i & 63) * 8;
            size_t g = (size_t)(bm + r) * HID + cseg;
            cp16(smb + (uint32_t)((r * 520 + cseg) * 2), hp_hi + g);
            cp16(smb + (uint32_t)((LSR_A_LO + r * 520 + cseg) * 2), hp_lo + g);
        }
        CP_COMMIT();

        float acc[4][4];
#pragma unroll
        for (int j = 0; j < 4; j++)
#pragma unroll
            for (int q = 0; q < 4; q++) acc[j][q] = 0.0f;

        // chunk 0 gate: A (+ anything earlier) fully arrived
        CP_WAIT0();
        __syncthreads();

        for (int ch = 0; ch < 16; ch++) {
            uint32_t bchunk;
            if (ch < 5) {
                bchunk = (uint32_t)(LSR_RES + ch * 10240);
            } else {
                if (ch > 5) {                 // ch==5 already covered by wait0
                    CP_WAIT1();
                    __syncthreads();
                }
                if (ch + 2 <= 15) {
                    int j = ch + 2;
                    lsr_issue_chunk(smb, (uint32_t)(LSR_RING + ((j - 5) % 3) * 10240),
                                    bn, j * 32, tid);
                    CP_COMMIT();
                }
                bchunk = (uint32_t)(LSR_RING + ((ch - 5) % 3) * 10240);
            }

            uint32_t bbase = smb + bchunk * 2 + boff;
#pragma unroll
            for (int k16 = 0; k16 < 2; k16++) {
                uint32_t ka = (uint32_t)(ch * 64 + k16 * 32);
                uint32_t kb = (uint32_t)(k16 * 32);
                uint32_t ah[4], al[4], bh0[4], bh1[4], bl0[4], bl1[4];
                ldm_x4(ah, smb + aoff + ka);
                ldm_x4(al, smb + (uint32_t)(LSR_A_LO * 2) + aoff + ka);
                ldm_x4(bh0, bbase + kb);
                ldm_x4(bh1, bbase + kb + 16 * 80);
                ldm_x4(bl0, bbase + (uint32_t)(5120 * 2) + kb);
                ldm_x4(bl1, bbase + (uint32_t)(5120 * 2) + kb + 16 * 80);

                mma16816(acc[0], ah, bh0[0], bh0[1]);
                mma16816(acc[0], ah, bl0[0], bl0[1]);
                mma16816(acc[0], al, bh0[0], bh0[1]);
                mma16816(acc[1], ah, bh0[2], bh0[3]);
                mma16816(acc[1], ah, bl0[2], bl0[3]);
                mma16816(acc[1], al, bh0[2], bh0[3]);
                mma16816(acc[2], ah, bh1[0], bh1[1]);
                mma16816(acc[2], ah, bl1[0], bl1[1]);
                mma16816(acc[2], al, bh1[0], bh1[1]);
                mma16816(acc[3], ah, bh1[2], bh1[3]);
                mma16816(acc[3], ah, bl1[2], bl1[3]);
                mma16816(acc[3], al, bh1[2], bh1[3]);
            }
        }

        // all ring reads done before next step reuses slots 0/1
        __syncthreads();
        if (s + 1 < SEQ) {
            lsr_issue_chunk(smb, (uint32_t)(LSR_RING + 0 * 10240), bn, 5 * 32, tid);
            CP_COMMIT();
            lsr_issue_chunk(smb, (uint32_t)(LSR_RING + 1 * 10240), bn, 6 * 32, tid);
            CP_COMMIT();
        }

        // epilogue: prefetched gin, gate pair-exchange, LSTM cell, h store
#pragma unroll
        for (int nj = 0; nj < 4; nj++) {
            int ncol = bn + wn + nj * 8 + t2 * 2;
            float fa = acc[nj][0] + pg0[nj].x;
            float fb = acc[nj][1] + pg0[nj].y;
            float fc = acc[nj][2] + pg1[nj].x;
            float fd = acc[nj][3] + pg1[nj].y;
            float pa = __shfl_xor_sync(0xffffffffu, fa, 1);
            float pb = __shfl_xor_sync(0xffffffffu, fb, 1);
            float pc = __shfl_xor_sync(0xffffffffu, fc, 1);
            float pd = __shfl_xor_sync(0xffffffffu, fd, 1);
            if (owner) {
                int u = ncol >> 2;
                {
                    float ig = sigmoidf_(fa), fg = sigmoidf_(fb);
                    float gg = tanhf(pa),     og = sigmoidf_(pb);
                    float cn = fg * cst[nj][0] + ig * gg;
                    cst[nj][0] = cn;
                    float hv = og * tanhf(cn);
                    u16 hi, lo; split_bf16(hv, hi, lo);
                    size_t idx = (size_t)m0r * HID + u;
                    st_cg_u16(&hn_hi[idx], hi);
                    st_cg_u16(&hn_lo[idx], lo);
                    if (store_all) {
                        size_t oidx = ((size_t)(s * BATCH + m0r)) * HID + u;
                        g_ahi[oidx] = hi; g_alo[oidx] = lo;
                    }
                }
                {
                    float ig = sigmoidf_(fc), fg = sigmoidf_(fd);
                    float gg = tanhf(pc),     og = sigmoidf_(pd);
                    float cn = fg * cst[nj][1] + ig * gg;
                    cst[nj][1] = cn;
                    float hv = og * tanhf(cn);
                    u16 hi, lo; split_bf16(hv, hi, lo);
                    size_t idx = (size_t)(m0r + 8) * HID + u;
                    st_cg_u16(&hn_hi[idx], hi);
                    st_cg_u16(&hn_lo[idx], lo);
                    if (store_all) {
                        size_t oidx = ((size_t)(s * BATCH + m0r + 8)) * HID + u;
                        g_ahi[oidx] = hi; g_alo[oidx] = lo;
                    }
                }
            }
        }
    }
}

// ------------- beff[n] = bcat[n] + sum_e Wicat[n][e] * b_proj[e] -------------
__global__ void __launch_bounds__(256) beff_kernel(const float* __restrict__ bproj)
{
    int n = blockIdx.x * 256 + threadIdx.x;
    if (n >= G4) return;
    float s = g_bcat[n];
    const float* w = &g_wicat[n * EMB];
    for (int e = 0; e < EMB; e++) s += w[e] * bproj[e];
    g_beff[n] = s;
}

// ------------- zero h buffer 0 + reset group barriers -------------
__global__ void __launch_bounds__(256) zero_h_kernel()
{
    int i = blockIdx.x * 256 + threadIdx.x;
    if (i < BH) { g_hhi[i] = 0; g_hlo[i] = 0; }
    if (i < 8) { g_bcnt8[i] = 0u; g_bgen8[i] = 0u; }
}

// =============================== launch ===============================
extern "C" void kernel_launch(void* const* d_in, const int* in_sizes, int n_in,
                              void* d_out, int out_size)
{
    const int*   X    = (const int*)  d_in[0];
    const float* C    = (const float*)d_in[1];
    const float* Wii  = (const float*)d_in[2];
    const float* Whi  = (const float*)d_in[3];
    const float* bi   = (const float*)d_in[4];
    const float* Wif  = (const float*)d_in[5];
    const float* Whf  = (const float*)d_in[6];
    const float* bf   = (const float*)d_in[7];
    const float* Wig  = (const float*)d_in[8];
    const float* Whg  = (const float*)d_in[9];
    const float* bg   = (const float*)d_in[10];
    const float* Wio  = (const float*)d_in[11];
    const float* Who  = (const float*)d_in[12];
    const float* bo   = (const float*)d_in[13];
    const float* Wp   = (const float*)d_in[14];   // [EMB, HID]
    const float* bp   = (const float*)d_in[15];   // [EMB]
    const float* Wfin = (const float*)d_in[16];   // [N_CLASS, HID]
    const float* bfin = (const float*)d_in[17];   // [N_CLASS]
    float* out = (float*)d_out;

    float *p_gin, *p_wicat, *p_bcat, *p_weff, *p_beff;
    u16 *p_ahi, *p_alo, *p_bhi, *p_blo, *p_hhi, *p_hlo;
    cudaGetSymbolAddress((void**)&p_gin,   g_gin);
    cudaGetSymbolAddress((void**)&p_wicat, g_wicat);
    cudaGetSymbolAddress((void**)&p_bcat,  g_bcat);
    cudaGetSymbolAddress((void**)&p_weff,  g_weff);
    cudaGetSymbolAddress((void**)&p_beff,  g_beff);
    cudaGetSymbolAddress((void**)&p_ahi,   g_ahi);
    cudaGetSymbolAddress((void**)&p_alo,   g_alo);
    cudaGetSymbolAddress((void**)&p_bhi,   g_bhi);
    cudaGetSymbolAddress((void**)&p_blo,   g_blo);
    cudaGetSymbolAddress((void**)&p_hhi,   g_hhi);
    cudaGetSymbolAddress((void**)&p_hlo,   g_hlo);

    cudaFuncSetAttribute(mma_gemm_kernel,
                         cudaFuncAttributeMaxDynamicSharedMemorySize, MG_SMEM);
    cudaFuncSetAttribute(lstm_layer_mma_kernel,
                         cudaFuncAttributeMaxDynamicSharedMemorySize, LSR_SMEM);

    // 1) weight prep
    prep_concat_kernel<<<(G4 * HID) / 256, 256>>>(Wii, Whi, bi, Wif, Whf, bf,
                                                  Wig, Whg, bg, Wio, Who, bo);
    // 2) embedding gather -> split bf16 A
    embed_kernel<<<MB_, EMB>>>(X, C);

    // 3) Gin0 = Emb @ Wicat^T + bcat   [16384 x 2048], K=256
    cvt_split_kernel<<<(G4 * EMB) / 256, 256>>>(p_wicat, p_bhi, p_blo, G4 * EMB);
    mma_gemm_kernel<<<dim3(G4 / 128, MB_ / 128), 256, MG_SMEM>>>(
        p_ahi, p_alo, p_bhi, p_blo, p_bcat, p_gin, G4, EMB);

    // 4) fold projection: Weff = Wicat @ Wp  (fp32), beff; cvt to bf16 B
    gemm128_kernel<true><<<dim3(HID / 128, G4 / 128), 256>>>(
        p_wicat, Wp, nullptr, p_weff, G4, HID, EMB);
    beff_kernel<<<G4 / 256, 256>>>(bp);
    cvt_split_kernel<<<(G4 * HID) / 256, 256>>>(p_weff, p_bhi, p_blo, G4 * HID);

    // 5) layer-0 recurrence (persistent, tensor-core; h0all -> g_ahi/g_alo)
    zero_h_kernel<<<BH / 256, 256>>>();
    lstm_layer_mma_kernel<<<dim3(16, 8), 256, LSR_SMEM>>>(1);

    // 6) Gin1 = H0all @ Weff^T + beff  [16384 x 2048], K=512
    mma_gemm_kernel<<<dim3(G4 / 128, MB_ / 128), 256, MG_SMEM>>>(
        p_ahi, p_alo, p_bhi, p_blo, p_beff, p_gin, G4, HID);

    // 7) layer-1 recurrence
    zero_h_kernel<<<BH / 256, 256>>>();
    lstm_layer_mma_kernel<<<dim3(16, 8), 256, LSR_SMEM>>>(0);

    // 8) logits = h_last @ Wfin^T + bfin  [256 x 32000], K=512
    //    (SEQ even -> final h in buffer 0 of g_hhi/g_hlo)
    cvt_split_kernel<<<(N_CLASS * HID) / 256, 256>>>(Wfin, p_bhi, p_blo, N_CLASS * HID);
    mma_gemm_kernel<<<dim3(N_CLASS / 128, BATCH / 128), 256, MG_SMEM>>>(
        p_hhi, p_hlo, p_bhi, p_blo, bfin, out, N_CLASS, HID);
}

// round 14
// speedup vs baseline: 4.1385x; 1.0990x over previous
#include <cuda_runtime.h>
#include <cuda_bf16.h>
#include <math.h>
#include <stdint.h>

// Problem constants
#define N_CLASS 32000
#define EMB     256
#define HID     512
#define BATCH   256
#define SEQ     64
#define G4      2048            // 4 gates * HID (gate-interleaved: n = u*4 + g)
#define MB_     (SEQ*BATCH)     // 16384
#define BH      (BATCH*HID)     // 131072

typedef unsigned long long u64;
typedef unsigned short u16;

// ---------------- static device scratch (allocation-free) ----------------
__device__ __align__(16) float g_gin  [MB_*G4];         // 134 MB gate inputs
__device__ __align__(16) float g_wicat[G4*EMB];         // fp32 (fold + cvt source)
__device__ __align__(16) float g_bcat [G4];
__device__ __align__(16) float g_weff [G4*HID];
__device__ __align__(16) float g_beff [G4];
__device__ __align__(16) u16   g_whqhi[G4*HID];         // hidden weights split bf16
__device__ __align__(16) u16   g_whqlo[G4*HID];
__device__ __align__(16) u16   g_hhi  [2*BH];           // h double buffer (split bf16)
__device__ __align__(16) u16   g_hlo  [2*BH];
__device__ unsigned          g_bcnt8[8];                // per-bm-group barrier counters
__device__ volatile unsigned g_bgen8[8];                // per-bm-group barrier generations
// split-bf16 A/B operand buffers for the big GEMMs
__device__ __align__(16) u16 g_ahi[MB_*HID];            // emb, then h0all
__device__ __align__(16) u16 g_alo[MB_*HID];
__device__ __align__(16) u16 g_bhi[N_CLASS*HID];
__device__ __align__(16) u16 g_blo[N_CLASS*HID];

// ---------------- small helpers ----------------
__device__ __forceinline__ u64 pack2(float x, float y) {
    u64 r; asm("mov.b64 %0, {%1, %2};" : "=l"(r) : "f"(x), "f"(y)); return r;
}
__device__ __forceinline__ float2 unpack2(u64 v) {
    float2 r; asm("mov.b64 {%0, %1}, %2;" : "=f"(r.x), "=f"(r.y) : "l"(v)); return r;
}
__device__ __forceinline__ void fma2(u64& d, u64 a, u64 b) {
    asm("fma.rn.f32x2 %0, %1, %2, %0;" : "+l"(d) : "l"(a), "l"(b));
}
__device__ __forceinline__ float sigmoidf_(float x) { return 1.0f / (1.0f + expf(-x)); }
__device__ __forceinline__ uint32_t smem_u32(const void* p) {
    uint32_t a;
    asm("{ .reg .u64 t; cvta.to.shared.u64 t, %1; cvt.u32.u64 %0, t; }"
        : "=r"(a) : "l"(p));
    return a;
}
__device__ __forceinline__ void split_bf16(float x, u16& hi, u16& lo) {
    __nv_bfloat16 h = __float2bfloat16(x);
    hi = __bfloat16_as_ushort(h);
    lo = __bfloat16_as_ushort(__float2bfloat16(x - __bfloat162float(h)));
}
__device__ __forceinline__ void st_cg_u16(u16* p, u16 v) {
    asm volatile("st.global.cg.u16 [%0], %1;" :: "l"(p), "h"(v));
}

// ---------------- cp.async helpers ----------------
__device__ __forceinline__ void cp16(uint32_t saddr, const void* g) {
    asm volatile("cp.async.cg.shared.global [%0], [%1], 16;"
                 :: "r"(saddr), "l"(g) : "memory");
}
#define CP_COMMIT() asm volatile("cp.async.commit_group;" ::: "memory")
#define CP_WAIT1()  asm volatile("cp.async.wait_group 1;" ::: "memory")
#define CP_WAIT0()  asm volatile("cp.async.wait_group 0;" ::: "memory")

// ---------------- mma.sync helpers (legacy tensor path, valid on sm_103) -----
__device__ __forceinline__ void ldm_x4(uint32_t* r, uint32_t addr) {
    asm volatile("ldmatrix.sync.aligned.m8n8.x4.shared.b16 {%0,%1,%2,%3}, [%4];"
                 : "=r"(r[0]), "=r"(r[1]), "=r"(r[2]), "=r"(r[3]) : "r"(addr));
}
__device__ __forceinline__ void mma16816(float* c, const uint32_t* a,
                                         uint32_t b0, uint32_t b1) {
    asm volatile(
        "mma.sync.aligned.m16n8k16.row.col.f32.bf16.bf16.f32 "
        "{%0,%1,%2,%3}, {%4,%5,%6,%7}, {%8,%9}, {%0,%1,%2,%3};"
        : "+f"(c[0]), "+f"(c[1]), "+f"(c[2]), "+f"(c[3])
        : "r"(a[0]), "r"(a[1]), "r"(a[2]), "r"(a[3]), "r"(b0), "r"(b1));
}

// ------------- build gate-interleaved weights (whq -> split bf16) -------------
__global__ void __launch_bounds__(256) prep_concat_kernel(
    const float* __restrict__ Wii, const float* __restrict__ Whi, const float* __restrict__ bi,
    const float* __restrict__ Wif, const float* __restrict__ Whf, const float* __restrict__ bf,
    const float* __restrict__ Wig, const float* __restrict__ Whg, const float* __restrict__ bg,
    const float* __restrict__ Wio, const float* __restrict__ Who, const float* __restrict__ bo)
{
    int idx = blockIdx.x * 256 + threadIdx.x;
    if (idx >= G4 * HID) return;
    int n = idx / HID;
    int k = idx - n * HID;
    int u = n >> 2;
    int g = n & 3;
    const float* Wh = (g == 0) ? Whi : (g == 1) ? Whf : (g == 2) ? Whg : Who;
    u16 hi, lo;
    split_bf16(Wh[u * HID + k], hi, lo);
    g_whqhi[idx] = hi;
    g_whqlo[idx] = lo;
    if (k < EMB) {
        const float* Wi = (g == 0) ? Wii : (g == 1) ? Wif : (g == 2) ? Wig : Wio;
        g_wicat[n * EMB + k] = Wi[u * EMB + k];
    }
    if (k == 0) {
        const float* bv = (g == 0) ? bi : (g == 1) ? bf : (g == 2) ? bg : bo;
        g_bcat[n] = bv[u];
    }
}

// ------------- embedding gather -> split bf16 directly -------------
__global__ void __launch_bounds__(EMB) embed_kernel(const int* __restrict__ X,
                                                    const float* __restrict__ C)
{
    int sb = blockIdx.x;
    int s  = sb >> 8;
    int b  = sb & 255;
    int row = X[b * SEQ + s];
    float v = C[(size_t)row * EMB + threadIdx.x];
    u16 hi, lo;
    split_bf16(v, hi, lo);
    g_ahi[(size_t)sb * EMB + threadIdx.x] = hi;
    g_alo[(size_t)sb * EMB + threadIdx.x] = lo;
}

// ------------- fp32 -> split bf16 (hi + lo) -------------
__global__ void __launch_bounds__(256) cvt_split_kernel(
    const float* __restrict__ src, u16* __restrict__ hi,
    u16* __restrict__ lo, int n)
{
    int i = blockIdx.x * 256 + threadIdx.x;
    if (i >= n) return;
    u16 h, l;
    split_bf16(src[i], h, l);
    hi[i] = h;
    lo[i] = l;
}

// ------------- split-bf16 tensor-core GEMM, 2-stage cp.async, 2 CTA/SM --------
// (R12 known-good, unchanged)
#define MG_ROWU  40
#define MG_ARRU  (128*MG_ROWU)            // 5120 u16 per array per stage
#define MG_STGU  (4*MG_ARRU)              // 20480 u16 per stage
#define MG_SMEM  (2*MG_STGU*2)            // 81920 bytes -> 2 CTAs/SM

__device__ __forceinline__ void mg_issue_stage(
    uint32_t sbase, const u16* __restrict__ Ahi, const u16* __restrict__ Alo,
    const u16* __restrict__ Bhi, const u16* __restrict__ Blo,
    int bm, int bn, int K, int k0, int tid)
{
#pragma unroll
    for (int t = 0; t < 2; t++) {
        int idx = tid + 256 * t;            // 0..511
        int row = idx >> 2, seg = (idx & 3) * 8;
        size_t ga = (size_t)(bm + row) * K + k0 + seg;
        size_t gb = (size_t)(bn + row) * K + k0 + seg;
        uint32_t d = sbase + (uint32_t)((row * MG_ROWU + seg) * 2);
        cp16(d + 0u * (MG_ARRU * 2), Ahi + ga);
        cp16(d + 1u * (MG_ARRU * 2), Alo + ga);
        cp16(d + 2u * (MG_ARRU * 2), Bhi + gb);
        cp16(d + 3u * (MG_ARRU * 2), Blo + gb);
    }
}

__global__ void __launch_bounds__(256, 2) mma_gemm_kernel(
    const u16* __restrict__ Ahi, const u16* __restrict__ Alo,
    const u16* __restrict__ Bhi, const u16* __restrict__ Blo,
    const float* __restrict__ bias, float* __restrict__ Y, int N, int K)
{
    extern __shared__ u16 smu[];
    uint32_t smb = smem_u32(smu);
    int tid  = threadIdx.x;
    int w    = tid >> 5;
    int lane = tid & 31;
    int bm = blockIdx.y * 128;
    int bn = blockIdx.x * 128;
    int wm = (w & 3) * 32;
    int wn = (w >> 2) * 64;
    int nch = K >> 5;

    int mat = lane >> 3, mi = lane & 7;
    uint32_t aoff = (uint32_t)((wm + (mat & 1) * 8 + mi) * 80 + (mat >> 1) * 16);
    uint32_t boff = (uint32_t)((wn + (mat >> 1) * 8 + mi) * 80 + (mat & 1) * 16);

    float acc[2][8][4];
#pragma unroll
    for (int i = 0; i < 2; i++)
#pragma unroll
        for (int j = 0; j < 8; j++)
#pragma unroll
            for (int q = 0; q < 4; q++) acc[i][j][q] = 0.0f;

    mg_issue_stage(smb, Ahi, Alo, Bhi, Blo, bm, bn, K, 0, tid);
    CP_COMMIT();

    for (int c = 0; c < nch; c++) {
        CP_WAIT0();
        __syncthreads();
        if (c + 1 < nch)
            mg_issue_stage(smb + (uint32_t)(((c + 1) & 1) * MG_STGU * 2),
                           Ahi, Alo, Bhi, Blo, bm, bn, K, (c + 1) * 32, tid);
        CP_COMMIT();

        uint32_t sb = smb + (uint32_t)((c & 1) * MG_STGU * 2);
#pragma unroll
        for (int k16 = 0; k16 < 2; k16++) {
            uint32_t kb = (uint32_t)(k16 * 32);
            uint32_t ah[2][4], al[2][4];
            ldm_x4(ah[0], sb + 0 * 10240 + aoff + kb);
            ldm_x4(ah[1], sb + 0 * 10240 + aoff + kb + 16 * 80);
            ldm_x4(al[0], sb + 1 * 10240 + aoff + kb);
            ldm_x4(al[1], sb + 1 * 10240 + aoff + kb + 16 * 80);
#pragma unroll
            for (int nb = 0; nb < 4; nb++) {
                uint32_t bh[4], bl[4];
                uint32_t bo = boff + kb + (uint32_t)(nb * 16 * 80);
                ldm_x4(bh, sb + 2 * 10240 + bo);
                ldm_x4(bl, sb + 3 * 10240 + bo);
#pragma unroll
                for (int mb = 0; mb < 2; mb++) {
#pragma unroll
                    for (int h = 0; h < 2; h++) {
                        float* cc = acc[mb][nb * 2 + h];
                        mma16816(cc, ah[mb], bh[2 * h], bh[2 * h + 1]);
                        mma16816(cc, ah[mb], bl[2 * h], bl[2 * h + 1]);
                        mma16816(cc, al[mb], bh[2 * h], bh[2 * h + 1]);
                    }
                }
            }
        }
    }

    int grp = lane >> 2, t2 = lane & 3;
#pragma unroll
    for (int mb = 0; mb < 2; mb++) {
#pragma unroll
        for (int nj = 0; nj < 8; nj++) {
            int n = bn + wn + nj * 8 + t2 * 2;
            float2 bv = *(const float2*)&bias[n];
            int mlo = bm + wm + mb * 16 + grp;
            const float* cc = acc[mb][nj];
            float2 v0 = make_float2(cc[0] + bv.x, cc[1] + bv.y);
            float2 v1 = make_float2(cc[2] + bv.x, cc[3] + bv.y);
            *(float2*)&Y[(size_t)mlo * N + n]       = v0;
            *(float2*)&Y[(size_t)(mlo + 8) * N + n] = v1;
        }
    }
}

// ------------- fp32 fold GEMM (known-good), TRANSB -------------
template <bool TRANSB>
__global__ void __launch_bounds__(256) gemm128_kernel(
    const float* __restrict__ A, const float* __restrict__ B,
    const float* __restrict__ bias, float* __restrict__ Y,
    int M, int N, int K)
{
    const int BK = 16;
    __shared__ float As[BK][128];
    __shared__ float Bs[BK][128];

    int bm = blockIdx.y * 128;
    int bn = blockIdx.x * 128;
    int tid = threadIdx.x;
    int tx = tid & 15;
    int ty = tid >> 4;
    int m0 = ty * 8;
    int n0 = tx * 8;

    u64 acc[8][4];
#pragma unroll
    for (int i = 0; i < 8; i++)
#pragma unroll
        for (int j = 0; j < 4; j++) acc[i][j] = 0ULL;

    for (int k0 = 0; k0 < K; k0 += BK) {
#pragma unroll
        for (int l = tid; l < 512; l += 256) {
            int r = l >> 2, kq = l & 3;
            float4 v = *(const float4*)&A[(size_t)(bm + r) * K + k0 + kq * 4];
            As[kq * 4 + 0][r] = v.x; As[kq * 4 + 1][r] = v.y;
            As[kq * 4 + 2][r] = v.z; As[kq * 4 + 3][r] = v.w;
        }
        if (!TRANSB) {
#pragma unroll
            for (int l = tid; l < 512; l += 256) {
                int r = l >> 2, kq = l & 3;
                float4 v = *(const float4*)&B[(size_t)(bn + r) * K + k0 + kq * 4];
                Bs[kq * 4 + 0][r] = v.x; Bs[kq * 4 + 1][r] = v.y;
                Bs[kq * 4 + 2][r] = v.z; Bs[kq * 4 + 3][r] = v.w;
            }
        } else {
#pragma unroll
            for (int l = tid; l < 512; l += 256) {
                int k = l >> 5, nq = l & 31;
                *(float4*)&Bs[k][nq * 4] =
                    *(const float4*)&B[(size_t)(k0 + k) * N + bn + nq * 4];
            }
        }
        __syncthreads();

#pragma unroll
        for (int k = 0; k < BK; k++) {
            float4 av0 = *(const float4*)&As[k][m0];
            float4 av1 = *(const float4*)&As[k][m0 + 4];
            u64 bp[4];
            bp[0] = *(const u64*)&Bs[k][n0];
            bp[1] = *(const u64*)&Bs[k][n0 + 2];
            bp[2] = *(const u64*)&Bs[k][n0 + 4];
            bp[3] = *(const u64*)&Bs[k][n0 + 6];
            float am[8] = {av0.x, av0.y, av0.z, av0.w, av1.x, av1.y, av1.z, av1.w};
#pragma unroll
            for (int i = 0; i < 8; i++) {
                u64 ad = pack2(am[i], am[i]);
#pragma unroll
                for (int j = 0; j < 4; j++) fma2(acc[i][j], ad, bp[j]);
            }
        }
        __syncthreads();
    }

#pragma unroll
    for (int i = 0; i < 8; i++) {
        int m = bm + m0 + i;
        float2 p0 = unpack2(acc[i][0]), p1 = unpack2(acc[i][1]);
        float2 p2 = unpack2(acc[i][2]), p3 = unpack2(acc[i][3]);
        float4 v0 = make_float4(p0.x, p0.y, p1.x, p1.y);
        float4 v1 = make_float4(p2.x, p2.y, p3.x, p3.y);
        *(float4*)&Y[(size_t)m * N + bn + n0]     = v0;
        *(float4*)&Y[(size_t)m * N + bn + n0 + 4] = v1;
    }
}

// ------------- per-bm-group barrier (16 blocks each, all co-resident) ---------
__device__ __forceinline__ void groupbar(int gid, unsigned target)
{
    __threadfence();
    __syncthreads();
    if (threadIdx.x == 0) {
        if (atomicAdd(&g_bcnt8[gid], 1u) == 15u) {
            g_bcnt8[gid] = 0u;
            __threadfence();
            g_bgen8[gid] = target;
        } else {
            while (g_bgen8[gid] < target) { }
        }
    }
    __syncthreads();
}

// ------------- persistent LSTM layer: 512 threads, resident-B + 3-slot ring ---
// grid (16,8) = 128 blocks, 512 threads (16 warps: 2m x 8n).
// Block tile: 32 batch x 128 gates x K512, split-bf16 3-term mma.
// Warp tile: 16m x 16n -> 6 mma per k16 per warp (4 warps/SMSP latency hiding).
// smem (u16): Ahi[32x520]=16640, Alo=16640,
//   resident B chunks 0..4 (5 x 10240), ring B chunks 5..15 (3 slots x 10240)
#define LSR_A_LO  16640
#define LSR_RES   33280
#define LSR_RING  (33280 + 5*10240)          // 84480
#define LSR_SMEMU (84480 + 3*10240)          // 115200 u16
#define LSR_SMEM  (LSR_SMEMU*2)              // 230400 bytes

// load B chunk (128 gates x 32 k, hi+lo) into smem offset (u16 units); 512 thr
__device__ __forceinline__ void lsr_issue_chunk(uint32_t smb, uint32_t off_u16,
                                                int bn, int k0, int tid)
{
    int r = tid >> 2, seg = (tid & 3) * 8;
    size_t g = (size_t)(bn + r) * HID + k0 + seg;
    uint32_t d = smb + (off_u16 + (uint32_t)(r * 40 + seg)) * 2;
    cp16(d, g_whqhi + g);
    cp16(d + 5120 * 2, g_whqlo + g);
}

__global__ void __launch_bounds__(512) lstm_layer_mma_kernel(int store_all)
{
    extern __shared__ u16 smu[];
    uint32_t smb = smem_u32(smu);
    int tid  = threadIdx.x;
    int w    = tid >> 5;
    int lane = tid & 31;
    int bn = blockIdx.x * 128;
    int bm = blockIdx.y * 32;
    int gid = blockIdx.y;
    int wm = (w & 1) * 16;
    int wn = (w >> 1) * 16;            // 8 n-slices of 16 gates

    int mat = lane >> 3, mi = lane & 7;
    uint32_t aoff = (uint32_t)((wm + (mat & 1) * 8 + mi) * 1040 + (mat >> 1) * 16);
    uint32_t boff = (uint32_t)((wn + (mat >> 1) * 8 + mi) * 80 + (mat & 1) * 16);

    int grp = lane >> 2, t2 = lane & 3;
    int m0r = bm + wm + grp;
    bool owner = (t2 & 1) == 0;

    float cst[2][2];
#pragma unroll
    for (int j = 0; j < 2; j++) { cst[j][0] = 0.0f; cst[j][1] = 0.0f; }

    // s=0 prologue: resident chunks 0..4 (one group), then ring chunks 5,6
    for (int c = 0; c < 5; c++)
        lsr_issue_chunk(smb, (uint32_t)(LSR_RES + c * 10240), bn, c * 32, tid);
    CP_COMMIT();
    lsr_issue_chunk(smb, (uint32_t)(LSR_RING + 0 * 10240), bn, 5 * 32, tid);
    CP_COMMIT();
    lsr_issue_chunk(smb, (uint32_t)(LSR_RING + 1 * 10240), bn, 6 * 32, tid);
    CP_COMMIT();

    for (int s = 0; s < SEQ; s++) {
        const u16* hp_hi = g_hhi + (s & 1) * BH;
        const u16* hp_lo = g_hlo + (s & 1) * BH;
        u16* hn_hi = g_hhi + ((s + 1) & 1) * BH;
        u16* hn_lo = g_hlo + ((s + 1) & 1) * BH;

        // prefetch this step's gin into registers (no h dependency)
        float2 pg0[2], pg1[2];
#pragma unroll
        for (int nj = 0; nj < 2; nj++) {
            int ncol = bn + wn + nj * 8 + t2 * 2;
            const float* gp = &g_gin[((size_t)(s * BATCH + m0r)) * G4 + ncol];
            pg0[nj] = *(const float2*)gp;
            pg1[nj] = *(const float2*)(gp + 8 * G4);
        }

        // group barrier: previous step's h stores must be visible
        if (s > 0) groupbar(gid, (unsigned)s);

        // A load (h prev, 32 rows x 512 u16, hi+lo) -- 512 threads
#pragma unroll
        for (int t = 0; t < 4; t++) {
            int i = tid + t * 512;          // 0..2047
            int r = i >> 6, cseg = (i & 63) * 8;
            size_t g = (size_t)(bm + r) * HID + cseg;
            cp16(smb + (uint32_t)((r * 520 + cseg) * 2), hp_hi + g);
            cp16(smb + (uint32_t)((LSR_A_LO + r * 520 + cseg) * 2), hp_lo + g);
        }
        CP_COMMIT();

        float acc[2][4];
#pragma unroll
        for (int j = 0; j < 2; j++)
#pragma unroll
            for (int q = 0; q < 4; q++) acc[j][q] = 0.0f;

        // chunk 0 gate: A (+ anything earlier) fully arrived
        CP_WAIT0();
        __syncthreads();

        for (int ch = 0; ch < 16; ch++) {
            uint32_t bchunk;
            if (ch < 5) {
                bchunk = (uint32_t)(LSR_RES + ch * 10240);
            } else {
                if (ch > 5) {                 // ch==5 already covered by wait0
                    CP_WAIT1();
                    __syncthreads();
                }
                if (ch + 2 <= 15) {
                    int j = ch + 2;
                    lsr_issue_chunk(smb, (uint32_t)(LSR_RING + ((j - 5) % 3) * 10240),
                                    bn, j * 32, tid);
                    CP_COMMIT();
                }
                bchunk = (uint32_t)(LSR_RING + ((ch - 5) % 3) * 10240);
            }

            uint32_t bbase = smb + bchunk * 2 + boff;
#pragma unroll
            for (int k16 = 0; k16 < 2; k16++) {
                uint32_t ka = (uint32_t)(ch * 64 + k16 * 32);
                uint32_t kb = (uint32_t)(k16 * 32);
                uint32_t ah[4], al[4], bh[4], bl[4];
                ldm_x4(ah, smb + aoff + ka);
                ldm_x4(al, smb + (uint32_t)(LSR_A_LO * 2) + aoff + ka);
                ldm_x4(bh, bbase + kb);
                ldm_x4(bl, bbase + (uint32_t)(5120 * 2) + kb);

                mma16816(acc[0], ah, bh[0], bh[1]);
                mma16816(acc[0], ah, bl[0], bl[1]);
                mma16816(acc[0], al, bh[0], bh[1]);
                mma16816(acc[1], ah, bh[2], bh[3]);
                mma16816(acc[1], ah, bl[2], bl[3]);
                mma16816(acc[1], al, bh[2], bh[3]);
            }
        }

        // all ring reads done before next step reuses slots 0/1
        __syncthreads();
        if (s + 1 < SEQ) {
            lsr_issue_chunk(smb, (uint32_t)(LSR_RING + 0 * 10240), bn, 5 * 32, tid);
            CP_COMMIT();
            lsr_issue_chunk(smb, (uint32_t)(LSR_RING + 1 * 10240), bn, 6 * 32, tid);
            CP_COMMIT();
        }

        // epilogue: prefetched gin, gate pair-exchange, LSTM cell, h store
#pragma unroll
        for (int nj = 0; nj < 2; nj++) {
            int ncol = bn + wn + nj * 8 + t2 * 2;
            float fa = acc[nj][0] + pg0[nj].x;
            float fb = acc[nj][1] + pg0[nj].y;
            float fc = acc[nj][2] + pg1[nj].x;
            float fd = acc[nj][3] + pg1[nj].y;
            float pa = __shfl_xor_sync(0xffffffffu, fa, 1);
            float pb = __shfl_xor_sync(0xffffffffu, fb, 1);
            float pc = __shfl_xor_sync(0xffffffffu, fc, 1);
            float pd = __shfl_xor_sync(0xffffffffu, fd, 1);
            if (owner) {
                int u = ncol >> 2;
                {
                    float ig = sigmoidf_(fa), fg = sigmoidf_(fb);
                    float gg = tanhf(pa),     og = sigmoidf_(pb);
                    float cn = fg * cst[nj][0] + ig * gg;
                    cst[nj][0] = cn;
                    float hv = og * tanhf(cn);
                    u16 hi, lo; split_bf16(hv, hi, lo);
                    size_t idx = (size_t)m0r * HID + u;
                    st_cg_u16(&hn_hi[idx], hi);
                    st_cg_u16(&hn_lo[idx], lo);
                    if (store_all) {
                        size_t oidx = ((size_t)(s * BATCH + m0r)) * HID + u;
                        g_ahi[oidx] = hi; g_alo[oidx] = lo;
                    }
                }
                {
                    float ig = sigmoidf_(fc), fg = sigmoidf_(fd);
                    float gg = tanhf(pc),     og = sigmoidf_(pd);
                    float cn = fg * cst[nj][1] + ig * gg;
                    cst[nj][1] = cn;
                    float hv = og * tanhf(cn);
                    u16 hi, lo; split_bf16(hv, hi, lo);
                    size_t idx = (size_t)(m0r + 8) * HID + u;
                    st_cg_u16(&hn_hi[idx], hi);
                    st_cg_u16(&hn_lo[idx], lo);
                    if (store_all) {
                        size_t oidx = ((size_t)(s * BATCH + m0r + 8)) * HID + u;
                        g_ahi[oidx] = hi; g_alo[oidx] = lo;
                    }
                }
            }
        }
    }
}

// ------------- beff[n] = bcat[n] + sum_e Wicat[n][e] * b_proj[e] -------------
__global__ void __launch_bounds__(256) beff_kernel(const float* __restrict__ bproj)
{
    int n = blockIdx.x * 256 + threadIdx.x;
    if (n >= G4) return;
    float s = g_bcat[n];
    const float* w = &g_wicat[n * EMB];
    for (int e = 0; e < EMB; e++) s += w[e] * bproj[e];
    g_beff[n] = s;
}

// ------------- zero h buffer 0 + reset group barriers -------------
__global__ void __launch_bounds__(256) zero_h_kernel()
{
    int i = blockIdx.x * 256 + threadIdx.x;
    if (i < BH) { g_hhi[i] = 0; g_hlo[i] = 0; }
    if (i < 8) { g_bcnt8[i] = 0u; g_bgen8[i] = 0u; }
}

// =============================== launch ===============================
extern "C" void kernel_launch(void* const* d_in, const int* in_sizes, int n_in,
                              void* d_out, int out_size)
{
    const int*   X    = (const int*)  d_in[0];
    const float* C    = (const float*)d_in[1];
    const float* Wii  = (const float*)d_in[2];
    const float* Whi  = (const float*)d_in[3];
    const float* bi   = (const float*)d_in[4];
    const float* Wif  = (const float*)d_in[5];
    const float* Whf  = (const float*)d_in[6];
    const float* bf   = (const float*)d_in[7];
    const float* Wig  = (const float*)d_in[8];
    const float* Whg  = (const float*)d_in[9];
    const float* bg   = (const float*)d_in[10];
    const float* Wio  = (const float*)d_in[11];
    const float* Who  = (const float*)d_in[12];
    const float* bo   = (const float*)d_in[13];
    const float* Wp   = (const float*)d_in[14];   // [EMB, HID]
    const float* bp   = (const float*)d_in[15];   // [EMB]
    const float* Wfin = (const float*)d_in[16];   // [N_CLASS, HID]
    const float* bfin = (const float*)d_in[17];   // [N_CLASS]
    float* out = (float*)d_out;

    float *p_gin, *p_wicat, *p_bcat, *p_weff, *p_beff;
    u16 *p_ahi, *p_alo, *p_bhi, *p_blo, *p_hhi, *p_hlo;
    cudaGetSymbolAddress((void**)&p_gin,   g_gin);
    cudaGetSymbolAddress((void**)&p_wicat, g_wicat);
    cudaGetSymbolAddress((void**)&p_bcat,  g_bcat);
    cudaGetSymbolAddress((void**)&p_weff,  g_weff);
    cudaGetSymbolAddress((void**)&p_beff,  g_beff);
    cudaGetSymbolAddress((void**)&p_ahi,   g_ahi);
    cudaGetSymbolAddress((void**)&p_alo,   g_alo);
    cudaGetSymbolAddress((void**)&p_bhi,   g_bhi);
    cudaGetSymbolAddress((void**)&p_blo,   g_blo);
    cudaGetSymbolAddress((void**)&p_hhi,   g_hhi);
    cudaGetSymbolAddress((void**)&p_hlo,   g_hlo);

    cudaFuncSetAttribute(mma_gemm_kernel,
                         cudaFuncAttributeMaxDynamicSharedMemorySize, MG_SMEM);
    cudaFuncSetAttribute(lstm_layer_mma_kernel,
                         cudaFuncAttributeMaxDynamicSharedMemorySize, LSR_SMEM);

    // 1) weight prep
    prep_concat_kernel<<<(G4 * HID) / 256, 256>>>(Wii, Whi, bi, Wif, Whf, bf,
                                                  Wig, Whg, bg, Wio, Who, bo);
    // 2) embedding gather -> split bf16 A
    embed_kernel<<<MB_, EMB>>>(X, C);

    // 3) Gin0 = Emb @ Wicat^T + bcat   [16384 x 2048], K=256
    cvt_split_kernel<<<(G4 * EMB) / 256, 256>>>(p_wicat, p_bhi, p_blo, G4 * EMB);
    mma_gemm_kernel<<<dim3(G4 / 128, MB_ / 128), 256, MG_SMEM>>>(
        p_ahi, p_alo, p_bhi, p_blo, p_bcat, p_gin, G4, EMB);

    // 4) fold projection: Weff = Wicat @ Wp  (fp32), beff; cvt to bf16 B
    gemm128_kernel<true><<<dim3(HID / 128, G4 / 128), 256>>>(
        p_wicat, Wp, nullptr, p_weff, G4, HID, EMB);
    beff_kernel<<<G4 / 256, 256>>>(bp);
    cvt_split_kernel<<<(G4 * HID) / 256, 256>>>(p_weff, p_bhi, p_blo, G4 * HID);

    // 5) layer-0 recurrence (persistent, tensor-core; h0all -> g_ahi/g_alo)
    zero_h_kernel<<<BH / 256, 256>>>();
    lstm_layer_mma_kernel<<<dim3(16, 8), 512, LSR_SMEM>>>(1);

    // 6) Gin1 = H0all @ Weff^T + beff  [16384 x 2048], K=512
    mma_gemm_kernel<<<dim3(G4 / 128, MB_ / 128), 256, MG_SMEM>>>(
        p_ahi, p_alo, p_bhi, p_blo, p_beff, p_gin, G4, HID);

    // 7) layer-1 recurrence
    zero_h_kernel<<<BH / 256, 256>>>();
    lstm_layer_mma_kernel<<<dim3(16, 8), 512, LSR_SMEM>>>(0);

    // 8) logits = h_last @ Wfin^T + bfin  [256 x 32000], K=512
    //    (SEQ even -> final h in buffer 0 of g_hhi/g_hlo)
    cvt_split_kernel<<<(N_CLASS * HID) / 256, 256>>>(Wfin, p_bhi, p_blo, N_CLASS * HID);
    mma_gemm_kernel<<<dim3(N_CLASS / 128, BATCH / 128), 256, MG_SMEM>>>(
        p_hhi, p_hlo, p_bhi, p_blo, bfin, out, N_CLASS, HID);
}